// round 2
// baseline (speedup 1.0000x reference)
#include <cuda_runtime.h>

#define NN 45056
#define EE 720896
#define FEA 60
#define HID 256
#define MACH 22
#define BATCH 2048           // NN / MACH
#define CAP 96               // max in-degree capacity (mean 16)
#define MLP_IN 6952          // MACH * (HID + FEA)
#define NEG_SLOPE 0.01f

// ---------------- scratch (device globals; no allocation allowed) ----------
static constexpr size_t OFF_DEG  = 0;
static constexpr size_t OFF_DINV = OFF_DEG  + (size_t)NN;
static constexpr size_t OFF_NRM  = OFF_DINV + (size_t)NN;
static constexpr size_t OFF_HW   = OFF_NRM  + (size_t)NN * CAP;
static constexpr size_t OFF_H    = OFF_HW   + (size_t)NN * HID;
static constexpr size_t OFF_FLAT = OFF_H    + (size_t)NN * HID;
static constexpr size_t OFF_Z0   = OFF_FLAT + (size_t)BATCH * MLP_IN;
static constexpr size_t OFF_Z1   = OFF_Z0   + (size_t)BATCH * HID;
static constexpr size_t FTOTAL   = OFF_Z1   + (size_t)BATCH * HID;

__device__ float g_f[FTOTAL];
__device__ int   g_i[(size_t)NN * (CAP + 1)];   // [0,NN): cnt ; rest: src lists
__device__ int   g_is32;                         // edge_index dtype flag

// ---------------- dtype detection ------------------------------------------
__global__ void k_detect(const void* __restrict__ ei) {
    if (threadIdx.x != 0 || blockIdx.x != 0) return;
    const long long* p = (const long long*)ei;
    int is32 = 0;
    for (int i = 0; i < 64; i++) {
        long long v = p[i];
        if (v < 0 || v >= NN) { is32 = 1; break; }
    }
    g_is32 = is32;
}

__device__ __forceinline__ int edge_idx(const void* ei, int half, int e, int is32) {
    if (is32) return ((const int*)ei)[(size_t)half * EE + e];
    return (int)((const long long*)ei)[(size_t)half * EE + e];
}

// ---------------- small kernels --------------------------------------------
__global__ void k_zero(float* __restrict__ deg, int* __restrict__ cnt) {
    int i = blockIdx.x * 256 + threadIdx.x;
    if (i < NN) { deg[i] = 0.f; cnt[i] = 0; }
}

__global__ void k_deg(const void* __restrict__ ei,
                      const float* __restrict__ ew,
                      float* __restrict__ deg) {
    int e = blockIdx.x * 256 + threadIdx.x;
    if (e >= EE) return;
    int is32 = g_is32;
    int c = edge_idx(ei, 1, e, is32);
    if ((unsigned)c < (unsigned)NN) atomicAdd(&deg[c], ew[e]);
}

__global__ void k_dinv(const float* __restrict__ deg, float* __restrict__ dinv) {
    int i = blockIdx.x * 256 + threadIdx.x;
    if (i < NN) dinv[i] = rsqrtf(deg[i] + 1.0f);   // +1 = self-loop weight
}

__global__ void k_fill(const void* __restrict__ ei,
                       const float* __restrict__ ew,
                       const float* __restrict__ dinv,
                       float* __restrict__ nrm, int* __restrict__ cnt,
                       int* __restrict__ src) {
    int e = blockIdx.x * 256 + threadIdx.x;
    if (e >= EE) return;
    int is32 = g_is32;
    int r = edge_idx(ei, 0, e, is32);
    int c = edge_idx(ei, 1, e, is32);
    if ((unsigned)r >= (unsigned)NN || (unsigned)c >= (unsigned)NN) return;
    float nv = dinv[r] * ew[e] * dinv[c];
    int p = atomicAdd(&cnt[c], 1);
    if (p < CAP) {
        src[(size_t)c * CAP + p] = r;
        nrm[(size_t)c * CAP + p] = nv;
    }
}

// ---------------- SIMT SGEMM: C = A[M,K] @ B[K,N] (+bias, +leaky) ----------
// M % 64 == 0, N % 64 == 0, arbitrary K.
template<bool LRELU>
__global__ __launch_bounds__(256)
void sgemm(const float* __restrict__ A, const float* __restrict__ B,
           const float* __restrict__ bias, float* __restrict__ C,
           int M, int N, int K) {
    __shared__ float As[64][9];
    __shared__ float Bs[8][64];
    int tid = threadIdx.x;
    int tx = tid & 15, ty = tid >> 4;
    int row0 = blockIdx.y * 64, col0 = blockIdx.x * 64;

    float acc[4][4];
#pragma unroll
    for (int i = 0; i < 4; i++)
#pragma unroll
        for (int j = 0; j < 4; j++) acc[i][j] = 0.f;

    int la_m = tid >> 3, la_k = tid & 7;   // A loader: rows la_m, la_m+32
    int lb_k = tid >> 6, lb_n = tid & 63;  // B loader: ks lb_k, lb_k+4

    for (int k0 = 0; k0 < K; k0 += 8) {
        int ka = k0 + la_k;
        float va0 = 0.f, va1 = 0.f;
        if (ka < K) {
            va0 = A[(size_t)(row0 + la_m) * K + ka];
            va1 = A[(size_t)(row0 + la_m + 32) * K + ka];
        }
        As[la_m][la_k] = va0;
        As[la_m + 32][la_k] = va1;

        int kb0 = k0 + lb_k, kb1 = k0 + lb_k + 4;
        Bs[lb_k][lb_n]     = (kb0 < K) ? B[(size_t)kb0 * N + col0 + lb_n] : 0.f;
        Bs[lb_k + 4][lb_n] = (kb1 < K) ? B[(size_t)kb1 * N + col0 + lb_n] : 0.f;
        __syncthreads();

#pragma unroll
        for (int kk = 0; kk < 8; kk++) {
            float a[4], b[4];
#pragma unroll
            for (int i = 0; i < 4; i++) a[i] = As[ty * 4 + i][kk];
#pragma unroll
            for (int j = 0; j < 4; j++) b[j] = Bs[kk][tx * 4 + j];
#pragma unroll
            for (int i = 0; i < 4; i++)
#pragma unroll
                for (int j = 0; j < 4; j++)
                    acc[i][j] = fmaf(a[i], b[j], acc[i][j]);
        }
        __syncthreads();
    }

#pragma unroll
    for (int i = 0; i < 4; i++) {
        size_t m = (size_t)row0 + ty * 4 + i;
#pragma unroll
        for (int j = 0; j < 4; j++) {
            int n = col0 + tx * 4 + j;
            float v = acc[i][j] + (bias ? bias[n] : 0.f);
            if (LRELU) v = v > 0.f ? v : NEG_SLOPE * v;
            C[m * (size_t)N + n] = v;
        }
    }
}

// ---------------- GCN gather (one block per node, 256 threads = features) --
// MODE 0: out[i*HID + t]          (conv1 -> h)
// MODE 1: out[flat index]         (conv2 -> flat buffer for MLP)
template<int MODE>
__global__ __launch_bounds__(256)
void k_gather(const float* __restrict__ hw, const float* __restrict__ bias,
              const float* __restrict__ dinv, const int* __restrict__ cnt,
              const int* __restrict__ src, const float* __restrict__ nrm,
              float* __restrict__ out) {
    int i = blockIdx.x;
    int t = threadIdx.x;
    __shared__ int   ssrc[CAP];
    __shared__ float snrm[CAP];
    int c = cnt[i]; if (c > CAP) c = CAP;
    if (t < c) {
        ssrc[t] = src[(size_t)i * CAP + t];
        snrm[t] = nrm[(size_t)i * CAP + t];
    }
    __syncthreads();

    float di = dinv[i];
    float acc = di * di * hw[(size_t)i * HID + t];   // self-loop
    int e = 0;
    for (; e + 4 <= c; e += 4) {
        float v0 = hw[(size_t)ssrc[e]     * HID + t];
        float v1 = hw[(size_t)ssrc[e + 1] * HID + t];
        float v2 = hw[(size_t)ssrc[e + 2] * HID + t];
        float v3 = hw[(size_t)ssrc[e + 3] * HID + t];
        acc = fmaf(snrm[e],     v0, acc);
        acc = fmaf(snrm[e + 1], v1, acc);
        acc = fmaf(snrm[e + 2], v2, acc);
        acc = fmaf(snrm[e + 3], v3, acc);
    }
    for (; e < c; e++)
        acc = fmaf(snrm[e], hw[(size_t)ssrc[e] * HID + t], acc);

    acc += bias[t];
    acc = acc > 0.f ? acc : NEG_SLOPE * acc;

    if (MODE == 0) {
        out[(size_t)i * HID + t] = acc;
    } else {
        int b = i / MACH, m = i - b * MACH;
        out[(size_t)b * MLP_IN + (size_t)m * (HID + FEA) + t] = acc;
    }
}

// ---------------- copy raw x into the flat MLP input -----------------------
__global__ void k_xcopy(const float* __restrict__ x, float* __restrict__ flat) {
    long long idx = (long long)blockIdx.x * 256 + threadIdx.x;
    if (idx >= (long long)NN * FEA) return;
    int i = (int)(idx / FEA);
    int j = (int)(idx - (long long)i * FEA);
    int b = i / MACH, m = i - b * MACH;
    flat[(size_t)b * MLP_IN + (size_t)m * (HID + FEA) + HID + j] = x[idx];
}

// ---------------- final head: out[2048,4] = z @ Wo + bo --------------------
__global__ __launch_bounds__(32)
void k_head(const float* __restrict__ z, const float* __restrict__ Wo,
            const float* __restrict__ bo, float* __restrict__ out) {
    int b = blockIdx.x;
    int lane = threadIdx.x;
    float a0 = 0.f, a1 = 0.f, a2 = 0.f, a3 = 0.f;
    for (int k = lane; k < HID; k += 32) {
        float v = z[(size_t)b * HID + k];
        a0 = fmaf(v, Wo[k * 4 + 0], a0);
        a1 = fmaf(v, Wo[k * 4 + 1], a1);
        a2 = fmaf(v, Wo[k * 4 + 2], a2);
        a3 = fmaf(v, Wo[k * 4 + 3], a3);
    }
#pragma unroll
    for (int o = 16; o > 0; o >>= 1) {
        a0 += __shfl_down_sync(0xffffffffu, a0, o);
        a1 += __shfl_down_sync(0xffffffffu, a1, o);
        a2 += __shfl_down_sync(0xffffffffu, a2, o);
        a3 += __shfl_down_sync(0xffffffffu, a3, o);
    }
    if (lane == 0) {
        out[(size_t)b * 4 + 0] = a0 + bo[0];
        out[(size_t)b * 4 + 1] = a1 + bo[1];
        out[(size_t)b * 4 + 2] = a2 + bo[2];
        out[(size_t)b * 4 + 3] = a3 + bo[3];
    }
}

// ---------------- launcher --------------------------------------------------
extern "C" void kernel_launch(void* const* d_in, const int* in_sizes, int n_in,
                              void* d_out, int out_size) {
    const float* x   = (const float*)d_in[0];
    const void*  ei  = d_in[1];
    const float* ew  = (const float*)d_in[2];
    const float* W1  = (const float*)d_in[3];
    const float* b1  = (const float*)d_in[4];
    const float* W2  = (const float*)d_in[5];
    const float* b2  = (const float*)d_in[6];
    const float* Wf0 = (const float*)d_in[7];
    const float* bf0 = (const float*)d_in[8];
    const float* Wf1 = (const float*)d_in[9];
    const float* bf1 = (const float*)d_in[10];
    const float* Wf2 = (const float*)d_in[11];
    const float* bf2 = (const float*)d_in[12];
    const float* Wo  = (const float*)d_in[13];
    const float* bo  = (const float*)d_in[14];
    float* out = (float*)d_out;

    float* gf = nullptr;
    int*   gi = nullptr;
    cudaGetSymbolAddress((void**)&gf, g_f);
    cudaGetSymbolAddress((void**)&gi, g_i);

    float* deg  = gf + OFF_DEG;
    float* dinv = gf + OFF_DINV;
    float* nrm  = gf + OFF_NRM;
    float* hw   = gf + OFF_HW;
    float* h    = gf + OFF_H;
    float* flat = gf + OFF_FLAT;
    float* z0   = gf + OFF_Z0;
    float* z1   = gf + OFF_Z1;
    int*   cnt  = gi;
    int*   src  = gi + NN;

    const int NB_N = (NN + 255) / 256;
    const int NB_E = (EE + 255) / 256;

    // edge_index dtype detection + graph normalization + padded CSR build
    k_detect<<<1, 32>>>(ei);
    k_zero<<<NB_N, 256>>>(deg, cnt);
    k_deg <<<NB_E, 256>>>(ei, ew, deg);
    k_dinv<<<NB_N, 256>>>(deg, dinv);
    k_fill<<<NB_E, 256>>>(ei, ew, dinv, nrm, cnt, src);

    // conv1: hw = x @ W1 ; h = leaky(gather(hw) + b1)
    sgemm<false><<<dim3(HID / 64, NN / 64), 256>>>(x, W1, nullptr, hw, NN, HID, FEA);
    k_gather<0><<<NN, 256>>>(hw, b1, dinv, cnt, src, nrm, h);

    // conv2: hw = h @ W2 ; flat[h-part] = leaky(gather(hw) + b2)
    sgemm<false><<<dim3(HID / 64, NN / 64), 256>>>(h, W2, nullptr, hw, NN, HID, HID);
    k_gather<1><<<NN, 256>>>(hw, b2, dinv, cnt, src, nrm, flat);

    // flat[x-part] = x
    k_xcopy<<<(int)(((long long)NN * FEA + 255) / 256), 256>>>(x, flat);

    // MLP
    sgemm<true><<<dim3(HID / 64, BATCH / 64), 256>>>(flat, Wf0, bf0, z0, BATCH, HID, MLP_IN);
    sgemm<true><<<dim3(HID / 64, BATCH / 64), 256>>>(z0, Wf1, bf1, z1, BATCH, HID, HID);
    sgemm<true><<<dim3(HID / 64, BATCH / 64), 256>>>(z1, Wf2, bf2, z0, BATCH, HID, HID);
    k_head<<<BATCH, 32>>>(z0, Wo, bo, out);
}

// round 3
// speedup vs baseline: 1.8680x; 1.8680x over previous
#include <cuda_runtime.h>

#define NN 45056
#define EE 720896
#define FEA 60
#define HID 256
#define MACH 22
#define BATCH 2048           // NN / MACH
#define CAP 96               // max in-degree capacity (mean 16)
#define MLP_IN 6952          // MACH * (HID + FEA)
#define NEG_SLOPE 0.01f

// ---------------- scratch (device globals; no allocation allowed) ----------
static constexpr size_t OFF_DEG  = 0;
static constexpr size_t OFF_DINV = OFF_DEG  + (size_t)NN;
static constexpr size_t OFF_NRM  = OFF_DINV + (size_t)NN;
static constexpr size_t OFF_HW   = OFF_NRM  + (size_t)NN * CAP;
static constexpr size_t OFF_H    = OFF_HW   + (size_t)NN * HID;
static constexpr size_t OFF_FLAT = OFF_H    + (size_t)NN * HID;
static constexpr size_t OFF_Z0   = OFF_FLAT + (size_t)BATCH * MLP_IN;
static constexpr size_t OFF_Z1   = OFF_Z0   + (size_t)BATCH * HID;
static constexpr size_t FTOTAL   = OFF_Z1   + (size_t)BATCH * HID;

__device__ float g_f[FTOTAL];
__device__ int   g_i[(size_t)NN * (CAP + 1)];   // [0,NN): cnt ; rest: src lists
__device__ int   g_is32;                         // edge_index dtype flag

// ---------------- dtype detection ------------------------------------------
__global__ void k_detect(const void* __restrict__ ei) {
    if (threadIdx.x != 0 || blockIdx.x != 0) return;
    const long long* p = (const long long*)ei;
    int is32 = 0;
    for (int i = 0; i < 64; i++) {
        long long v = p[i];
        if (v < 0 || v >= NN) { is32 = 1; break; }
    }
    g_is32 = is32;
}

__device__ __forceinline__ int edge_idx(const void* ei, int half, int e, int is32) {
    if (is32) return ((const int*)ei)[(size_t)half * EE + e];
    return (int)((const long long*)ei)[(size_t)half * EE + e];
}

// ---------------- small kernels --------------------------------------------
__global__ void k_zero(float* __restrict__ deg, int* __restrict__ cnt) {
    int i = blockIdx.x * 256 + threadIdx.x;
    if (i < NN) { deg[i] = 0.f; cnt[i] = 0; }
}

__global__ void k_deg(const void* __restrict__ ei,
                      const float* __restrict__ ew,
                      float* __restrict__ deg) {
    int e = blockIdx.x * 256 + threadIdx.x;
    if (e >= EE) return;
    int is32 = g_is32;
    int c = edge_idx(ei, 1, e, is32);
    if ((unsigned)c < (unsigned)NN) atomicAdd(&deg[c], ew[e]);
}

__global__ void k_dinv(const float* __restrict__ deg, float* __restrict__ dinv) {
    int i = blockIdx.x * 256 + threadIdx.x;
    if (i < NN) dinv[i] = rsqrtf(deg[i] + 1.0f);   // +1 = self-loop weight
}

__global__ void k_fill(const void* __restrict__ ei,
                       const float* __restrict__ ew,
                       const float* __restrict__ dinv,
                       float* __restrict__ nrm, int* __restrict__ cnt,
                       int* __restrict__ src) {
    int e = blockIdx.x * 256 + threadIdx.x;
    if (e >= EE) return;
    int is32 = g_is32;
    int r = edge_idx(ei, 0, e, is32);
    int c = edge_idx(ei, 1, e, is32);
    if ((unsigned)r >= (unsigned)NN || (unsigned)c >= (unsigned)NN) return;
    float nv = dinv[r] * ew[e] * dinv[c];
    int p = atomicAdd(&cnt[c], 1);
    if (p < CAP) {
        src[(size_t)c * CAP + p] = r;
        nrm[(size_t)c * CAP + p] = nv;
    }
}

// ---------------- SGEMM 128x128 tile, 8x8/thread, split-K optional ---------
// C = A[M,K] @ B[K,N]. M%128==0, N%128==0, K%4==0, kstep%8==0.
// ATOMIC=true: atomicAdd partials into C (C must be pre-zeroed); bias ignored.
// ATOMIC=false: direct store with optional bias (+leaky if LRELU).
template<bool LRELU, bool ATOMIC>
__global__ __launch_bounds__(256)
void sgemm128(const float* __restrict__ A, const float* __restrict__ B,
              const float* __restrict__ bias, float* __restrict__ C,
              int M, int N, int K, int kstep) {
    __shared__ float As[8][128];
    __shared__ float Bs[8][128];
    const int tid = threadIdx.x;
    const int row0 = blockIdx.y * 128, col0 = blockIdx.x * 128;
    const int kb = blockIdx.z * kstep;
    const int ke = min(kb + kstep, K);

    const int am = tid >> 1, ak = (tid & 1) << 2;   // A loader
    const int bk = tid >> 5, bn = (tid & 31) << 2;  // B loader
    const int warp = tid >> 5, lane = tid & 31;
    const int tm = ((warp >> 1) << 5) + ((lane >> 3) << 3);
    const int tn = ((warp & 1) << 6) + ((lane & 7) << 3);

    float acc[8][8];
#pragma unroll
    for (int i = 0; i < 8; i++)
#pragma unroll
        for (int j = 0; j < 8; j++) acc[i][j] = 0.f;

    float4 ar, br;
    {
        int k = kb + ak;
        ar = (k < ke) ? *(const float4*)&A[(size_t)(row0 + am) * K + k]
                      : make_float4(0.f, 0.f, 0.f, 0.f);
        int k2 = kb + bk;
        br = (k2 < ke) ? *(const float4*)&B[(size_t)k2 * N + col0 + bn]
                       : make_float4(0.f, 0.f, 0.f, 0.f);
    }

    for (int k0 = kb; k0 < ke; k0 += 8) {
        As[ak + 0][am] = ar.x;
        As[ak + 1][am] = ar.y;
        As[ak + 2][am] = ar.z;
        As[ak + 3][am] = ar.w;
        *(float4*)&Bs[bk][bn] = br;
        __syncthreads();

        int k1 = k0 + 8;
        if (k1 < ke) {
            int k = k1 + ak;
            ar = (k < ke) ? *(const float4*)&A[(size_t)(row0 + am) * K + k]
                          : make_float4(0.f, 0.f, 0.f, 0.f);
            int k2 = k1 + bk;
            br = (k2 < ke) ? *(const float4*)&B[(size_t)k2 * N + col0 + bn]
                           : make_float4(0.f, 0.f, 0.f, 0.f);
        }

#pragma unroll
        for (int kk = 0; kk < 8; kk++) {
            float a[8], b[8];
            *(float4*)&a[0] = *(const float4*)&As[kk][tm];
            *(float4*)&a[4] = *(const float4*)&As[kk][tm + 4];
            *(float4*)&b[0] = *(const float4*)&Bs[kk][tn];
            *(float4*)&b[4] = *(const float4*)&Bs[kk][tn + 4];
#pragma unroll
            for (int i = 0; i < 8; i++)
#pragma unroll
                for (int j = 0; j < 8; j++)
                    acc[i][j] = fmaf(a[i], b[j], acc[i][j]);
        }
        __syncthreads();
    }

    if (ATOMIC) {
#pragma unroll
        for (int i = 0; i < 8; i++) {
            size_t m = (size_t)(row0 + tm + i);
#pragma unroll
            for (int j = 0; j < 8; j++)
                atomicAdd(&C[m * N + col0 + tn + j], acc[i][j]);
        }
    } else {
        float bv[8];
#pragma unroll
        for (int j = 0; j < 8; j++) bv[j] = bias ? bias[col0 + tn + j] : 0.f;
#pragma unroll
        for (int i = 0; i < 8; i++) {
            size_t m = (size_t)(row0 + tm + i);
            float o[8];
#pragma unroll
            for (int j = 0; j < 8; j++) {
                float v = acc[i][j] + bv[j];
                if (LRELU) v = v > 0.f ? v : NEG_SLOPE * v;
                o[j] = v;
            }
            *(float4*)&C[m * N + col0 + tn]     = *(float4*)&o[0];
            *(float4*)&C[m * N + col0 + tn + 4] = *(float4*)&o[4];
        }
    }
}

// ---------------- bias + leaky epilogue for split-K outputs ----------------
__global__ void k_epi(float* __restrict__ z, const float* __restrict__ bias) {
    int i = blockIdx.x * 256 + threadIdx.x;   // grid sized to BATCH*HID
    float v = z[i] + bias[i & (HID - 1)];
    z[i] = v > 0.f ? v : NEG_SLOPE * v;
}

// ---------------- GCN gather (one block per node, 256 threads = features) --
// MODE 0: out[i*HID + t]          (conv1 -> h)
// MODE 1: out[flat index]         (conv2 -> flat buffer for MLP)
template<int MODE>
__global__ __launch_bounds__(256)
void k_gather(const float* __restrict__ hw, const float* __restrict__ bias,
              const float* __restrict__ dinv, const int* __restrict__ cnt,
              const int* __restrict__ src, const float* __restrict__ nrm,
              float* __restrict__ out) {
    int i = blockIdx.x;
    int t = threadIdx.x;
    __shared__ int   ssrc[CAP];
    __shared__ float snrm[CAP];
    int c = cnt[i]; if (c > CAP) c = CAP;
    if (t < c) {
        ssrc[t] = src[(size_t)i * CAP + t];
        snrm[t] = nrm[(size_t)i * CAP + t];
    }
    __syncthreads();

    float di = dinv[i];
    float acc = di * di * hw[(size_t)i * HID + t];   // self-loop
    int e = 0;
    for (; e + 4 <= c; e += 4) {
        float v0 = hw[(size_t)ssrc[e]     * HID + t];
        float v1 = hw[(size_t)ssrc[e + 1] * HID + t];
        float v2 = hw[(size_t)ssrc[e + 2] * HID + t];
        float v3 = hw[(size_t)ssrc[e + 3] * HID + t];
        acc = fmaf(snrm[e],     v0, acc);
        acc = fmaf(snrm[e + 1], v1, acc);
        acc = fmaf(snrm[e + 2], v2, acc);
        acc = fmaf(snrm[e + 3], v3, acc);
    }
    for (; e < c; e++)
        acc = fmaf(snrm[e], hw[(size_t)ssrc[e] * HID + t], acc);

    acc += bias[t];
    acc = acc > 0.f ? acc : NEG_SLOPE * acc;

    if (MODE == 0) {
        out[(size_t)i * HID + t] = acc;
    } else {
        int b = i / MACH, m = i - b * MACH;
        out[(size_t)b * MLP_IN + (size_t)m * (HID + FEA) + t] = acc;
    }
}

// ---------------- copy raw x into the flat MLP input -----------------------
__global__ void k_xcopy(const float* __restrict__ x, float* __restrict__ flat) {
    long long idx = (long long)blockIdx.x * 256 + threadIdx.x;
    if (idx >= (long long)NN * FEA) return;
    int i = (int)(idx / FEA);
    int j = (int)(idx - (long long)i * FEA);
    int b = i / MACH, m = i - b * MACH;
    flat[(size_t)b * MLP_IN + (size_t)m * (HID + FEA) + HID + j] = x[idx];
}

// ---------------- final head: out[2048,4] = z @ Wo + bo --------------------
__global__ __launch_bounds__(32)
void k_head(const float* __restrict__ z, const float* __restrict__ Wo,
            const float* __restrict__ bo, float* __restrict__ out) {
    int b = blockIdx.x;
    int lane = threadIdx.x;
    float a0 = 0.f, a1 = 0.f, a2 = 0.f, a3 = 0.f;
    for (int k = lane; k < HID; k += 32) {
        float v = z[(size_t)b * HID + k];
        a0 = fmaf(v, Wo[k * 4 + 0], a0);
        a1 = fmaf(v, Wo[k * 4 + 1], a1);
        a2 = fmaf(v, Wo[k * 4 + 2], a2);
        a3 = fmaf(v, Wo[k * 4 + 3], a3);
    }
#pragma unroll
    for (int o = 16; o > 0; o >>= 1) {
        a0 += __shfl_down_sync(0xffffffffu, a0, o);
        a1 += __shfl_down_sync(0xffffffffu, a1, o);
        a2 += __shfl_down_sync(0xffffffffu, a2, o);
        a3 += __shfl_down_sync(0xffffffffu, a3, o);
    }
    if (lane == 0) {
        out[(size_t)b * 4 + 0] = a0 + bo[0];
        out[(size_t)b * 4 + 1] = a1 + bo[1];
        out[(size_t)b * 4 + 2] = a2 + bo[2];
        out[(size_t)b * 4 + 3] = a3 + bo[3];
    }
}

// ---------------- launcher --------------------------------------------------
extern "C" void kernel_launch(void* const* d_in, const int* in_sizes, int n_in,
                              void* d_out, int out_size) {
    const float* x   = (const float*)d_in[0];
    const void*  ei  = d_in[1];
    const float* ew  = (const float*)d_in[2];
    const float* W1  = (const float*)d_in[3];
    const float* b1  = (const float*)d_in[4];
    const float* W2  = (const float*)d_in[5];
    const float* b2  = (const float*)d_in[6];
    const float* Wf0 = (const float*)d_in[7];
    const float* bf0 = (const float*)d_in[8];
    const float* Wf1 = (const float*)d_in[9];
    const float* bf1 = (const float*)d_in[10];
    const float* Wf2 = (const float*)d_in[11];
    const float* bf2 = (const float*)d_in[12];
    const float* Wo  = (const float*)d_in[13];
    const float* bo  = (const float*)d_in[14];
    float* out = (float*)d_out;

    float* gf = nullptr;
    int*   gi = nullptr;
    cudaGetSymbolAddress((void**)&gf, g_f);
    cudaGetSymbolAddress((void**)&gi, g_i);

    float* deg  = gf + OFF_DEG;
    float* dinv = gf + OFF_DINV;
    float* nrm  = gf + OFF_NRM;
    float* hw   = gf + OFF_HW;
    float* h    = gf + OFF_H;
    float* flat = gf + OFF_FLAT;
    float* z0   = gf + OFF_Z0;
    float* z1   = gf + OFF_Z1;
    int*   cnt  = gi;
    int*   src  = gi + NN;

    const int NB_N = (NN + 255) / 256;
    const int NB_E = (EE + 255) / 256;

    // edge_index dtype detection + graph normalization + padded CSR build
    k_detect<<<1, 32>>>(ei);
    k_zero<<<NB_N, 256>>>(deg, cnt);
    k_deg <<<NB_E, 256>>>(ei, ew, deg);
    k_dinv<<<NB_N, 256>>>(deg, dinv);
    k_fill<<<NB_E, 256>>>(ei, ew, dinv, nrm, cnt, src);

    // conv1: hw = x @ W1 ; h = leaky(gather(hw) + b1)
    sgemm128<false, false><<<dim3(HID / 128, NN / 128, 1), 256>>>(
        x, W1, nullptr, hw, NN, HID, FEA, FEA);
    k_gather<0><<<NN, 256>>>(hw, b1, dinv, cnt, src, nrm, h);

    // conv2: hw = h @ W2 ; flat[h-part] = leaky(gather(hw) + b2)
    sgemm128<false, false><<<dim3(HID / 128, NN / 128, 1), 256>>>(
        h, W2, nullptr, hw, NN, HID, HID, HID);
    k_gather<1><<<NN, 256>>>(hw, b2, dinv, cnt, src, nrm, flat);

    // flat[x-part] = x
    k_xcopy<<<(int)(((long long)NN * FEA + 255) / 256), 256>>>(x, flat);

    const size_t ZBYTES = (size_t)BATCH * HID * sizeof(float);

    // MLP layer 0: split-K=8 (kstep 872, 6952 = 7*872 + 848)
    cudaMemsetAsync(z0, 0, ZBYTES);
    sgemm128<false, true><<<dim3(HID / 128, BATCH / 128, 8), 256>>>(
        flat, Wf0, nullptr, z0, BATCH, HID, MLP_IN, 872);
    k_epi<<<BATCH * HID / 256, 256>>>(z0, bf0);

    // MLP layer 1: split-K=4 (kstep 64)
    cudaMemsetAsync(z1, 0, ZBYTES);
    sgemm128<false, true><<<dim3(HID / 128, BATCH / 128, 4), 256>>>(
        z0, Wf1, nullptr, z1, BATCH, HID, HID, 64);
    k_epi<<<BATCH * HID / 256, 256>>>(z1, bf1);

    // MLP layer 2: split-K=4
    cudaMemsetAsync(z0, 0, ZBYTES);
    sgemm128<false, true><<<dim3(HID / 128, BATCH / 128, 4), 256>>>(
        z1, Wf2, nullptr, z0, BATCH, HID, HID, 64);
    k_epi<<<BATCH * HID / 256, 256>>>(z0, bf2);

    // head
    k_head<<<BATCH, 32>>>(z0, Wo, bo, out);
}

// round 5
// speedup vs baseline: 2.5230x; 1.3506x over previous
#include <cuda_runtime.h>
#include <cuda_bf16.h>
#include <cstdint>

typedef unsigned int u32;

#define NN 45056
#define EE 720896
#define FEA 60
#define HID 256
#define MACH 22
#define BATCH 2048
#define CAP 96
#define MLP_IN 6952
#define KP0 6960             // MLP_IN padded to x16
#define KP1 64               // FEA padded to x16
#define NEG_SLOPE 0.01f

// ---------------- fp32 scratch ----------------------------------------------
static constexpr size_t OFF_DEG  = 0;
static constexpr size_t OFF_DINV = OFF_DEG  + (size_t)NN;
static constexpr size_t OFF_NRM  = OFF_DINV + (size_t)NN;
static constexpr size_t OFF_HW   = OFF_NRM  + (size_t)NN * CAP;
static constexpr size_t OFF_Z0   = OFF_HW   + (size_t)NN * HID;
static constexpr size_t OFF_Z1   = OFF_Z0   + (size_t)BATCH * HID;
static constexpr size_t FTOTAL   = OFF_Z1   + (size_t)BATCH * HID;
__device__ float g_f[FTOTAL];

// ---------------- bf16 split scratch ----------------------------------------
static constexpr size_t XSZ  = (size_t)NN * KP1;
static constexpr size_t HSZ  = (size_t)NN * HID;
static constexpr size_t FSZ  = (size_t)BATCH * KP0;
static constexpr size_t W1SZ = (size_t)KP1 * HID;
static constexpr size_t W2SZ = (size_t)HID * HID;
static constexpr size_t F0SZ = (size_t)KP0 * HID;
static constexpr size_t ZSZ  = (size_t)BATCH * HID;
static constexpr size_t OFF_XH  = 0;
static constexpr size_t OFF_XL  = OFF_XH  + XSZ;
static constexpr size_t OFF_HH  = OFF_XL  + XSZ;
static constexpr size_t OFF_HL  = OFF_HH  + HSZ;
static constexpr size_t OFF_FH  = OFF_HL  + HSZ;
static constexpr size_t OFF_FL  = OFF_FH  + FSZ;
static constexpr size_t OFF_W1H = OFF_FL  + FSZ;
static constexpr size_t OFF_W1L = OFF_W1H + W1SZ;
static constexpr size_t OFF_W2H = OFF_W1L + W1SZ;
static constexpr size_t OFF_W2L = OFF_W2H + W2SZ;
static constexpr size_t OFF_F0H = OFF_W2L + W2SZ;
static constexpr size_t OFF_F0L = OFF_F0H + F0SZ;
static constexpr size_t OFF_F1H = OFF_F0L + F0SZ;
static constexpr size_t OFF_F1L = OFF_F1H + W2SZ;
static constexpr size_t OFF_F2H = OFF_F1L + W2SZ;
static constexpr size_t OFF_F2L = OFF_F2H + W2SZ;
static constexpr size_t OFF_ZH  = OFF_F2L + W2SZ;
static constexpr size_t OFF_ZL  = OFF_ZH  + ZSZ;
static constexpr size_t HTOTAL  = OFF_ZL  + ZSZ;
__device__ __align__(16) __nv_bfloat16 g_h[HTOTAL];

__device__ int g_i[(size_t)NN * (CAP + 1)];
__device__ int g_is32;

// ---------------- helpers ----------------------------------------------------
__device__ __forceinline__ void split2(float v, __nv_bfloat16* hi, __nv_bfloat16* lo) {
    __nv_bfloat16 h = __float2bfloat16(v);
    *hi = h;
    *lo = __float2bfloat16(v - __bfloat162float(h));
}

__device__ __forceinline__ u32 smem_u32(const void* p) {
    return (u32)__cvta_generic_to_shared(p);
}
__device__ __forceinline__ void ldsm_x4(u32* r, u32 a) {
    asm volatile("ldmatrix.sync.aligned.m8n8.x4.shared.b16 {%0,%1,%2,%3}, [%4];"
        : "=r"(r[0]), "=r"(r[1]), "=r"(r[2]), "=r"(r[3]) : "r"(a));
}
__device__ __forceinline__ void ldsm_x4_t(u32* r, u32 a) {
    asm volatile("ldmatrix.sync.aligned.m8n8.x4.trans.shared.b16 {%0,%1,%2,%3}, [%4];"
        : "=r"(r[0]), "=r"(r[1]), "=r"(r[2]), "=r"(r[3]) : "r"(a));
}
__device__ __forceinline__ void mma16816(float* c, const u32* a, const u32* b) {
    asm volatile(
        "mma.sync.aligned.m16n8k16.row.col.f32.bf16.bf16.f32 "
        "{%0,%1,%2,%3}, {%4,%5,%6,%7}, {%8,%9}, {%0,%1,%2,%3};"
        : "+f"(c[0]), "+f"(c[1]), "+f"(c[2]), "+f"(c[3])
        : "r"(a[0]), "r"(a[1]), "r"(a[2]), "r"(a[3]), "r"(b[0]), "r"(b[1]));
}

// ---------------- dtype detect / graph prep ---------------------------------
__global__ void k_detect(const void* __restrict__ ei) {
    if (threadIdx.x != 0 || blockIdx.x != 0) return;
    const long long* p = (const long long*)ei;
    int is32 = 0;
    for (int i = 0; i < 64; i++) {
        long long v = p[i];
        if (v < 0 || v >= NN) { is32 = 1; break; }
    }
    g_is32 = is32;
}
__device__ __forceinline__ int edge_idx(const void* ei, int half, int e, int is32) {
    if (is32) return ((const int*)ei)[(size_t)half * EE + e];
    return (int)((const long long*)ei)[(size_t)half * EE + e];
}
__global__ void k_zero(float* __restrict__ deg, int* __restrict__ cnt) {
    int i = blockIdx.x * 256 + threadIdx.x;
    if (i < NN) { deg[i] = 0.f; cnt[i] = 0; }
}
__global__ void k_deg(const void* __restrict__ ei, const float* __restrict__ ew,
                      float* __restrict__ deg) {
    int e = blockIdx.x * 256 + threadIdx.x;
    if (e >= EE) return;
    int c = edge_idx(ei, 1, e, g_is32);
    if ((unsigned)c < (unsigned)NN) atomicAdd(&deg[c], ew[e]);
}
__global__ void k_dinv(const float* __restrict__ deg, float* __restrict__ dinv) {
    int i = blockIdx.x * 256 + threadIdx.x;
    if (i < NN) dinv[i] = rsqrtf(deg[i] + 1.0f);
}
__global__ void k_fill(const void* __restrict__ ei, const float* __restrict__ ew,
                       const float* __restrict__ dinv, float* __restrict__ nrm,
                       int* __restrict__ cnt, int* __restrict__ src) {
    int e = blockIdx.x * 256 + threadIdx.x;
    if (e >= EE) return;
    int is32 = g_is32;
    int r = edge_idx(ei, 0, e, is32);
    int c = edge_idx(ei, 1, e, is32);
    if ((unsigned)r >= (unsigned)NN || (unsigned)c >= (unsigned)NN) return;
    float nv = dinv[r] * ew[e] * dinv[c];
    int p = atomicAdd(&cnt[c], 1);
    if (p < CAP) {
        src[(size_t)c * CAP + p] = r;
        nrm[(size_t)c * CAP + p] = nv;
    }
}

// ---------------- conversions ------------------------------------------------
__global__ void k_cvt_x(const float* __restrict__ x,
                        __nv_bfloat16* __restrict__ xh, __nv_bfloat16* __restrict__ xl) {
    size_t idx = (size_t)blockIdx.x * 256 + threadIdx.x;   // NN*KP1 threads
    int i = (int)(idx >> 6), k = (int)(idx & 63);
    float v = (k < FEA) ? x[(size_t)i * FEA + k] : 0.f;
    split2(v, &xh[idx], &xl[idx]);
}
__global__ void k_cvt_w(const float* __restrict__ w, int K,
                        __nv_bfloat16* __restrict__ wh, __nv_bfloat16* __restrict__ wl) {
    size_t idx = (size_t)blockIdx.x * 256 + threadIdx.x;   // KPAD*256 threads
    int k = (int)(idx >> 8);
    float v = (k < K) ? w[(size_t)k * HID + (idx & 255)] : 0.f;
    split2(v, &wh[idx], &wl[idx]);
}
__global__ void k_padflat(__nv_bfloat16* __restrict__ fh, __nv_bfloat16* __restrict__ fl) {
    int idx = blockIdx.x * 256 + threadIdx.x;              // BATCH*8 threads
    int b = idx >> 3, j = idx & 7;
    size_t p = (size_t)b * KP0 + MLP_IN + j;
    fh[p] = __float2bfloat16(0.f);
    fl[p] = __float2bfloat16(0.f);
}

// ---------------- tensor-core GEMM: C[M,256] = (Ah+Al)[M,K] @ (Bh+Bl)[K,256] -
template<bool ATOMIC>
__global__ __launch_bounds__(256)
void bmma(const __nv_bfloat16* __restrict__ Ah, const __nv_bfloat16* __restrict__ Al,
          const __nv_bfloat16* __restrict__ Bh, const __nv_bfloat16* __restrict__ Bl,
          float* __restrict__ C, int K, int kstep) {
    __shared__ __align__(16) __nv_bfloat16 As_h[128][24], As_l[128][24];
    __shared__ __align__(16) __nv_bfloat16 Bs_h[16][136], Bs_l[16][136];

    const int tid = threadIdx.x;
    const int lane = tid & 31, warp = tid >> 5;
    const int wm = warp >> 2, wn = warp & 3;             // 2 x 4 warps
    const int row0 = blockIdx.y * 128, col0 = blockIdx.x * 128;
    const int kb = blockIdx.z * kstep;
    const int ke = min(kb + kstep, K);

    const int ar = tid >> 1, ac = (tid & 1) * 8;         // A loader
    const int bkr = tid >> 4, bc = (tid & 15) * 8;       // B loader

    float acc[4][4][4];
#pragma unroll
    for (int i = 0; i < 4; i++)
#pragma unroll
        for (int j = 0; j < 4; j++)
#pragma unroll
            for (int q = 0; q < 4; q++) acc[i][j][q] = 0.f;

    const size_t a_base = (size_t)(row0 + ar) * K;
    uint4 pa_h = *(const uint4*)&Ah[a_base + kb + ac];
    uint4 pa_l = *(const uint4*)&Al[a_base + kb + ac];
    uint4 pb_h = *(const uint4*)&Bh[(size_t)(kb + bkr) * 256 + col0 + bc];
    uint4 pb_l = *(const uint4*)&Bl[(size_t)(kb + bkr) * 256 + col0 + bc];

    const int lr = (lane & 7) + ((lane >> 3) & 1) * 8;
    const int lc = (lane >> 4) * 8;
    u32 aaddr_h[4], aaddr_l[4], baddr_h[2], baddr_l[2];
#pragma unroll
    for (int mf = 0; mf < 4; mf++) {
        int r = wm * 64 + mf * 16 + lr;
        aaddr_h[mf] = smem_u32(&As_h[r][lc]);
        aaddr_l[mf] = smem_u32(&As_l[r][lc]);
    }
#pragma unroll
    for (int g = 0; g < 2; g++) {
        int n = wn * 32 + g * 16 + lc;
        baddr_h[g] = smem_u32(&Bs_h[lr][n]);
        baddr_l[g] = smem_u32(&Bs_l[lr][n]);
    }

    for (int k0 = kb; k0 < ke; k0 += 16) {
        *(uint4*)&As_h[ar][ac] = pa_h;
        *(uint4*)&As_l[ar][ac] = pa_l;
        *(uint4*)&Bs_h[bkr][bc] = pb_h;
        *(uint4*)&Bs_l[bkr][bc] = pb_l;
        __syncthreads();

        int k1 = k0 + 16;
        if (k1 < ke) {
            pa_h = *(const uint4*)&Ah[a_base + k1 + ac];
            pa_l = *(const uint4*)&Al[a_base + k1 + ac];
            pb_h = *(const uint4*)&Bh[(size_t)(k1 + bkr) * 256 + col0 + bc];
            pb_l = *(const uint4*)&Bl[(size_t)(k1 + bkr) * 256 + col0 + bc];
        }

        u32 a_h[4][4], a_l[4][4], b_h[4][2], b_l[4][2];
#pragma unroll
        for (int mf = 0; mf < 4; mf++) {
            ldsm_x4(a_h[mf], aaddr_h[mf]);
            ldsm_x4(a_l[mf], aaddr_l[mf]);
        }
#pragma unroll
        for (int g = 0; g < 2; g++) {
            u32 t[4];
            ldsm_x4_t(t, baddr_h[g]);
            b_h[2*g][0] = t[0]; b_h[2*g][1] = t[1];
            b_h[2*g+1][0] = t[2]; b_h[2*g+1][1] = t[3];
            ldsm_x4_t(t, baddr_l[g]);
            b_l[2*g][0] = t[0]; b_l[2*g][1] = t[1];
            b_l[2*g+1][0] = t[2]; b_l[2*g+1][1] = t[3];
        }
#pragma unroll
        for (int mf = 0; mf < 4; mf++)
#pragma unroll
            for (int nf = 0; nf < 4; nf++) {
                mma16816(acc[mf][nf], a_h[mf], b_h[nf]);
                mma16816(acc[mf][nf], a_h[mf], b_l[nf]);
                mma16816(acc[mf][nf], a_l[mf], b_h[nf]);
            }
        __syncthreads();
    }

    const int er = lane >> 2, ec = (lane & 3) * 2;
#pragma unroll
    for (int mf = 0; mf < 4; mf++)
#pragma unroll
        for (int nf = 0; nf < 4; nf++) {
            int r = row0 + wm * 64 + mf * 16 + er;
            int c = col0 + wn * 32 + nf * 8 + ec;
            float* p0 = &C[(size_t)r * 256 + c];
            float* p1 = &C[(size_t)(r + 8) * 256 + c];
            if (ATOMIC) {
                atomicAdd(p0,     acc[mf][nf][0]);
                atomicAdd(p0 + 1, acc[mf][nf][1]);
                atomicAdd(p1,     acc[mf][nf][2]);
                atomicAdd(p1 + 1, acc[mf][nf][3]);
            } else {
                p0[0] = acc[mf][nf][0]; p0[1] = acc[mf][nf][1];
                p1[0] = acc[mf][nf][2]; p1[1] = acc[mf][nf][3];
            }
        }
}

// ---------------- split-K epilogue: bias + leaky + bf16 split ---------------
__global__ void k_epi(float* __restrict__ z, const float* __restrict__ bias,
                      __nv_bfloat16* __restrict__ zh, __nv_bfloat16* __restrict__ zl) {
    int i = blockIdx.x * 256 + threadIdx.x;
    float v = z[i] + bias[i & (HID - 1)];
    v = v > 0.f ? v : NEG_SLOPE * v;
    z[i] = v;
    split2(v, &zh[i], &zl[i]);
}

// ---------------- GCN gather: writes split-bf16 output ----------------------
// MODE 0: h layout [i][256] ; MODE 1: flat layout b*KP0 + m*316 + t
template<int MODE>
__global__ __launch_bounds__(256)
void k_gather(const float* __restrict__ hw, const float* __restrict__ bias,
              const float* __restrict__ dinv, const int* __restrict__ cnt,
              const int* __restrict__ src, const float* __restrict__ nrm,
              __nv_bfloat16* __restrict__ oh, __nv_bfloat16* __restrict__ ol) {
    int i = blockIdx.x;
    int t = threadIdx.x;
    __shared__ int   ssrc[CAP];
    __shared__ float snrm[CAP];
    int c = cnt[i]; if (c > CAP) c = CAP;
    if (t < c) {
        ssrc[t] = src[(size_t)i * CAP + t];
        snrm[t] = nrm[(size_t)i * CAP + t];
    }
    __syncthreads();

    float di = dinv[i];
    float acc = di * di * hw[(size_t)i * HID + t];
    int e = 0;
    for (; e + 4 <= c; e += 4) {
        float v0 = hw[(size_t)ssrc[e]     * HID + t];
        float v1 = hw[(size_t)ssrc[e + 1] * HID + t];
        float v2 = hw[(size_t)ssrc[e + 2] * HID + t];
        float v3 = hw[(size_t)ssrc[e + 3] * HID + t];
        acc = fmaf(snrm[e],     v0, acc);
        acc = fmaf(snrm[e + 1], v1, acc);
        acc = fmaf(snrm[e + 2], v2, acc);
        acc = fmaf(snrm[e + 3], v3, acc);
    }
    for (; e < c; e++)
        acc = fmaf(snrm[e], hw[(size_t)ssrc[e] * HID + t], acc);

    acc += bias[t];
    acc = acc > 0.f ? acc : NEG_SLOPE * acc;

    size_t p;
    if (MODE == 0) {
        p = (size_t)i * HID + t;
    } else {
        int b = i / MACH, m = i - b * MACH;
        p = (size_t)b * KP0 + (size_t)m * (HID + FEA) + t;
    }
    split2(acc, &oh[p], &ol[p]);
}

// ---------------- x -> flat (split) ------------------------------------------
__global__ void k_xcopy(const float* __restrict__ x,
                        __nv_bfloat16* __restrict__ fh, __nv_bfloat16* __restrict__ fl) {
    long long idx = (long long)blockIdx.x * 256 + threadIdx.x;
    if (idx >= (long long)NN * FEA) return;
    int i = (int)(idx / FEA);
    int j = (int)(idx - (long long)i * FEA);
    int b = i / MACH, m = i - b * MACH;
    size_t p = (size_t)b * KP0 + (size_t)m * (HID + FEA) + HID + j;
    split2(x[idx], &fh[p], &fl[p]);
}

// ---------------- head -------------------------------------------------------
__global__ __launch_bounds__(32)
void k_head(const float* __restrict__ z, const float* __restrict__ Wo,
            const float* __restrict__ bo, float* __restrict__ out) {
    int b = blockIdx.x;
    int lane = threadIdx.x;
    float a0 = 0.f, a1 = 0.f, a2 = 0.f, a3 = 0.f;
    for (int k = lane; k < HID; k += 32) {
        float v = z[(size_t)b * HID + k];
        a0 = fmaf(v, Wo[k * 4 + 0], a0);
        a1 = fmaf(v, Wo[k * 4 + 1], a1);
        a2 = fmaf(v, Wo[k * 4 + 2], a2);
        a3 = fmaf(v, Wo[k * 4 + 3], a3);
    }
#pragma unroll
    for (int o = 16; o > 0; o >>= 1) {
        a0 += __shfl_down_sync(0xffffffffu, a0, o);
        a1 += __shfl_down_sync(0xffffffffu, a1, o);
        a2 += __shfl_down_sync(0xffffffffu, a2, o);
        a3 += __shfl_down_sync(0xffffffffu, a3, o);
    }
    if (lane == 0) {
        out[(size_t)b * 4 + 0] = a0 + bo[0];
        out[(size_t)b * 4 + 1] = a1 + bo[1];
        out[(size_t)b * 4 + 2] = a2 + bo[2];
        out[(size_t)b * 4 + 3] = a3 + bo[3];
    }
}

// ---------------- launcher ---------------------------------------------------
extern "C" void kernel_launch(void* const* d_in, const int* in_sizes, int n_in,
                              void* d_out, int out_size) {
    const float* x   = (const float*)d_in[0];
    const void*  ei  = d_in[1];
    const float* ew  = (const float*)d_in[2];
    const float* W1  = (const float*)d_in[3];
    const float* b1  = (const float*)d_in[4];
    const float* W2  = (const float*)d_in[5];
    const float* b2  = (const float*)d_in[6];
    const float* Wf0 = (const float*)d_in[7];
    const float* bf0 = (const float*)d_in[8];
    const float* Wf1 = (const float*)d_in[9];
    const float* bf1 = (const float*)d_in[10];
    const float* Wf2 = (const float*)d_in[11];
    const float* bf2 = (const float*)d_in[12];
    const float* Wo  = (const float*)d_in[13];
    const float* bo  = (const float*)d_in[14];
    float* out = (float*)d_out;

    float* gf = nullptr; int* gi = nullptr; __nv_bfloat16* gh = nullptr;
    cudaGetSymbolAddress((void**)&gf, g_f);
    cudaGetSymbolAddress((void**)&gi, g_i);
    cudaGetSymbolAddress((void**)&gh, g_h);

    float* deg  = gf + OFF_DEG;
    float* dinv = gf + OFF_DINV;
    float* nrm  = gf + OFF_NRM;
    float* hw   = gf + OFF_HW;
    float* z0   = gf + OFF_Z0;
    float* z1   = gf + OFF_Z1;
    int*   cnt  = gi;
    int*   src  = gi + NN;

    __nv_bfloat16 *xh = gh + OFF_XH,  *xl = gh + OFF_XL;
    __nv_bfloat16 *hh = gh + OFF_HH,  *hl = gh + OFF_HL;
    __nv_bfloat16 *fh = gh + OFF_FH,  *fl = gh + OFF_FL;
    __nv_bfloat16 *w1h = gh + OFF_W1H, *w1l = gh + OFF_W1L;
    __nv_bfloat16 *w2h = gh + OFF_W2H, *w2l = gh + OFF_W2L;
    __nv_bfloat16 *f0h = gh + OFF_F0H, *f0l = gh + OFF_F0L;
    __nv_bfloat16 *f1h = gh + OFF_F1H, *f1l = gh + OFF_F1L;
    __nv_bfloat16 *f2h = gh + OFF_F2H, *f2l = gh + OFF_F2L;
    __nv_bfloat16 *zh = gh + OFF_ZH,   *zl = gh + OFF_ZL;

    const int NB_N = (NN + 255) / 256;
    const int NB_E = (EE + 255) / 256;

    // graph prep
    k_detect<<<1, 32>>>(ei);
    k_zero<<<NB_N, 256>>>(deg, cnt);
    k_deg <<<NB_E, 256>>>(ei, ew, deg);
    k_dinv<<<NB_N, 256>>>(deg, dinv);
    k_fill<<<NB_E, 256>>>(ei, ew, dinv, nrm, cnt, src);

    // conversions
    k_cvt_x<<<(int)(XSZ / 256), 256>>>(x, xh, xl);
    k_cvt_w<<<KP1, 256>>>(W1, FEA, w1h, w1l);
    k_cvt_w<<<HID, 256>>>(W2, HID, w2h, w2l);
    k_cvt_w<<<KP0, 256>>>(Wf0, MLP_IN, f0h, f0l);
    k_cvt_w<<<HID, 256>>>(Wf1, HID, f1h, f1l);
    k_cvt_w<<<HID, 256>>>(Wf2, HID, f2h, f2l);

    // conv1
    bmma<false><<<dim3(2, NN / 128, 1), 256>>>(xh, xl, w1h, w1l, hw, KP1, KP1);
    k_gather<0><<<NN, 256>>>(hw, b1, dinv, cnt, src, nrm, hh, hl);

    // conv2
    bmma<false><<<dim3(2, NN / 128, 1), 256>>>(hh, hl, w2h, w2l, hw, HID, HID);
    k_gather<1><<<NN, 256>>>(hw, b2, dinv, cnt, src, nrm, fh, fl);
    k_xcopy<<<(int)(((long long)NN * FEA + 255) / 256), 256>>>(x, fh, fl);
    k_padflat<<<BATCH * 8 / 256, 256>>>(fh, fl);

    const size_t ZBYTES = (size_t)BATCH * HID * sizeof(float);

    // MLP0: split-K=8 (7*880 + 800)
    cudaMemsetAsync(z0, 0, ZBYTES);
    bmma<true><<<dim3(2, BATCH / 128, 8), 256>>>(fh, fl, f0h, f0l, z0, KP0, 880);
    k_epi<<<BATCH * HID / 256, 256>>>(z0, bf0, zh, zl);

    // MLP1: split-K=4
    cudaMemsetAsync(z1, 0, ZBYTES);
    bmma<true><<<dim3(2, BATCH / 128, 4), 256>>>(zh, zl, f1h, f1l, z1, HID, 64);
    k_epi<<<BATCH * HID / 256, 256>>>(z1, bf1, zh, zl);

    // MLP2: split-K=4
    cudaMemsetAsync(z0, 0, ZBYTES);
    bmma<true><<<dim3(2, BATCH / 128, 4), 256>>>(zh, zl, f2h, f2l, z0, HID, 64);
    k_epi<<<BATCH * HID / 256, 256>>>(z0, bf2, zh, zl);

    // head
    k_head<<<BATCH, 32>>>(z0, Wo, bo, out);
}

// round 6
// speedup vs baseline: 3.2741x; 1.2977x over previous
#include <cuda_runtime.h>
#include <cuda_bf16.h>
#include <cstdint>

typedef unsigned int u32;

#define NN 45056
#define EE 720896
#define FEA 60
#define HID 256
#define MACH 22
#define BATCH 2048
#define CAP 96
#define MLP_IN 6952
#define KP0 6960             // MLP_IN padded to x16
#define KP1 64               // FEA padded to x16
#define NEG_SLOPE 0.01f

// ---------------- fp32 scratch ----------------------------------------------
static constexpr size_t OFF_DEG  = 0;
static constexpr size_t OFF_DINV = OFF_DEG  + (size_t)NN;
static constexpr size_t OFF_SEW  = OFF_DINV + (size_t)NN;          // raw edge weights per slot
static constexpr size_t OFF_Z0   = OFF_SEW  + (size_t)NN * CAP;
static constexpr size_t OFF_Z1   = OFF_Z0   + (size_t)BATCH * HID;
static constexpr size_t FTOTAL   = OFF_Z1   + (size_t)BATCH * HID;
__device__ float g_f[FTOTAL];

// ---------------- bf16 split scratch ----------------------------------------
static constexpr size_t XSZ  = (size_t)NN * KP1;       // aggregated x
static constexpr size_t HSZ  = (size_t)NN * HID;       // h and agg_h
static constexpr size_t FSZ  = (size_t)BATCH * KP0;
static constexpr size_t W1SZ = (size_t)KP1 * HID;
static constexpr size_t W2SZ = (size_t)HID * HID;
static constexpr size_t F0SZ = (size_t)KP0 * HID;
static constexpr size_t ZSZ  = (size_t)BATCH * HID;
static constexpr size_t OFF_XH  = 0;
static constexpr size_t OFF_XL  = OFF_XH  + XSZ;
static constexpr size_t OFF_HH  = OFF_XL  + XSZ;
static constexpr size_t OFF_HL  = OFF_HH  + HSZ;
static constexpr size_t OFF_AH  = OFF_HL  + HSZ;
static constexpr size_t OFF_AL  = OFF_AH  + HSZ;
static constexpr size_t OFF_FH  = OFF_AL  + HSZ;
static constexpr size_t OFF_FL  = OFF_FH  + FSZ;
static constexpr size_t OFF_W1H = OFF_FL  + FSZ;
static constexpr size_t OFF_W1L = OFF_W1H + W1SZ;
static constexpr size_t OFF_W2H = OFF_W1L + W1SZ;
static constexpr size_t OFF_W2L = OFF_W2H + W2SZ;
static constexpr size_t OFF_F0H = OFF_W2L + W2SZ;
static constexpr size_t OFF_F0L = OFF_F0H + F0SZ;
static constexpr size_t OFF_F1H = OFF_F0L + F0SZ;
static constexpr size_t OFF_F1L = OFF_F1H + W2SZ;
static constexpr size_t OFF_F2H = OFF_F1L + W2SZ;
static constexpr size_t OFF_F2L = OFF_F2H + W2SZ;
static constexpr size_t OFF_ZH  = OFF_F2L + W2SZ;
static constexpr size_t OFF_ZL  = OFF_ZH  + ZSZ;
static constexpr size_t HTOTAL  = OFF_ZL  + ZSZ;
__device__ __align__(16) __nv_bfloat16 g_h[HTOTAL];

__device__ int g_i[(size_t)NN * (CAP + 1)];
__device__ int g_is32;

// ---------------- helpers ----------------------------------------------------
__device__ __forceinline__ void split2(float v, __nv_bfloat16* hi, __nv_bfloat16* lo) {
    __nv_bfloat16 h = __float2bfloat16(v);
    *hi = h;
    *lo = __float2bfloat16(v - __bfloat162float(h));
}
__device__ __forceinline__ u32 smem_u32(const void* p) {
    return (u32)__cvta_generic_to_shared(p);
}
__device__ __forceinline__ void ldsm_x4(u32* r, u32 a) {
    asm volatile("ldmatrix.sync.aligned.m8n8.x4.shared.b16 {%0,%1,%2,%3}, [%4];"
        : "=r"(r[0]), "=r"(r[1]), "=r"(r[2]), "=r"(r[3]) : "r"(a));
}
__device__ __forceinline__ void ldsm_x4_t(u32* r, u32 a) {
    asm volatile("ldmatrix.sync.aligned.m8n8.x4.trans.shared.b16 {%0,%1,%2,%3}, [%4];"
        : "=r"(r[0]), "=r"(r[1]), "=r"(r[2]), "=r"(r[3]) : "r"(a));
}
__device__ __forceinline__ void mma16816(float* c, const u32* a, const u32* b) {
    asm volatile(
        "mma.sync.aligned.m16n8k16.row.col.f32.bf16.bf16.f32 "
        "{%0,%1,%2,%3}, {%4,%5,%6,%7}, {%8,%9}, {%0,%1,%2,%3};"
        : "+f"(c[0]), "+f"(c[1]), "+f"(c[2]), "+f"(c[3])
        : "r"(a[0]), "r"(a[1]), "r"(a[2]), "r"(a[3]), "r"(b[0]), "r"(b[1]));
}

// ---------------- dtype detect / graph prep ---------------------------------
__global__ void k_detect(const void* __restrict__ ei) {
    if (threadIdx.x != 0 || blockIdx.x != 0) return;
    const long long* p = (const long long*)ei;
    int is32 = 0;
    for (int i = 0; i < 64; i++) {
        long long v = p[i];
        if (v < 0 || v >= NN) { is32 = 1; break; }
    }
    g_is32 = is32;
}
__device__ __forceinline__ int edge_idx(const void* ei, int half, int e, int is32) {
    if (is32) return ((const int*)ei)[(size_t)half * EE + e];
    return (int)((const long long*)ei)[(size_t)half * EE + e];
}
__global__ void k_zero(float* __restrict__ deg, int* __restrict__ cnt) {
    int i = blockIdx.x * 256 + threadIdx.x;
    if (i < NN) { deg[i] = 0.f; cnt[i] = 0; }
}
// single edge pass: degree accumulation + padded-CSR fill (raw weights)
__global__ void k_degfill(const void* __restrict__ ei, const float* __restrict__ ew,
                          float* __restrict__ deg, int* __restrict__ cnt,
                          int* __restrict__ src, float* __restrict__ sew) {
    int e = blockIdx.x * 256 + threadIdx.x;
    if (e >= EE) return;
    int is32 = g_is32;
    int r = edge_idx(ei, 0, e, is32);
    int c = edge_idx(ei, 1, e, is32);
    if ((unsigned)r >= (unsigned)NN || (unsigned)c >= (unsigned)NN) return;
    float w = ew[e];
    atomicAdd(&deg[c], w);
    int p = atomicAdd(&cnt[c], 1);
    if (p < CAP) {
        src[(size_t)c * CAP + p] = r;
        sew[(size_t)c * CAP + p] = w;
    }
}
__global__ void k_dinv(const float* __restrict__ deg, float* __restrict__ dinv) {
    int i = blockIdx.x * 256 + threadIdx.x;
    if (i < NN) dinv[i] = rsqrtf(deg[i] + 1.0f);
}

// ---------------- weight conversions ------------------------------------------
__global__ void k_cvt_w(const float* __restrict__ w, int K,
                        __nv_bfloat16* __restrict__ wh, __nv_bfloat16* __restrict__ wl) {
    size_t idx = (size_t)blockIdx.x * 256 + threadIdx.x;
    int k = (int)(idx >> 8);
    float v = (k < K) ? w[(size_t)k * HID + (idx & 255)] : 0.f;
    split2(v, &wh[idx], &wl[idx]);
}
__global__ void k_padflat(__nv_bfloat16* __restrict__ fh, __nv_bfloat16* __restrict__ fl) {
    int idx = blockIdx.x * 256 + threadIdx.x;
    int b = idx >> 3, j = idx & 7;
    size_t p = (size_t)b * KP0 + MLP_IN + j;
    fh[p] = __float2bfloat16(0.f);
    fl[p] = __float2bfloat16(0.f);
}

// ---------------- gather of raw x (pre-conv1): 4 nodes/block ----------------
__global__ __launch_bounds__(256)
void k_gather_x(const float* __restrict__ x, const float* __restrict__ dinv,
                const int* __restrict__ cnt, const int* __restrict__ src,
                const float* __restrict__ sew,
                __nv_bfloat16* __restrict__ oh, __nv_bfloat16* __restrict__ ol) {
    int sub = threadIdx.x >> 6, lane = threadIdx.x & 63;
    int i = blockIdx.x * 4 + sub;
    __shared__ int   ssrc[4][CAP];
    __shared__ float snrm[4][CAP];
    int c = cnt[i]; if (c > CAP) c = CAP;
    float di = dinv[i];
    for (int e = lane; e < c; e += 64) {
        int s = src[(size_t)i * CAP + e];
        ssrc[sub][e] = s;
        snrm[sub][e] = dinv[s] * sew[(size_t)i * CAP + e] * di;
    }
    __syncthreads();
    float acc = 0.f;
    if (lane < FEA) {
        acc = di * di * x[(size_t)i * FEA + lane];
        int e = 0;
        for (; e + 2 <= c; e += 2) {
            float v0 = x[(size_t)ssrc[sub][e]     * FEA + lane];
            float v1 = x[(size_t)ssrc[sub][e + 1] * FEA + lane];
            acc = fmaf(snrm[sub][e],     v0, acc);
            acc = fmaf(snrm[sub][e + 1], v1, acc);
        }
        if (e < c)
            acc = fmaf(snrm[sub][e], x[(size_t)ssrc[sub][e] * FEA + lane], acc);
    }
    size_t p = (size_t)i * KP1 + lane;
    split2(acc, &oh[p], &ol[p]);
}

// ---------------- gather of h (pre-conv2): 2 nodes/block, bf16x2 lanes ------
__global__ __launch_bounds__(256)
void k_gather_h(const __nv_bfloat16* __restrict__ hh, const __nv_bfloat16* __restrict__ hl,
                const float* __restrict__ dinv, const int* __restrict__ cnt,
                const int* __restrict__ src, const float* __restrict__ sew,
                __nv_bfloat16* __restrict__ ah, __nv_bfloat16* __restrict__ al) {
    int sub = threadIdx.x >> 7, lane = threadIdx.x & 127;
    int i = blockIdx.x * 2 + sub;
    __shared__ int   ssrc[2][CAP];
    __shared__ float snrm[2][CAP];
    int c = cnt[i]; if (c > CAP) c = CAP;
    float di = dinv[i];
    if (lane < c) {
        int s = src[(size_t)i * CAP + lane];
        ssrc[sub][lane] = s;
        snrm[sub][lane] = dinv[s] * sew[(size_t)i * CAP + lane] * di;
    }
    __syncthreads();

    const int col = lane * 2;
    float ax, ay;
    {
        __nv_bfloat162 vh = *(const __nv_bfloat162*)&hh[(size_t)i * HID + col];
        __nv_bfloat162 vl = *(const __nv_bfloat162*)&hl[(size_t)i * HID + col];
        float s = di * di;
        ax = s * (__bfloat162float(vh.x) + __bfloat162float(vl.x));
        ay = s * (__bfloat162float(vh.y) + __bfloat162float(vl.y));
    }
    int e = 0;
    for (; e + 2 <= c; e += 2) {
        size_t r0 = (size_t)ssrc[sub][e]     * HID + col;
        size_t r1 = (size_t)ssrc[sub][e + 1] * HID + col;
        __nv_bfloat162 h0 = *(const __nv_bfloat162*)&hh[r0];
        __nv_bfloat162 l0 = *(const __nv_bfloat162*)&hl[r0];
        __nv_bfloat162 h1 = *(const __nv_bfloat162*)&hh[r1];
        __nv_bfloat162 l1 = *(const __nv_bfloat162*)&hl[r1];
        float w0 = snrm[sub][e], w1 = snrm[sub][e + 1];
        ax = fmaf(w0, __bfloat162float(h0.x) + __bfloat162float(l0.x), ax);
        ay = fmaf(w0, __bfloat162float(h0.y) + __bfloat162float(l0.y), ay);
        ax = fmaf(w1, __bfloat162float(h1.x) + __bfloat162float(l1.x), ax);
        ay = fmaf(w1, __bfloat162float(h1.y) + __bfloat162float(l1.y), ay);
    }
    if (e < c) {
        size_t r0 = (size_t)ssrc[sub][e] * HID + col;
        __nv_bfloat162 h0 = *(const __nv_bfloat162*)&hh[r0];
        __nv_bfloat162 l0 = *(const __nv_bfloat162*)&hl[r0];
        float w0 = snrm[sub][e];
        ax = fmaf(w0, __bfloat162float(h0.x) + __bfloat162float(l0.x), ax);
        ay = fmaf(w0, __bfloat162float(h0.y) + __bfloat162float(l0.y), ay);
    }

    __nv_bfloat16 hx, lx, hy, ly;
    split2(ax, &hx, &lx);
    split2(ay, &hy, &ly);
    size_t p = (size_t)i * HID + col;
    *(__nv_bfloat162*)&ah[p] = __nv_bfloat162(hx, hy);
    *(__nv_bfloat162*)&al[p] = __nv_bfloat162(lx, ly);
}

// ---------------- tensor-core GEMM ------------------------------------------
// C/out[M,256] = (Ah+Al)[M,K] @ (Bh+Bl)[K,256]
// MODE 0: fp32 atomicAdd into C (split-K), no bias
// MODE 1: bias + leaky + split-bf16 store, linear stride 256 (conv1 -> h)
// MODE 2: bias + leaky + split-bf16 store, flat-mapped (conv2 -> flat)
template<int MODE>
__global__ __launch_bounds__(256)
void bmma(const __nv_bfloat16* __restrict__ Ah, const __nv_bfloat16* __restrict__ Al,
          const __nv_bfloat16* __restrict__ Bh, const __nv_bfloat16* __restrict__ Bl,
          float* __restrict__ C, const float* __restrict__ bias,
          __nv_bfloat16* __restrict__ oh, __nv_bfloat16* __restrict__ ol,
          int K, int kstep) {
    __shared__ __align__(16) __nv_bfloat16 As_h[128][24], As_l[128][24];
    __shared__ __align__(16) __nv_bfloat16 Bs_h[16][136], Bs_l[16][136];

    const int tid = threadIdx.x;
    const int lane = tid & 31, warp = tid >> 5;
    const int wm = warp >> 2, wn = warp & 3;
    const int row0 = blockIdx.y * 128, col0 = blockIdx.x * 128;
    const int kb = blockIdx.z * kstep;
    const int ke = min(kb + kstep, K);

    const int ar = tid >> 1, ac = (tid & 1) * 8;
    const int bkr = tid >> 4, bc = (tid & 15) * 8;

    float acc[4][4][4];
#pragma unroll
    for (int i = 0; i < 4; i++)
#pragma unroll
        for (int j = 0; j < 4; j++)
#pragma unroll
            for (int q = 0; q < 4; q++) acc[i][j][q] = 0.f;

    const size_t a_base = (size_t)(row0 + ar) * K;
    uint4 pa_h = *(const uint4*)&Ah[a_base + kb + ac];
    uint4 pa_l = *(const uint4*)&Al[a_base + kb + ac];
    uint4 pb_h = *(const uint4*)&Bh[(size_t)(kb + bkr) * 256 + col0 + bc];
    uint4 pb_l = *(const uint4*)&Bl[(size_t)(kb + bkr) * 256 + col0 + bc];

    const int lr = (lane & 7) + ((lane >> 3) & 1) * 8;
    const int lc = (lane >> 4) * 8;
    u32 aaddr_h[4], aaddr_l[4], baddr_h[2], baddr_l[2];
#pragma unroll
    for (int mf = 0; mf < 4; mf++) {
        int r = wm * 64 + mf * 16 + lr;
        aaddr_h[mf] = smem_u32(&As_h[r][lc]);
        aaddr_l[mf] = smem_u32(&As_l[r][lc]);
    }
#pragma unroll
    for (int g = 0; g < 2; g++) {
        int n = wn * 32 + g * 16 + lc;
        baddr_h[g] = smem_u32(&Bs_h[lr][n]);
        baddr_l[g] = smem_u32(&Bs_l[lr][n]);
    }

    for (int k0 = kb; k0 < ke; k0 += 16) {
        *(uint4*)&As_h[ar][ac] = pa_h;
        *(uint4*)&As_l[ar][ac] = pa_l;
        *(uint4*)&Bs_h[bkr][bc] = pb_h;
        *(uint4*)&Bs_l[bkr][bc] = pb_l;
        __syncthreads();

        int k1 = k0 + 16;
        if (k1 < ke) {
            pa_h = *(const uint4*)&Ah[a_base + k1 + ac];
            pa_l = *(const uint4*)&Al[a_base + k1 + ac];
            pb_h = *(const uint4*)&Bh[(size_t)(k1 + bkr) * 256 + col0 + bc];
            pb_l = *(const uint4*)&Bl[(size_t)(k1 + bkr) * 256 + col0 + bc];
        }

        u32 a_h[4][4], a_l[4][4], b_h[4][2], b_l[4][2];
#pragma unroll
        for (int mf = 0; mf < 4; mf++) {
            ldsm_x4(a_h[mf], aaddr_h[mf]);
            ldsm_x4(a_l[mf], aaddr_l[mf]);
        }
#pragma unroll
        for (int g = 0; g < 2; g++) {
            u32 t[4];
            ldsm_x4_t(t, baddr_h[g]);
            b_h[2*g][0] = t[0]; b_h[2*g][1] = t[1];
            b_h[2*g+1][0] = t[2]; b_h[2*g+1][1] = t[3];
            ldsm_x4_t(t, baddr_l[g]);
            b_l[2*g][0] = t[0]; b_l[2*g][1] = t[1];
            b_l[2*g+1][0] = t[2]; b_l[2*g+1][1] = t[3];
        }
#pragma unroll
        for (int mf = 0; mf < 4; mf++)
#pragma unroll
            for (int nf = 0; nf < 4; nf++) {
                mma16816(acc[mf][nf], a_h[mf], b_h[nf]);
                mma16816(acc[mf][nf], a_h[mf], b_l[nf]);
                mma16816(acc[mf][nf], a_l[mf], b_h[nf]);
            }
        __syncthreads();
    }

    const int er = lane >> 2, ec = (lane & 3) * 2;
#pragma unroll
    for (int mf = 0; mf < 4; mf++)
#pragma unroll
        for (int nf = 0; nf < 4; nf++) {
            int r = row0 + wm * 64 + mf * 16 + er;
            int c = col0 + wn * 32 + nf * 8 + ec;
            if (MODE == 0) {
                float* p0 = &C[(size_t)r * 256 + c];
                float* p1 = &C[(size_t)(r + 8) * 256 + c];
                atomicAdd(p0,     acc[mf][nf][0]);
                atomicAdd(p0 + 1, acc[mf][nf][1]);
                atomicAdd(p1,     acc[mf][nf][2]);
                atomicAdd(p1 + 1, acc[mf][nf][3]);
            } else {
                float bv0 = bias[c], bv1 = bias[c + 1];
#pragma unroll
                for (int half = 0; half < 2; half++) {
                    int rr = r + half * 8;
                    float v0 = acc[mf][nf][half * 2]     + bv0;
                    float v1 = acc[mf][nf][half * 2 + 1] + bv1;
                    v0 = v0 > 0.f ? v0 : NEG_SLOPE * v0;
                    v1 = v1 > 0.f ? v1 : NEG_SLOPE * v1;
                    __nv_bfloat16 h0, l0, h1, l1;
                    split2(v0, &h0, &l0);
                    split2(v1, &h1, &l1);
                    size_t p;
                    if (MODE == 1) {
                        p = (size_t)rr * 256 + c;
                    } else {
                        int b = rr / MACH, m = rr - b * MACH;
                        p = (size_t)b * KP0 + (size_t)m * (HID + FEA) + c;
                    }
                    *(__nv_bfloat162*)&oh[p] = __nv_bfloat162(h0, h1);
                    *(__nv_bfloat162*)&ol[p] = __nv_bfloat162(l0, l1);
                }
            }
        }
}

// ---------------- split-K epilogue: bias + leaky + bf16 split ---------------
__global__ void k_epi(float* __restrict__ z, const float* __restrict__ bias,
                      __nv_bfloat16* __restrict__ zh, __nv_bfloat16* __restrict__ zl) {
    int i = blockIdx.x * 256 + threadIdx.x;
    float v = z[i] + bias[i & (HID - 1)];
    v = v > 0.f ? v : NEG_SLOPE * v;
    z[i] = v;
    split2(v, &zh[i], &zl[i]);
}

// ---------------- x -> flat (split) ------------------------------------------
__global__ void k_xcopy(const float* __restrict__ x,
                        __nv_bfloat16* __restrict__ fh, __nv_bfloat16* __restrict__ fl) {
    long long idx = (long long)blockIdx.x * 256 + threadIdx.x;
    if (idx >= (long long)NN * FEA) return;
    int i = (int)(idx / FEA);
    int j = (int)(idx - (long long)i * FEA);
    int b = i / MACH, m = i - b * MACH;
    size_t p = (size_t)b * KP0 + (size_t)m * (HID + FEA) + HID + j;
    split2(x[idx], &fh[p], &fl[p]);
}

// ---------------- head -------------------------------------------------------
__global__ __launch_bounds__(32)
void k_head(const float* __restrict__ z, const float* __restrict__ Wo,
            const float* __restrict__ bo, float* __restrict__ out) {
    int b = blockIdx.x;
    int lane = threadIdx.x;
    float a0 = 0.f, a1 = 0.f, a2 = 0.f, a3 = 0.f;
    for (int k = lane; k < HID; k += 32) {
        float v = z[(size_t)b * HID + k];
        a0 = fmaf(v, Wo[k * 4 + 0], a0);
        a1 = fmaf(v, Wo[k * 4 + 1], a1);
        a2 = fmaf(v, Wo[k * 4 + 2], a2);
        a3 = fmaf(v, Wo[k * 4 + 3], a3);
    }
#pragma unroll
    for (int o = 16; o > 0; o >>= 1) {
        a0 += __shfl_down_sync(0xffffffffu, a0, o);
        a1 += __shfl_down_sync(0xffffffffu, a1, o);
        a2 += __shfl_down_sync(0xffffffffu, a2, o);
        a3 += __shfl_down_sync(0xffffffffu, a3, o);
    }
    if (lane == 0) {
        out[(size_t)b * 4 + 0] = a0 + bo[0];
        out[(size_t)b * 4 + 1] = a1 + bo[1];
        out[(size_t)b * 4 + 2] = a2 + bo[2];
        out[(size_t)b * 4 + 3] = a3 + bo[3];
    }
}

// ---------------- launcher ---------------------------------------------------
extern "C" void kernel_launch(void* const* d_in, const int* in_sizes, int n_in,
                              void* d_out, int out_size) {
    const float* x   = (const float*)d_in[0];
    const void*  ei  = d_in[1];
    const float* ew  = (const float*)d_in[2];
    const float* W1  = (const float*)d_in[3];
    const float* b1  = (const float*)d_in[4];
    const float* W2  = (const float*)d_in[5];
    const float* b2  = (const float*)d_in[6];
    const float* Wf0 = (const float*)d_in[7];
    const float* bf0 = (const float*)d_in[8];
    const float* Wf1 = (const float*)d_in[9];
    const float* bf1 = (const float*)d_in[10];
    const float* Wf2 = (const float*)d_in[11];
    const float* bf2 = (const float*)d_in[12];
    const float* Wo  = (const float*)d_in[13];
    const float* bo  = (const float*)d_in[14];
    float* out = (float*)d_out;

    float* gf = nullptr; int* gi = nullptr; __nv_bfloat16* gh = nullptr;
    cudaGetSymbolAddress((void**)&gf, g_f);
    cudaGetSymbolAddress((void**)&gi, g_i);
    cudaGetSymbolAddress((void**)&gh, g_h);

    float* deg  = gf + OFF_DEG;
    float* dinv = gf + OFF_DINV;
    float* sew  = gf + OFF_SEW;
    float* z0   = gf + OFF_Z0;
    float* z1   = gf + OFF_Z1;
    int*   cnt  = gi;
    int*   src  = gi + NN;

    __nv_bfloat16 *xh = gh + OFF_XH,  *xl = gh + OFF_XL;
    __nv_bfloat16 *hh = gh + OFF_HH,  *hl = gh + OFF_HL;
    __nv_bfloat16 *ah = gh + OFF_AH,  *al = gh + OFF_AL;
    __nv_bfloat16 *fh = gh + OFF_FH,  *fl = gh + OFF_FL;
    __nv_bfloat16 *w1h = gh + OFF_W1H, *w1l = gh + OFF_W1L;
    __nv_bfloat16 *w2h = gh + OFF_W2H, *w2l = gh + OFF_W2L;
    __nv_bfloat16 *f0h = gh + OFF_F0H, *f0l = gh + OFF_F0L;
    __nv_bfloat16 *f1h = gh + OFF_F1H, *f1l = gh + OFF_F1L;
    __nv_bfloat16 *f2h = gh + OFF_F2H, *f2l = gh + OFF_F2L;
    __nv_bfloat16 *zh = gh + OFF_ZH,   *zl = gh + OFF_ZL;

    const int NB_N = (NN + 255) / 256;
    const int NB_E = (EE + 255) / 256;

    // graph prep (single edge pass)
    k_detect<<<1, 32>>>(ei);
    k_zero<<<NB_N, 256>>>(deg, cnt);
    k_degfill<<<NB_E, 256>>>(ei, ew, deg, cnt, src, sew);
    k_dinv<<<NB_N, 256>>>(deg, dinv);

    // weight conversions
    k_cvt_w<<<KP1, 256>>>(W1, FEA, w1h, w1l);
    k_cvt_w<<<HID, 256>>>(W2, HID, w2h, w2l);
    k_cvt_w<<<KP0, 256>>>(Wf0, MLP_IN, f0h, f0l);
    k_cvt_w<<<HID, 256>>>(Wf1, HID, f1h, f1l);
    k_cvt_w<<<HID, 256>>>(Wf2, HID, f2h, f2l);

    // conv1: aggx = agg(x) ; h = leaky(aggx @ W1 + b1)  (split-bf16 out)
    k_gather_x<<<NN / 4, 256>>>(x, dinv, cnt, src, sew, xh, xl);
    bmma<1><<<dim3(2, NN / 128, 1), 256>>>(xh, xl, w1h, w1l,
                                           nullptr, b1, hh, hl, KP1, KP1);

    // conv2: aggh = agg(h) ; flat[h-part] = leaky(aggh @ W2 + b2)
    k_gather_h<<<NN / 2, 256>>>(hh, hl, dinv, cnt, src, sew, ah, al);
    bmma<2><<<dim3(2, NN / 128, 1), 256>>>(ah, al, w2h, w2l,
                                           nullptr, b2, fh, fl, HID, HID);

    // flat[x-part] = x ; pad tail
    k_xcopy<<<(int)(((long long)NN * FEA + 255) / 256), 256>>>(x, fh, fl);
    k_padflat<<<BATCH * 8 / 256, 256>>>(fh, fl);

    const size_t ZBYTES = (size_t)BATCH * HID * sizeof(float);

    // MLP0: split-K=8 (7*880 + 800)
    cudaMemsetAsync(z0, 0, ZBYTES);
    bmma<0><<<dim3(2, BATCH / 128, 8), 256>>>(fh, fl, f0h, f0l,
                                              z0, nullptr, nullptr, nullptr, KP0, 880);
    k_epi<<<BATCH * HID / 256, 256>>>(z0, bf0, zh, zl);

    // MLP1: split-K=4
    cudaMemsetAsync(z1, 0, ZBYTES);
    bmma<0><<<dim3(2, BATCH / 128, 4), 256>>>(zh, zl, f1h, f1l,
                                              z1, nullptr, nullptr, nullptr, HID, 64);
    k_epi<<<BATCH * HID / 256, 256>>>(z1, bf1, zh, zl);

    // MLP2: split-K=4
    cudaMemsetAsync(z0, 0, ZBYTES);
    bmma<0><<<dim3(2, BATCH / 128, 4), 256>>>(zh, zl, f2h, f2l,
                                              z0, nullptr, nullptr, nullptr, HID, 64);
    k_epi<<<BATCH * HID / 256, 256>>>(z0, bf2, zh, zl);

    // head
    k_head<<<BATCH, 32>>>(z0, Wo, bo, out);
}

// round 7
// speedup vs baseline: 3.4611x; 1.0571x over previous
#include <cuda_runtime.h>
#include <cuda_bf16.h>
#include <cstdint>

typedef unsigned int u32;

#define NN 45056
#define EE 720896
#define FEA 60
#define HID 256
#define MACH 22
#define BATCH 2048
#define CAP 96
#define MLP_IN 6952
#define KP0 6960             // MLP_IN padded to x16
#define KP1 64               // FEA padded to x16
#define NEG_SLOPE 0.01f

// ---------------- fp32 scratch ----------------------------------------------
static constexpr size_t OFF_DEG  = 0;
static constexpr size_t OFF_DINV = OFF_DEG  + (size_t)NN;
static constexpr size_t OFF_SEW  = OFF_DINV + (size_t)NN;
static constexpr size_t OFF_Z0   = OFF_SEW  + (size_t)NN * CAP;
static constexpr size_t OFF_Z1   = OFF_Z0   + (size_t)BATCH * HID;
static constexpr size_t FTOTAL   = OFF_Z1   + (size_t)BATCH * HID;
__device__ float g_f[FTOTAL];

// ---------------- bf16 split scratch ----------------------------------------
static constexpr size_t XSZ  = (size_t)NN * KP1;
static constexpr size_t HSZ  = (size_t)NN * HID;
static constexpr size_t FSZ  = (size_t)BATCH * KP0;
static constexpr size_t W1SZ = (size_t)KP1 * HID;
static constexpr size_t W2SZ = (size_t)HID * HID;
static constexpr size_t F0SZ = (size_t)KP0 * HID;
static constexpr size_t ZSZ  = (size_t)BATCH * HID;
static constexpr size_t OFF_XH  = 0;
static constexpr size_t OFF_XL  = OFF_XH  + XSZ;
static constexpr size_t OFF_HH  = OFF_XL  + XSZ;
static constexpr size_t OFF_HL  = OFF_HH  + HSZ;
static constexpr size_t OFF_AH  = OFF_HL  + HSZ;
static constexpr size_t OFF_AL  = OFF_AH  + HSZ;
static constexpr size_t OFF_FH  = OFF_AL  + HSZ;
static constexpr size_t OFF_FL  = OFF_FH  + FSZ;
static constexpr size_t OFF_W1H = OFF_FL  + FSZ;
static constexpr size_t OFF_W1L = OFF_W1H + W1SZ;
static constexpr size_t OFF_W2H = OFF_W1L + W1SZ;
static constexpr size_t OFF_W2L = OFF_W2H + W2SZ;
static constexpr size_t OFF_F0H = OFF_W2L + W2SZ;
static constexpr size_t OFF_F0L = OFF_F0H + F0SZ;
static constexpr size_t OFF_F1H = OFF_F0L + F0SZ;
static constexpr size_t OFF_F1L = OFF_F1H + W2SZ;
static constexpr size_t OFF_F2H = OFF_F1L + W2SZ;
static constexpr size_t OFF_F2L = OFF_F2H + W2SZ;
static constexpr size_t OFF_ZH  = OFF_F2L + W2SZ;
static constexpr size_t OFF_ZL  = OFF_ZH  + ZSZ;
static constexpr size_t HTOTAL  = OFF_ZL  + ZSZ;
__device__ __align__(16) __nv_bfloat16 g_h[HTOTAL];

__device__ int g_i[(size_t)NN * (CAP + 1)];
__device__ int g_is32;

// ---------------- helpers ----------------------------------------------------
__device__ __forceinline__ void split2(float v, __nv_bfloat16* hi, __nv_bfloat16* lo) {
    __nv_bfloat16 h = __float2bfloat16(v);
    *hi = h;
    *lo = __float2bfloat16(v - __bfloat162float(h));
}
__device__ __forceinline__ u32 smem_u32(const void* p) {
    return (u32)__cvta_generic_to_shared(p);
}
__device__ __forceinline__ void cp16(u32 dst, const void* src) {
    asm volatile("cp.async.cg.shared.global [%0], [%1], 16;" :: "r"(dst), "l"(src));
}
__device__ __forceinline__ void ldsm_x4(u32* r, u32 a) {
    asm volatile("ldmatrix.sync.aligned.m8n8.x4.shared.b16 {%0,%1,%2,%3}, [%4];"
        : "=r"(r[0]), "=r"(r[1]), "=r"(r[2]), "=r"(r[3]) : "r"(a));
}
__device__ __forceinline__ void ldsm_x4_t(u32* r, u32 a) {
    asm volatile("ldmatrix.sync.aligned.m8n8.x4.trans.shared.b16 {%0,%1,%2,%3}, [%4];"
        : "=r"(r[0]), "=r"(r[1]), "=r"(r[2]), "=r"(r[3]) : "r"(a));
}
__device__ __forceinline__ void mma16816(float* c, const u32* a, const u32* b) {
    asm volatile(
        "mma.sync.aligned.m16n8k16.row.col.f32.bf16.bf16.f32 "
        "{%0,%1,%2,%3}, {%4,%5,%6,%7}, {%8,%9}, {%0,%1,%2,%3};"
        : "+f"(c[0]), "+f"(c[1]), "+f"(c[2]), "+f"(c[3])
        : "r"(a[0]), "r"(a[1]), "r"(a[2]), "r"(a[3]), "r"(b[0]), "r"(b[1]));
}

// ---------------- dtype detect / graph prep ---------------------------------
__global__ void k_detect(const void* __restrict__ ei) {
    if (threadIdx.x != 0 || blockIdx.x != 0) return;
    const long long* p = (const long long*)ei;
    int is32 = 0;
    for (int i = 0; i < 64; i++) {
        long long v = p[i];
        if (v < 0 || v >= NN) { is32 = 1; break; }
    }
    g_is32 = is32;
}
__device__ __forceinline__ int edge_idx(const void* ei, int half, int e, int is32) {
    if (is32) return ((const int*)ei)[(size_t)half * EE + e];
    return (int)((const long long*)ei)[(size_t)half * EE + e];
}
__global__ void k_zero(float* __restrict__ deg, int* __restrict__ cnt) {
    int i = blockIdx.x * 256 + threadIdx.x;
    if (i < NN) { deg[i] = 0.f; cnt[i] = 0; }
}
__global__ void k_degfill(const void* __restrict__ ei, const float* __restrict__ ew,
                          float* __restrict__ deg, int* __restrict__ cnt,
                          int* __restrict__ src, float* __restrict__ sew) {
    int e = blockIdx.x * 256 + threadIdx.x;
    if (e >= EE) return;
    int is32 = g_is32;
    int r = edge_idx(ei, 0, e, is32);
    int c = edge_idx(ei, 1, e, is32);
    if ((unsigned)r >= (unsigned)NN || (unsigned)c >= (unsigned)NN) return;
    float w = ew[e];
    atomicAdd(&deg[c], w);
    int p = atomicAdd(&cnt[c], 1);
    if (p < CAP) {
        src[(size_t)c * CAP + p] = r;
        sew[(size_t)c * CAP + p] = w;
    }
}
__global__ void k_dinv(const float* __restrict__ deg, float* __restrict__ dinv) {
    int i = blockIdx.x * 256 + threadIdx.x;
    if (i < NN) dinv[i] = rsqrtf(deg[i] + 1.0f);
}

// ---------------- merged weight conversion -----------------------------------
// segments (row index r): [0,64) W1 (valid FEA rows), [64,320) W2,
// [320,7280) Wf0 (valid MLP_IN rows), [7280,7536) Wf1, [7536,7792) Wf2
#define CVT_ROWS 7792
__global__ void k_cvt_all(const float* __restrict__ W1, const float* __restrict__ W2,
                          const float* __restrict__ Wf0, const float* __restrict__ Wf1,
                          const float* __restrict__ Wf2,
                          __nv_bfloat16* __restrict__ gh_base) {
    int r = blockIdx.x, t = threadIdx.x;
    float v; size_t off;
    __nv_bfloat16 *dh, *dl;
    if (r < 64) {
        v = (r < FEA) ? W1[(size_t)r * 256 + t] : 0.f;
        dh = gh_base + OFF_W1H; dl = gh_base + OFF_W1L;
        off = (size_t)r * 256 + t;
    } else if (r < 320) {
        int k = r - 64;
        v = W2[(size_t)k * 256 + t];
        dh = gh_base + OFF_W2H; dl = gh_base + OFF_W2L;
        off = (size_t)k * 256 + t;
    } else if (r < 7280) {
        int k = r - 320;
        v = (k < MLP_IN) ? Wf0[(size_t)k * 256 + t] : 0.f;
        dh = gh_base + OFF_F0H; dl = gh_base + OFF_F0L;
        off = (size_t)k * 256 + t;
    } else if (r < 7536) {
        int k = r - 7280;
        v = Wf1[(size_t)k * 256 + t];
        dh = gh_base + OFF_F1H; dl = gh_base + OFF_F1L;
        off = (size_t)k * 256 + t;
    } else {
        int k = r - 7536;
        v = Wf2[(size_t)k * 256 + t];
        dh = gh_base + OFF_F2H; dl = gh_base + OFF_F2L;
        off = (size_t)k * 256 + t;
    }
    split2(v, &dh[off], &dl[off]);
}
__global__ void k_padflat(__nv_bfloat16* __restrict__ fh, __nv_bfloat16* __restrict__ fl) {
    int idx = blockIdx.x * 256 + threadIdx.x;
    int b = idx >> 3, j = idx & 7;
    size_t p = (size_t)b * KP0 + MLP_IN + j;
    fh[p] = __float2bfloat16(0.f);
    fl[p] = __float2bfloat16(0.f);
}

// ---------------- gather of raw x (pre-conv1): 4 nodes/block ----------------
__global__ __launch_bounds__(256)
void k_gather_x(const float* __restrict__ x, const float* __restrict__ dinv,
                const int* __restrict__ cnt, const int* __restrict__ src,
                const float* __restrict__ sew,
                __nv_bfloat16* __restrict__ oh, __nv_bfloat16* __restrict__ ol) {
    int sub = threadIdx.x >> 6, lane = threadIdx.x & 63;
    int i = blockIdx.x * 4 + sub;
    __shared__ int   ssrc[4][CAP];
    __shared__ float snrm[4][CAP];
    int c = cnt[i]; if (c > CAP) c = CAP;
    float di = dinv[i];
    for (int e = lane; e < c; e += 64) {
        int s = src[(size_t)i * CAP + e];
        ssrc[sub][e] = s;
        snrm[sub][e] = dinv[s] * sew[(size_t)i * CAP + e] * di;
    }
    __syncthreads();
    float acc = 0.f;
    if (lane < FEA) {
        acc = di * di * x[(size_t)i * FEA + lane];
        int e = 0;
        for (; e + 2 <= c; e += 2) {
            float v0 = x[(size_t)ssrc[sub][e]     * FEA + lane];
            float v1 = x[(size_t)ssrc[sub][e + 1] * FEA + lane];
            acc = fmaf(snrm[sub][e],     v0, acc);
            acc = fmaf(snrm[sub][e + 1], v1, acc);
        }
        if (e < c)
            acc = fmaf(snrm[sub][e], x[(size_t)ssrc[sub][e] * FEA + lane], acc);
    }
    size_t p = (size_t)i * KP1 + lane;
    split2(acc, &oh[p], &ol[p]);
}

// ---------------- gather of h (pre-conv2): 2 nodes/block, bf16x2 lanes ------
__global__ __launch_bounds__(256)
void k_gather_h(const __nv_bfloat16* __restrict__ hh, const __nv_bfloat16* __restrict__ hl,
                const float* __restrict__ dinv, const int* __restrict__ cnt,
                const int* __restrict__ src, const float* __restrict__ sew,
                __nv_bfloat16* __restrict__ ah, __nv_bfloat16* __restrict__ al) {
    int sub = threadIdx.x >> 7, lane = threadIdx.x & 127;
    int i = blockIdx.x * 2 + sub;
    __shared__ int   ssrc[2][CAP];
    __shared__ float snrm[2][CAP];
    int c = cnt[i]; if (c > CAP) c = CAP;
    float di = dinv[i];
    if (lane < c) {
        int s = src[(size_t)i * CAP + lane];
        ssrc[sub][lane] = s;
        snrm[sub][lane] = dinv[s] * sew[(size_t)i * CAP + lane] * di;
    }
    __syncthreads();

    const int col = lane * 2;
    float ax, ay;
    {
        __nv_bfloat162 vh = *(const __nv_bfloat162*)&hh[(size_t)i * HID + col];
        __nv_bfloat162 vl = *(const __nv_bfloat162*)&hl[(size_t)i * HID + col];
        float s = di * di;
        ax = s * (__bfloat162float(vh.x) + __bfloat162float(vl.x));
        ay = s * (__bfloat162float(vh.y) + __bfloat162float(vl.y));
    }
    int e = 0;
    for (; e + 4 <= c; e += 4) {
        size_t r0 = (size_t)ssrc[sub][e]     * HID + col;
        size_t r1 = (size_t)ssrc[sub][e + 1] * HID + col;
        size_t r2 = (size_t)ssrc[sub][e + 2] * HID + col;
        size_t r3 = (size_t)ssrc[sub][e + 3] * HID + col;
        __nv_bfloat162 h0 = *(const __nv_bfloat162*)&hh[r0];
        __nv_bfloat162 h1 = *(const __nv_bfloat162*)&hh[r1];
        __nv_bfloat162 h2 = *(const __nv_bfloat162*)&hh[r2];
        __nv_bfloat162 h3 = *(const __nv_bfloat162*)&hh[r3];
        __nv_bfloat162 l0 = *(const __nv_bfloat162*)&hl[r0];
        __nv_bfloat162 l1 = *(const __nv_bfloat162*)&hl[r1];
        __nv_bfloat162 l2 = *(const __nv_bfloat162*)&hl[r2];
        __nv_bfloat162 l3 = *(const __nv_bfloat162*)&hl[r3];
        float w0 = snrm[sub][e], w1 = snrm[sub][e + 1];
        float w2 = snrm[sub][e + 2], w3 = snrm[sub][e + 3];
        ax = fmaf(w0, __bfloat162float(h0.x) + __bfloat162float(l0.x), ax);
        ay = fmaf(w0, __bfloat162float(h0.y) + __bfloat162float(l0.y), ay);
        ax = fmaf(w1, __bfloat162float(h1.x) + __bfloat162float(l1.x), ax);
        ay = fmaf(w1, __bfloat162float(h1.y) + __bfloat162float(l1.y), ay);
        ax = fmaf(w2, __bfloat162float(h2.x) + __bfloat162float(l2.x), ax);
        ay = fmaf(w2, __bfloat162float(h2.y) + __bfloat162float(l2.y), ay);
        ax = fmaf(w3, __bfloat162float(h3.x) + __bfloat162float(l3.x), ax);
        ay = fmaf(w3, __bfloat162float(h3.y) + __bfloat162float(l3.y), ay);
    }
    for (; e < c; e++) {
        size_t r0 = (size_t)ssrc[sub][e] * HID + col;
        __nv_bfloat162 h0 = *(const __nv_bfloat162*)&hh[r0];
        __nv_bfloat162 l0 = *(const __nv_bfloat162*)&hl[r0];
        float w0 = snrm[sub][e];
        ax = fmaf(w0, __bfloat162float(h0.x) + __bfloat162float(l0.x), ax);
        ay = fmaf(w0, __bfloat162float(h0.y) + __bfloat162float(l0.y), ay);
    }

    __nv_bfloat16 hx, lx, hy, ly;
    split2(ax, &hx, &lx);
    split2(ay, &hy, &ly);
    size_t p = (size_t)i * HID + col;
    *(__nv_bfloat162*)&ah[p] = __nv_bfloat162(hx, hy);
    *(__nv_bfloat162*)&al[p] = __nv_bfloat162(lx, ly);
}

// ---------------- tensor-core GEMM (cp.async double-buffered) ---------------
// MODE 0: fp32 atomicAdd into C (split-K), no bias
// MODE 1: bias + leaky + split-bf16 store, linear stride 256 (conv1 -> h)
// MODE 2: bias + leaky + split-bf16 store, flat-mapped (conv2 -> flat)
template<int MODE>
__global__ __launch_bounds__(256)
void bmma(const __nv_bfloat16* __restrict__ Ah, const __nv_bfloat16* __restrict__ Al,
          const __nv_bfloat16* __restrict__ Bh, const __nv_bfloat16* __restrict__ Bl,
          float* __restrict__ C, const float* __restrict__ bias,
          __nv_bfloat16* __restrict__ oh, __nv_bfloat16* __restrict__ ol,
          int K, int kstep) {
    __shared__ __align__(16) __nv_bfloat16 As_h[2][128][24], As_l[2][128][24];
    __shared__ __align__(16) __nv_bfloat16 Bs_h[2][16][136], Bs_l[2][16][136];
    constexpr u32 ABUF = 128 * 24 * 2;   // bytes per A buffer
    constexpr u32 BBUF = 16 * 136 * 2;   // bytes per B buffer

    const int tid = threadIdx.x;
    const int lane = tid & 31, warp = tid >> 5;
    const int wm = warp >> 2, wn = warp & 3;
    const int row0 = blockIdx.y * 128, col0 = blockIdx.x * 128;
    const int kb = blockIdx.z * kstep;
    const int ke = min(kb + kstep, K);     // ke-kb always multiple of 16

    const int ar = tid >> 1, ac = (tid & 1) * 8;
    const int bkr = tid >> 4, bc = (tid & 15) * 8;
    const size_t a_base = (size_t)(row0 + ar) * K + ac;

    const u32 a_h_dst = smem_u32(&As_h[0][ar][ac]);
    const u32 a_l_dst = smem_u32(&As_l[0][ar][ac]);
    const u32 b_h_dst = smem_u32(&Bs_h[0][bkr][bc]);
    const u32 b_l_dst = smem_u32(&Bs_l[0][bkr][bc]);

    float acc[4][4][4];
#pragma unroll
    for (int i = 0; i < 4; i++)
#pragma unroll
        for (int j = 0; j < 4; j++)
#pragma unroll
            for (int q = 0; q < 4; q++) acc[i][j][q] = 0.f;

    const int lr = (lane & 7) + ((lane >> 3) & 1) * 8;
    const int lc = (lane >> 4) * 8;
    u32 aaddr_h[4], aaddr_l[4], baddr_h[2], baddr_l[2];
#pragma unroll
    for (int mf = 0; mf < 4; mf++) {
        int r = wm * 64 + mf * 16 + lr;
        aaddr_h[mf] = smem_u32(&As_h[0][r][lc]);
        aaddr_l[mf] = smem_u32(&As_l[0][r][lc]);
    }
#pragma unroll
    for (int g = 0; g < 2; g++) {
        int n = wn * 32 + g * 16 + lc;
        baddr_h[g] = smem_u32(&Bs_h[0][lr][n]);
        baddr_l[g] = smem_u32(&Bs_l[0][lr][n]);
    }

    // stage loader: buf in {0,1}, k0 = global k of this stage
    auto load_stage = [&](int buf, int k0) {
        if (k0 < ke) {
            cp16(a_h_dst + buf * ABUF, Ah + a_base + k0);
            cp16(a_l_dst + buf * ABUF, Al + a_base + k0);
            cp16(b_h_dst + buf * BBUF, Bh + (size_t)(k0 + bkr) * 256 + col0 + bc);
            cp16(b_l_dst + buf * BBUF, Bl + (size_t)(k0 + bkr) * 256 + col0 + bc);
        }
        asm volatile("cp.async.commit_group;");
    };

    load_stage(0, kb);
    load_stage(1, kb + 16);

    int buf = 0;
    for (int k0 = kb; k0 < ke; k0 += 16, buf ^= 1) {
        asm volatile("cp.async.wait_group 1;");
        __syncthreads();

        u32 a_h[4][4], a_l[4][4], b_h[4][2], b_l[4][2];
#pragma unroll
        for (int mf = 0; mf < 4; mf++) {
            ldsm_x4(a_h[mf], aaddr_h[mf] + buf * ABUF);
            ldsm_x4(a_l[mf], aaddr_l[mf] + buf * ABUF);
        }
#pragma unroll
        for (int g = 0; g < 2; g++) {
            u32 t[4];
            ldsm_x4_t(t, baddr_h[g] + buf * BBUF);
            b_h[2*g][0] = t[0]; b_h[2*g][1] = t[1];
            b_h[2*g+1][0] = t[2]; b_h[2*g+1][1] = t[3];
            ldsm_x4_t(t, baddr_l[g] + buf * BBUF);
            b_l[2*g][0] = t[0]; b_l[2*g][1] = t[1];
            b_l[2*g+1][0] = t[2]; b_l[2*g+1][1] = t[3];
        }
#pragma unroll
        for (int mf = 0; mf < 4; mf++)
#pragma unroll
            for (int nf = 0; nf < 4; nf++) {
                mma16816(acc[mf][nf], a_h[mf], b_h[nf]);
                mma16816(acc[mf][nf], a_h[mf], b_l[nf]);
                mma16816(acc[mf][nf], a_l[mf], b_h[nf]);
            }
        __syncthreads();
        load_stage(buf, k0 + 32);
    }

    const int er = lane >> 2, ec = (lane & 3) * 2;
#pragma unroll
    for (int mf = 0; mf < 4; mf++)
#pragma unroll
        for (int nf = 0; nf < 4; nf++) {
            int r = row0 + wm * 64 + mf * 16 + er;
            int c = col0 + wn * 32 + nf * 8 + ec;
            if (MODE == 0) {
                float* p0 = &C[(size_t)r * 256 + c];
                float* p1 = &C[(size_t)(r + 8) * 256 + c];
                atomicAdd(p0,     acc[mf][nf][0]);
                atomicAdd(p0 + 1, acc[mf][nf][1]);
                atomicAdd(p1,     acc[mf][nf][2]);
                atomicAdd(p1 + 1, acc[mf][nf][3]);
            } else {
                float bv0 = bias[c], bv1 = bias[c + 1];
#pragma unroll
                for (int half = 0; half < 2; half++) {
                    int rr = r + half * 8;
                    float v0 = acc[mf][nf][half * 2]     + bv0;
                    float v1 = acc[mf][nf][half * 2 + 1] + bv1;
                    v0 = v0 > 0.f ? v0 : NEG_SLOPE * v0;
                    v1 = v1 > 0.f ? v1 : NEG_SLOPE * v1;
                    __nv_bfloat16 h0, l0, h1, l1;
                    split2(v0, &h0, &l0);
                    split2(v1, &h1, &l1);
                    size_t p;
                    if (MODE == 1) {
                        p = (size_t)rr * 256 + c;
                    } else {
                        int b = rr / MACH, m = rr - b * MACH;
                        p = (size_t)b * KP0 + (size_t)m * (HID + FEA) + c;
                    }
                    *(__nv_bfloat162*)&oh[p] = __nv_bfloat162(h0, h1);
                    *(__nv_bfloat162*)&ol[p] = __nv_bfloat162(l0, l1);
                }
            }
        }
}

// ---------------- split-K epilogue: bias + leaky + bf16 split ---------------
__global__ void k_epi(float* __restrict__ z, const float* __restrict__ bias,
                      __nv_bfloat16* __restrict__ zh, __nv_bfloat16* __restrict__ zl) {
    int i = blockIdx.x * 256 + threadIdx.x;
    float v = z[i] + bias[i & (HID - 1)];
    v = v > 0.f ? v : NEG_SLOPE * v;
    z[i] = v;
    split2(v, &zh[i], &zl[i]);
}

// ---------------- x -> flat (split) ------------------------------------------
__global__ void k_xcopy(const float* __restrict__ x,
                        __nv_bfloat16* __restrict__ fh, __nv_bfloat16* __restrict__ fl) {
    long long idx = (long long)blockIdx.x * 256 + threadIdx.x;
    if (idx >= (long long)NN * FEA) return;
    int i = (int)(idx / FEA);
    int j = (int)(idx - (long long)i * FEA);
    int b = i / MACH, m = i - b * MACH;
    size_t p = (size_t)b * KP0 + (size_t)m * (HID + FEA) + HID + j;
    split2(x[idx], &fh[p], &fl[p]);
}

// ---------------- head -------------------------------------------------------
__global__ __launch_bounds__(32)
void k_head(const float* __restrict__ z, const float* __restrict__ Wo,
            const float* __restrict__ bo, float* __restrict__ out) {
    int b = blockIdx.x;
    int lane = threadIdx.x;
    float a0 = 0.f, a1 = 0.f, a2 = 0.f, a3 = 0.f;
    for (int k = lane; k < HID; k += 32) {
        float v = z[(size_t)b * HID + k];
        a0 = fmaf(v, Wo[k * 4 + 0], a0);
        a1 = fmaf(v, Wo[k * 4 + 1], a1);
        a2 = fmaf(v, Wo[k * 4 + 2], a2);
        a3 = fmaf(v, Wo[k * 4 + 3], a3);
    }
#pragma unroll
    for (int o = 16; o > 0; o >>= 1) {
        a0 += __shfl_down_sync(0xffffffffu, a0, o);
        a1 += __shfl_down_sync(0xffffffffu, a1, o);
        a2 += __shfl_down_sync(0xffffffffu, a2, o);
        a3 += __shfl_down_sync(0xffffffffu, a3, o);
    }
    if (lane == 0) {
        out[(size_t)b * 4 + 0] = a0 + bo[0];
        out[(size_t)b * 4 + 1] = a1 + bo[1];
        out[(size_t)b * 4 + 2] = a2 + bo[2];
        out[(size_t)b * 4 + 3] = a3 + bo[3];
    }
}

// ---------------- launcher ---------------------------------------------------
extern "C" void kernel_launch(void* const* d_in, const int* in_sizes, int n_in,
                              void* d_out, int out_size) {
    const float* x   = (const float*)d_in[0];
    const void*  ei  = d_in[1];
    const float* ew  = (const float*)d_in[2];
    const float* W1  = (const float*)d_in[3];
    const float* b1  = (const float*)d_in[4];
    const float* W2  = (const float*)d_in[5];
    const float* b2  = (const float*)d_in[6];
    const float* Wf0 = (const float*)d_in[7];
    const float* bf0 = (const float*)d_in[8];
    const float* Wf1 = (const float*)d_in[9];
    const float* bf1 = (const float*)d_in[10];
    const float* Wf2 = (const float*)d_in[11];
    const float* bf2 = (const float*)d_in[12];
    const float* Wo  = (const float*)d_in[13];
    const float* bo  = (const float*)d_in[14];
    float* out = (float*)d_out;

    float* gf = nullptr; int* gi = nullptr; __nv_bfloat16* gh = nullptr;
    cudaGetSymbolAddress((void**)&gf, g_f);
    cudaGetSymbolAddress((void**)&gi, g_i);
    cudaGetSymbolAddress((void**)&gh, g_h);

    float* deg  = gf + OFF_DEG;
    float* dinv = gf + OFF_DINV;
    float* sew  = gf + OFF_SEW;
    float* z0   = gf + OFF_Z0;
    float* z1   = gf + OFF_Z1;
    int*   cnt  = gi;
    int*   src  = gi + NN;

    __nv_bfloat16 *xh = gh + OFF_XH,  *xl = gh + OFF_XL;
    __nv_bfloat16 *hh = gh + OFF_HH,  *hl = gh + OFF_HL;
    __nv_bfloat16 *ah = gh + OFF_AH,  *al = gh + OFF_AL;
    __nv_bfloat16 *fh = gh + OFF_FH,  *fl = gh + OFF_FL;
    __nv_bfloat16 *w1h = gh + OFF_W1H, *w1l = gh + OFF_W1L;
    __nv_bfloat16 *w2h = gh + OFF_W2H, *w2l = gh + OFF_W2L;
    __nv_bfloat16 *f0h = gh + OFF_F0H, *f0l = gh + OFF_F0L;
    __nv_bfloat16 *f1h = gh + OFF_F1H, *f1l = gh + OFF_F1L;
    __nv_bfloat16 *f2h = gh + OFF_F2H, *f2l = gh + OFF_F2L;
    __nv_bfloat16 *zh = gh + OFF_ZH,   *zl = gh + OFF_ZL;

    const int NB_N = (NN + 255) / 256;
    const int NB_E = (EE + 255) / 256;

    // order matters for ncu (-s 5 with 2 harness pre-launches => 4th kernel
    // here is the one profiled): put k_degfill 4th.
    k_detect<<<1, 32>>>(ei);                                           // 1
    k_zero<<<NB_N, 256>>>(deg, cnt);                                   // 2
    k_cvt_all<<<CVT_ROWS, 256>>>(W1, W2, Wf0, Wf1, Wf2, gh);           // 3
    k_degfill<<<NB_E, 256>>>(ei, ew, deg, cnt, src, sew);              // 4 <- profiled
    k_dinv<<<NB_N, 256>>>(deg, dinv);                                  // 5

    // conv1: aggx = agg(x) ; h = leaky(aggx @ W1 + b1)
    k_gather_x<<<NN / 4, 256>>>(x, dinv, cnt, src, sew, xh, xl);
    bmma<1><<<dim3(2, NN / 128, 1), 256>>>(xh, xl, w1h, w1l,
                                           nullptr, b1, hh, hl, KP1, KP1);

    // conv2: aggh = agg(h) ; flat[h-part] = leaky(aggh @ W2 + b2)
    k_gather_h<<<NN / 2, 256>>>(hh, hl, dinv, cnt, src, sew, ah, al);
    bmma<2><<<dim3(2, NN / 128, 1), 256>>>(ah, al, w2h, w2l,
                                           nullptr, b2, fh, fl, HID, HID);

    // flat[x-part] = x ; pad tail
    k_xcopy<<<(int)(((long long)NN * FEA + 255) / 256), 256>>>(x, fh, fl);
    k_padflat<<<BATCH * 8 / 256, 256>>>(fh, fl);

    const size_t ZBYTES = (size_t)BATCH * HID * sizeof(float);

    // MLP0: split-K=8 (7*880 + 800)
    cudaMemsetAsync(z0, 0, ZBYTES);
    bmma<0><<<dim3(2, BATCH / 128, 8), 256>>>(fh, fl, f0h, f0l,
                                              z0, nullptr, nullptr, nullptr, KP0, 880);
    k_epi<<<BATCH * HID / 256, 256>>>(z0, bf0, zh, zl);

    // MLP1: split-K=4
    cudaMemsetAsync(z1, 0, ZBYTES);
    bmma<0><<<dim3(2, BATCH / 128, 4), 256>>>(zh, zl, f1h, f1l,
                                              z1, nullptr, nullptr, nullptr, HID, 64);
    k_epi<<<BATCH * HID / 256, 256>>>(z1, bf1, zh, zl);

    // MLP2: split-K=4
    cudaMemsetAsync(z0, 0, ZBYTES);
    bmma<0><<<dim3(2, BATCH / 128, 4), 256>>>(zh, zl, f2h, f2l,
                                              z0, nullptr, nullptr, nullptr, HID, 64);
    k_epi<<<BATCH * HID / 256, 256>>>(z0, bf2, zh, zl);

    // head
    k_head<<<BATCH, 32>>>(z0, Wo, bo, out);
}

// round 8
// speedup vs baseline: 3.8498x; 1.1123x over previous
#include <cuda_runtime.h>
#include <cuda_bf16.h>
#include <cuda_fp16.h>
#include <cstdint>

typedef unsigned int u32;

#define NN 45056
#define EE 720896
#define FEA 60
#define HID 256
#define MACH 22
#define BATCH 2048
#define CAP 96
#define MLP_IN 6952
#define KP0 6960             // MLP_IN padded to x16
#define KP1 64               // FEA padded to x16
#define NEG_SLOPE 0.01f

// ---------------- fp32 scratch ----------------------------------------------
static constexpr size_t OFF_DEG  = 0;
static constexpr size_t OFF_DINV = OFF_DEG  + (size_t)NN;
static constexpr size_t OFF_SEW  = OFF_DINV + (size_t)NN;
static constexpr size_t OFF_Z0   = OFF_SEW  + (size_t)NN * CAP;
static constexpr size_t OFF_Z1   = OFF_Z0   + (size_t)BATCH * HID;
static constexpr size_t FTOTAL   = OFF_Z1   + (size_t)BATCH * HID;
__device__ float g_f[FTOTAL];

// ---------------- bf16/fp16 scratch ------------------------------------------
static constexpr size_t XSZ  = (size_t)NN * KP1;
static constexpr size_t HSZ  = (size_t)NN * HID;
static constexpr size_t FSZ  = (size_t)BATCH * KP0;
static constexpr size_t W1SZ = (size_t)KP1 * HID;
static constexpr size_t W2SZ = (size_t)HID * HID;
static constexpr size_t F0SZ = (size_t)KP0 * HID;
static constexpr size_t ZSZ  = (size_t)BATCH * HID;
static constexpr size_t OFF_XH  = 0;
static constexpr size_t OFF_XL  = OFF_XH  + XSZ;
static constexpr size_t OFF_HH  = OFF_XL  + XSZ;   // fp16 h lives here (HSZ 2B slots)
static constexpr size_t OFF_AH  = OFF_HH  + HSZ;
static constexpr size_t OFF_AL  = OFF_AH  + HSZ;
static constexpr size_t OFF_FH  = OFF_AL  + HSZ;
static constexpr size_t OFF_FL  = OFF_FH  + FSZ;
static constexpr size_t OFF_W1H = OFF_FL  + FSZ;
static constexpr size_t OFF_W1L = OFF_W1H + W1SZ;
static constexpr size_t OFF_W2H = OFF_W1L + W1SZ;
static constexpr size_t OFF_W2L = OFF_W2H + W2SZ;
static constexpr size_t OFF_F0H = OFF_W2L + W2SZ;
static constexpr size_t OFF_F0L = OFF_F0H + F0SZ;
static constexpr size_t OFF_F1H = OFF_F0L + F0SZ;
static constexpr size_t OFF_F1L = OFF_F1H + W2SZ;
static constexpr size_t OFF_F2H = OFF_F1L + W2SZ;
static constexpr size_t OFF_F2L = OFF_F2H + W2SZ;
static constexpr size_t OFF_ZH  = OFF_F2L + W2SZ;
static constexpr size_t OFF_ZL  = OFF_ZH  + ZSZ;
static constexpr size_t HTOTAL  = OFF_ZL  + ZSZ;
__device__ __align__(16) __nv_bfloat16 g_h[HTOTAL];

__device__ int g_i[(size_t)NN * (CAP + 1)];
__device__ int g_is32;

// ---------------- helpers ----------------------------------------------------
__device__ __forceinline__ void split2(float v, __nv_bfloat16* hi, __nv_bfloat16* lo) {
    __nv_bfloat16 h = __float2bfloat16(v);
    *hi = h;
    *lo = __float2bfloat16(v - __bfloat162float(h));
}
__device__ __forceinline__ u32 smem_u32(const void* p) {
    return (u32)__cvta_generic_to_shared(p);
}
__device__ __forceinline__ void cp16(u32 dst, const void* src) {
    asm volatile("cp.async.cg.shared.global [%0], [%1], 16;" :: "r"(dst), "l"(src));
}
__device__ __forceinline__ void ldsm_x4(u32* r, u32 a) {
    asm volatile("ldmatrix.sync.aligned.m8n8.x4.shared.b16 {%0,%1,%2,%3}, [%4];"
        : "=r"(r[0]), "=r"(r[1]), "=r"(r[2]), "=r"(r[3]) : "r"(a));
}
__device__ __forceinline__ void ldsm_x4_t(u32* r, u32 a) {
    asm volatile("ldmatrix.sync.aligned.m8n8.x4.trans.shared.b16 {%0,%1,%2,%3}, [%4];"
        : "=r"(r[0]), "=r"(r[1]), "=r"(r[2]), "=r"(r[3]) : "r"(a));
}
__device__ __forceinline__ void mma16816(float* c, const u32* a, const u32* b) {
    asm volatile(
        "mma.sync.aligned.m16n8k16.row.col.f32.bf16.bf16.f32 "
        "{%0,%1,%2,%3}, {%4,%5,%6,%7}, {%8,%9}, {%0,%1,%2,%3};"
        : "+f"(c[0]), "+f"(c[1]), "+f"(c[2]), "+f"(c[3])
        : "r"(a[0]), "r"(a[1]), "r"(a[2]), "r"(a[3]), "r"(b[0]), "r"(b[1]));
}

// ---------------- dtype detect / graph prep ---------------------------------
__global__ void k_detect(const void* __restrict__ ei) {
    if (threadIdx.x != 0 || blockIdx.x != 0) return;
    const long long* p = (const long long*)ei;
    int is32 = 0;
    for (int i = 0; i < 64; i++) {
        long long v = p[i];
        if (v < 0 || v >= NN) { is32 = 1; break; }
    }
    g_is32 = is32;
}
__device__ __forceinline__ int edge_idx(const void* ei, int half, int e, int is32) {
    if (is32) return ((const int*)ei)[(size_t)half * EE + e];
    return (int)((const long long*)ei)[(size_t)half * EE + e];
}
__global__ void k_zero(float* __restrict__ deg, int* __restrict__ cnt) {
    int i = blockIdx.x * 256 + threadIdx.x;
    if (i < NN) { deg[i] = 0.f; cnt[i] = 0; }
}
__global__ void k_degfill(const void* __restrict__ ei, const float* __restrict__ ew,
                          float* __restrict__ deg, int* __restrict__ cnt,
                          int* __restrict__ src, float* __restrict__ sew) {
    int e = blockIdx.x * 256 + threadIdx.x;
    if (e >= EE) return;
    int is32 = g_is32;
    int r = edge_idx(ei, 0, e, is32);
    int c = edge_idx(ei, 1, e, is32);
    if ((unsigned)r >= (unsigned)NN || (unsigned)c >= (unsigned)NN) return;
    float w = ew[e];
    atomicAdd(&deg[c], w);
    int p = atomicAdd(&cnt[c], 1);
    if (p < CAP) {
        src[(size_t)c * CAP + p] = r;
        sew[(size_t)c * CAP + p] = w;
    }
}
__global__ void k_dinv(const float* __restrict__ deg, float* __restrict__ dinv) {
    int i = blockIdx.x * 256 + threadIdx.x;
    if (i < NN) dinv[i] = rsqrtf(deg[i] + 1.0f);
}

// ---------------- merged weight conversion -----------------------------------
#define CVT_ROWS 7792
__global__ void k_cvt_all(const float* __restrict__ W1, const float* __restrict__ W2,
                          const float* __restrict__ Wf0, const float* __restrict__ Wf1,
                          const float* __restrict__ Wf2,
                          __nv_bfloat16* __restrict__ gh_base) {
    int r = blockIdx.x, t = threadIdx.x;
    float v; size_t off;
    __nv_bfloat16 *dh, *dl;
    if (r < 64) {
        v = (r < FEA) ? W1[(size_t)r * 256 + t] : 0.f;
        dh = gh_base + OFF_W1H; dl = gh_base + OFF_W1L;
        off = (size_t)r * 256 + t;
    } else if (r < 320) {
        int k = r - 64;
        v = W2[(size_t)k * 256 + t];
        dh = gh_base + OFF_W2H; dl = gh_base + OFF_W2L;
        off = (size_t)k * 256 + t;
    } else if (r < 7280) {
        int k = r - 320;
        v = (k < MLP_IN) ? Wf0[(size_t)k * 256 + t] : 0.f;
        dh = gh_base + OFF_F0H; dl = gh_base + OFF_F0L;
        off = (size_t)k * 256 + t;
    } else if (r < 7536) {
        int k = r - 7280;
        v = Wf1[(size_t)k * 256 + t];
        dh = gh_base + OFF_F1H; dl = gh_base + OFF_F1L;
        off = (size_t)k * 256 + t;
    } else {
        int k = r - 7536;
        v = Wf2[(size_t)k * 256 + t];
        dh = gh_base + OFF_F2H; dl = gh_base + OFF_F2L;
        off = (size_t)k * 256 + t;
    }
    split2(v, &dh[off], &dl[off]);
}

// ---------------- gather of raw x (pre-conv1): 4 nodes/block ----------------
__global__ __launch_bounds__(256)
void k_gather_x(const float* __restrict__ x, const float* __restrict__ dinv,
                const int* __restrict__ cnt, const int* __restrict__ src,
                const float* __restrict__ sew,
                __nv_bfloat16* __restrict__ oh, __nv_bfloat16* __restrict__ ol) {
    int sub = threadIdx.x >> 6, lane = threadIdx.x & 63;
    int i = blockIdx.x * 4 + sub;
    __shared__ int   ssrc[4][CAP];
    __shared__ float snrm[4][CAP];
    int c = cnt[i]; if (c > CAP) c = CAP;
    float di = dinv[i];
    for (int e = lane; e < c; e += 64) {
        int s = src[(size_t)i * CAP + e];
        ssrc[sub][e] = s;
        snrm[sub][e] = dinv[s] * sew[(size_t)i * CAP + e] * di;
    }
    __syncthreads();
    float acc = 0.f;
    if (lane < FEA) {
        acc = di * di * x[(size_t)i * FEA + lane];
        int e = 0;
        for (; e + 2 <= c; e += 2) {
            float v0 = x[(size_t)ssrc[sub][e]     * FEA + lane];
            float v1 = x[(size_t)ssrc[sub][e + 1] * FEA + lane];
            acc = fmaf(snrm[sub][e],     v0, acc);
            acc = fmaf(snrm[sub][e + 1], v1, acc);
        }
        if (e < c)
            acc = fmaf(snrm[sub][e], x[(size_t)ssrc[sub][e] * FEA + lane], acc);
    }
    size_t p = (size_t)i * KP1 + lane;
    split2(acc, &oh[p], &ol[p]);
}

// ---------------- gather of fp16 h (pre-conv2): 2 nodes/block ---------------
__global__ __launch_bounds__(256)
void k_gather_h(const __half* __restrict__ h,
                const float* __restrict__ dinv, const int* __restrict__ cnt,
                const int* __restrict__ src, const float* __restrict__ sew,
                __nv_bfloat16* __restrict__ ah, __nv_bfloat16* __restrict__ al) {
    int sub = threadIdx.x >> 7, lane = threadIdx.x & 127;
    int i = blockIdx.x * 2 + sub;
    __shared__ int   ssrc[2][CAP];
    __shared__ float snrm[2][CAP];
    int c = cnt[i]; if (c > CAP) c = CAP;
    float di = dinv[i];
    if (lane < c) {
        int s = src[(size_t)i * CAP + lane];
        ssrc[sub][lane] = s;
        snrm[sub][lane] = dinv[s] * sew[(size_t)i * CAP + lane] * di;
    }
    __syncthreads();

    const int col = lane * 2;
    float ax, ay;
    {
        float2 v = __half22float2(*(const __half2*)&h[(size_t)i * HID + col]);
        float s = di * di;
        ax = s * v.x;
        ay = s * v.y;
    }
    int e = 0;
    for (; e + 4 <= c; e += 4) {
        float2 v0 = __half22float2(*(const __half2*)&h[(size_t)ssrc[sub][e]     * HID + col]);
        float2 v1 = __half22float2(*(const __half2*)&h[(size_t)ssrc[sub][e + 1] * HID + col]);
        float2 v2 = __half22float2(*(const __half2*)&h[(size_t)ssrc[sub][e + 2] * HID + col]);
        float2 v3 = __half22float2(*(const __half2*)&h[(size_t)ssrc[sub][e + 3] * HID + col]);
        float w0 = snrm[sub][e],     w1 = snrm[sub][e + 1];
        float w2 = snrm[sub][e + 2], w3 = snrm[sub][e + 3];
        ax = fmaf(w0, v0.x, ax); ay = fmaf(w0, v0.y, ay);
        ax = fmaf(w1, v1.x, ax); ay = fmaf(w1, v1.y, ay);
        ax = fmaf(w2, v2.x, ax); ay = fmaf(w2, v2.y, ay);
        ax = fmaf(w3, v3.x, ax); ay = fmaf(w3, v3.y, ay);
    }
    for (; e < c; e++) {
        float2 v0 = __half22float2(*(const __half2*)&h[(size_t)ssrc[sub][e] * HID + col]);
        float w0 = snrm[sub][e];
        ax = fmaf(w0, v0.x, ax); ay = fmaf(w0, v0.y, ay);
    }

    __nv_bfloat16 hx, lx, hy, ly;
    split2(ax, &hx, &lx);
    split2(ay, &hy, &ly);
    size_t p = (size_t)i * HID + col;
    *(__nv_bfloat162*)&ah[p] = __nv_bfloat162(hx, hy);
    *(__nv_bfloat162*)&al[p] = __nv_bfloat162(lx, ly);
}

// ---------------- tensor-core GEMM (cp.async double-buffered) ---------------
// MODE 0: fp32 atomicAdd into C (split-K), no bias
// MODE 1: bias + leaky + fp16 store, linear stride 256 (conv1 -> h)
// MODE 2: bias + leaky + split-bf16 store, flat-mapped (conv2 -> flat)
template<int MODE>
__global__ __launch_bounds__(256)
void bmma(const __nv_bfloat16* __restrict__ Ah, const __nv_bfloat16* __restrict__ Al,
          const __nv_bfloat16* __restrict__ Bh, const __nv_bfloat16* __restrict__ Bl,
          float* __restrict__ C, const float* __restrict__ bias,
          __nv_bfloat16* __restrict__ oh, __nv_bfloat16* __restrict__ ol,
          int K, int kstep) {
    __shared__ __align__(16) __nv_bfloat16 As_h[2][128][24], As_l[2][128][24];
    __shared__ __align__(16) __nv_bfloat16 Bs_h[2][16][136], Bs_l[2][16][136];
    constexpr u32 ABUF = 128 * 24 * 2;
    constexpr u32 BBUF = 16 * 136 * 2;

    const int tid = threadIdx.x;
    const int lane = tid & 31, warp = tid >> 5;
    const int wm = warp >> 2, wn = warp & 3;
    const int row0 = blockIdx.y * 128, col0 = blockIdx.x * 128;
    const int kb = blockIdx.z * kstep;
    const int ke = min(kb + kstep, K);

    const int ar = tid >> 1, ac = (tid & 1) * 8;
    const int bkr = tid >> 4, bc = (tid & 15) * 8;
    const size_t a_base = (size_t)(row0 + ar) * K + ac;

    const u32 a_h_dst = smem_u32(&As_h[0][ar][ac]);
    const u32 a_l_dst = smem_u32(&As_l[0][ar][ac]);
    const u32 b_h_dst = smem_u32(&Bs_h[0][bkr][bc]);
    const u32 b_l_dst = smem_u32(&Bs_l[0][bkr][bc]);

    float acc[4][4][4];
#pragma unroll
    for (int i = 0; i < 4; i++)
#pragma unroll
        for (int j = 0; j < 4; j++)
#pragma unroll
            for (int q = 0; q < 4; q++) acc[i][j][q] = 0.f;

    const int lr = (lane & 7) + ((lane >> 3) & 1) * 8;
    const int lc = (lane >> 4) * 8;
    u32 aaddr_h[4], aaddr_l[4], baddr_h[2], baddr_l[2];
#pragma unroll
    for (int mf = 0; mf < 4; mf++) {
        int r = wm * 64 + mf * 16 + lr;
        aaddr_h[mf] = smem_u32(&As_h[0][r][lc]);
        aaddr_l[mf] = smem_u32(&As_l[0][r][lc]);
    }
#pragma unroll
    for (int g = 0; g < 2; g++) {
        int n = wn * 32 + g * 16 + lc;
        baddr_h[g] = smem_u32(&Bs_h[0][lr][n]);
        baddr_l[g] = smem_u32(&Bs_l[0][lr][n]);
    }

    auto load_stage = [&](int buf, int k0) {
        if (k0 < ke) {
            cp16(a_h_dst + buf * ABUF, Ah + a_base + k0);
            cp16(a_l_dst + buf * ABUF, Al + a_base + k0);
            cp16(b_h_dst + buf * BBUF, Bh + (size_t)(k0 + bkr) * 256 + col0 + bc);
            cp16(b_l_dst + buf * BBUF, Bl + (size_t)(k0 + bkr) * 256 + col0 + bc);
        }
        asm volatile("cp.async.commit_group;");
    };

    load_stage(0, kb);
    load_stage(1, kb + 16);

    int buf = 0;
    for (int k0 = kb; k0 < ke; k0 += 16, buf ^= 1) {
        asm volatile("cp.async.wait_group 1;");
        __syncthreads();

        u32 a_h[4][4], a_l[4][4], b_h[4][2], b_l[4][2];
#pragma unroll
        for (int mf = 0; mf < 4; mf++) {
            ldsm_x4(a_h[mf], aaddr_h[mf] + buf * ABUF);
            ldsm_x4(a_l[mf], aaddr_l[mf] + buf * ABUF);
        }
#pragma unroll
        for (int g = 0; g < 2; g++) {
            u32 t[4];
            ldsm_x4_t(t, baddr_h[g] + buf * BBUF);
            b_h[2*g][0] = t[0]; b_h[2*g][1] = t[1];
            b_h[2*g+1][0] = t[2]; b_h[2*g+1][1] = t[3];
            ldsm_x4_t(t, baddr_l[g] + buf * BBUF);
            b_l[2*g][0] = t[0]; b_l[2*g][1] = t[1];
            b_l[2*g+1][0] = t[2]; b_l[2*g+1][1] = t[3];
        }
#pragma unroll
        for (int mf = 0; mf < 4; mf++)
#pragma unroll
            for (int nf = 0; nf < 4; nf++) {
                mma16816(acc[mf][nf], a_h[mf], b_h[nf]);
                mma16816(acc[mf][nf], a_h[mf], b_l[nf]);
                mma16816(acc[mf][nf], a_l[mf], b_h[nf]);
            }
        __syncthreads();
        load_stage(buf, k0 + 32);
    }

    const int er = lane >> 2, ec = (lane & 3) * 2;
#pragma unroll
    for (int mf = 0; mf < 4; mf++)
#pragma unroll
        for (int nf = 0; nf < 4; nf++) {
            int r = row0 + wm * 64 + mf * 16 + er;
            int c = col0 + wn * 32 + nf * 8 + ec;
            if (MODE == 0) {
                float* p0 = &C[(size_t)r * 256 + c];
                float* p1 = &C[(size_t)(r + 8) * 256 + c];
                atomicAdd(p0,     acc[mf][nf][0]);
                atomicAdd(p0 + 1, acc[mf][nf][1]);
                atomicAdd(p1,     acc[mf][nf][2]);
                atomicAdd(p1 + 1, acc[mf][nf][3]);
            } else {
                float bv0 = bias[c], bv1 = bias[c + 1];
#pragma unroll
                for (int half = 0; half < 2; half++) {
                    int rr = r + half * 8;
                    float v0 = acc[mf][nf][half * 2]     + bv0;
                    float v1 = acc[mf][nf][half * 2 + 1] + bv1;
                    v0 = v0 > 0.f ? v0 : NEG_SLOPE * v0;
                    v1 = v1 > 0.f ? v1 : NEG_SLOPE * v1;
                    if (MODE == 1) {
                        size_t p = (size_t)rr * 256 + c;
                        *(__half2*)&((__half*)oh)[p] = __floats2half2_rn(v0, v1);
                    } else {
                        int b = rr / MACH, m = rr - b * MACH;
                        size_t p = (size_t)b * KP0 + (size_t)m * (HID + FEA) + c;
                        __nv_bfloat16 h0, l0, h1, l1;
                        split2(v0, &h0, &l0);
                        split2(v1, &h1, &l1);
                        *(__nv_bfloat162*)&oh[p] = __nv_bfloat162(h0, h1);
                        *(__nv_bfloat162*)&ol[p] = __nv_bfloat162(l0, l1);
                    }
                }
            }
        }
}

// ---------------- split-K epilogue: bias + leaky + bf16 split ---------------
__global__ void k_epi(float* __restrict__ z, const float* __restrict__ bias,
                      __nv_bfloat16* __restrict__ zh, __nv_bfloat16* __restrict__ zl) {
    int i = blockIdx.x * 256 + threadIdx.x;
    float v = z[i] + bias[i & (HID - 1)];
    v = v > 0.f ? v : NEG_SLOPE * v;
    z[i] = v;
    split2(v, &zh[i], &zl[i]);
}

// ---------------- x -> flat (split) + tail padding, merged -------------------
#define NNFEA ((long long)NN * FEA)
__global__ void k_xpad(const float* __restrict__ x,
                       __nv_bfloat16* __restrict__ fh, __nv_bfloat16* __restrict__ fl) {
    long long idx = (long long)blockIdx.x * 256 + threadIdx.x;
    if (idx < NNFEA) {
        int i = (int)(idx / FEA);
        int j = (int)(idx - (long long)i * FEA);
        int b = i / MACH, m = i - b * MACH;
        size_t p = (size_t)b * KP0 + (size_t)m * (HID + FEA) + HID + j;
        split2(x[idx], &fh[p], &fl[p]);
    } else {
        long long q = idx - NNFEA;          // BATCH*8 pad slots
        int b = (int)(q >> 3), j = (int)(q & 7);
        size_t p = (size_t)b * KP0 + MLP_IN + j;
        fh[p] = __float2bfloat16(0.f);
        fl[p] = __float2bfloat16(0.f);
    }
}

// ---------------- head -------------------------------------------------------
__global__ __launch_bounds__(32)
void k_head(const float* __restrict__ z, const float* __restrict__ Wo,
            const float* __restrict__ bo, float* __restrict__ out) {
    int b = blockIdx.x;
    int lane = threadIdx.x;
    float a0 = 0.f, a1 = 0.f, a2 = 0.f, a3 = 0.f;
    for (int k = lane; k < HID; k += 32) {
        float v = z[(size_t)b * HID + k];
        a0 = fmaf(v, Wo[k * 4 + 0], a0);
        a1 = fmaf(v, Wo[k * 4 + 1], a1);
        a2 = fmaf(v, Wo[k * 4 + 2], a2);
        a3 = fmaf(v, Wo[k * 4 + 3], a3);
    }
#pragma unroll
    for (int o = 16; o > 0; o >>= 1) {
        a0 += __shfl_down_sync(0xffffffffu, a0, o);
        a1 += __shfl_down_sync(0xffffffffu, a1, o);
        a2 += __shfl_down_sync(0xffffffffu, a2, o);
        a3 += __shfl_down_sync(0xffffffffu, a3, o);
    }
    if (lane == 0) {
        out[(size_t)b * 4 + 0] = a0 + bo[0];
        out[(size_t)b * 4 + 1] = a1 + bo[1];
        out[(size_t)b * 4 + 2] = a2 + bo[2];
        out[(size_t)b * 4 + 3] = a3 + bo[3];
    }
}

// ---------------- launcher ---------------------------------------------------
extern "C" void kernel_launch(void* const* d_in, const int* in_sizes, int n_in,
                              void* d_out, int out_size) {
    const float* x   = (const float*)d_in[0];
    const void*  ei  = d_in[1];
    const float* ew  = (const float*)d_in[2];
    const float* W1  = (const float*)d_in[3];
    const float* b1  = (const float*)d_in[4];
    const float* W2  = (const float*)d_in[5];
    const float* b2  = (const float*)d_in[6];
    const float* Wf0 = (const float*)d_in[7];
    const float* bf0 = (const float*)d_in[8];
    const float* Wf1 = (const float*)d_in[9];
    const float* bf1 = (const float*)d_in[10];
    const float* Wf2 = (const float*)d_in[11];
    const float* bf2 = (const float*)d_in[12];
    const float* Wo  = (const float*)d_in[13];
    const float* bo  = (const float*)d_in[14];
    float* out = (float*)d_out;

    float* gf = nullptr; int* gi = nullptr; __nv_bfloat16* gh = nullptr;
    cudaGetSymbolAddress((void**)&gf, g_f);
    cudaGetSymbolAddress((void**)&gi, g_i);
    cudaGetSymbolAddress((void**)&gh, g_h);

    float* deg  = gf + OFF_DEG;
    float* dinv = gf + OFF_DINV;
    float* sew  = gf + OFF_SEW;
    float* z0   = gf + OFF_Z0;
    float* z1   = gf + OFF_Z1;
    int*   cnt  = gi;
    int*   src  = gi + NN;

    __nv_bfloat16 *xh = gh + OFF_XH,  *xl = gh + OFF_XL;
    __nv_bfloat16 *hh = gh + OFF_HH;                     // fp16 h (cast)
    __nv_bfloat16 *ah = gh + OFF_AH,  *al = gh + OFF_AL;
    __nv_bfloat16 *fh = gh + OFF_FH,  *fl = gh + OFF_FL;
    __nv_bfloat16 *w1h = gh + OFF_W1H, *w1l = gh + OFF_W1L;
    __nv_bfloat16 *w2h = gh + OFF_W2H, *w2l = gh + OFF_W2L;
    __nv_bfloat16 *f0h = gh + OFF_F0H, *f0l = gh + OFF_F0L;
    __nv_bfloat16 *f1h = gh + OFF_F1H, *f1l = gh + OFF_F1L;
    __nv_bfloat16 *f2h = gh + OFF_F2H, *f2l = gh + OFF_F2L;
    __nv_bfloat16 *zh = gh + OFF_ZH,   *zl = gh + OFF_ZL;

    const int NB_N = (NN + 255) / 256;
    const int NB_E = (EE + 255) / 256;

    // 4th launch is the one ncu captures: measure k_cvt_all this round
    k_detect<<<1, 32>>>(ei);                                           // 1
    k_zero<<<NB_N, 256>>>(deg, cnt);                                   // 2
    k_degfill<<<NB_E, 256>>>(ei, ew, deg, cnt, src, sew);              // 3
    k_cvt_all<<<CVT_ROWS, 256>>>(W1, W2, Wf0, Wf1, Wf2, gh);           // 4 <- profiled
    k_dinv<<<NB_N, 256>>>(deg, dinv);                                  // 5

    // conv1: aggx = agg(x) ; h = leaky(aggx @ W1 + b1)  -> fp16 h
    k_gather_x<<<NN / 4, 256>>>(x, dinv, cnt, src, sew, xh, xl);
    bmma<1><<<dim3(2, NN / 128, 1), 256>>>(xh, xl, w1h, w1l,
                                           nullptr, b1, hh, nullptr, KP1, KP1);

    // conv2: aggh = agg(h) ; flat[h-part] = leaky(aggh @ W2 + b2)
    k_gather_h<<<NN / 2, 256>>>((const __half*)hh, dinv, cnt, src, sew, ah, al);
    bmma<2><<<dim3(2, NN / 128, 1), 256>>>(ah, al, w2h, w2l,
                                           nullptr, b2, fh, fl, HID, HID);

    // flat[x-part] = x ; pad tail (merged)
    k_xpad<<<(int)((NNFEA + BATCH * 8) / 256), 256>>>(x, fh, fl);

    const size_t ZBYTES = (size_t)BATCH * HID * sizeof(float);

    // MLP0: split-K=8
    cudaMemsetAsync(z0, 0, ZBYTES);
    bmma<0><<<dim3(2, BATCH / 128, 8), 256>>>(fh, fl, f0h, f0l,
                                              z0, nullptr, nullptr, nullptr, KP0, 880);
    k_epi<<<BATCH * HID / 256, 256>>>(z0, bf0, zh, zl);

    // MLP1: split-K=4
    cudaMemsetAsync(z1, 0, ZBYTES);
    bmma<0><<<dim3(2, BATCH / 128, 4), 256>>>(zh, zl, f1h, f1l,
                                              z1, nullptr, nullptr, nullptr, HID, 64);
    k_epi<<<BATCH * HID / 256, 256>>>(z1, bf1, zh, zl);

    // MLP2: split-K=4
    cudaMemsetAsync(z0, 0, ZBYTES);
    bmma<0><<<dim3(2, BATCH / 128, 4), 256>>>(zh, zl, f2h, f2l,
                                              z0, nullptr, nullptr, nullptr, HID, 64);
    k_epi<<<BATCH * HID / 256, 256>>>(z0, bf2, zh, zl);

    // head
    k_head<<<BATCH, 32>>>(z0, Wo, bo, out);
}

// round 9
// speedup vs baseline: 3.8935x; 1.0114x over previous
#include <cuda_runtime.h>
#include <cuda_bf16.h>
#include <cuda_fp16.h>
#include <cstdint>

typedef unsigned int u32;

#define NN 45056
#define EE 720896
#define FEA 60
#define HID 256
#define MACH 22
#define BATCH 2048
#define CAP 96
#define MLP_IN 6952
#define KP0 6960
#define KP1 64
#define NEG_SLOPE 0.01f

// ---------------- fp32 scratch ----------------------------------------------
static constexpr size_t ZSZ  = (size_t)BATCH * HID;
static constexpr size_t OFF_DEG  = 0;
static constexpr size_t OFF_DINV = OFF_DEG  + (size_t)NN;
static constexpr size_t OFF_SEW  = OFF_DINV + (size_t)NN;
static constexpr size_t OFF_ZP   = OFF_SEW  + (size_t)NN * CAP;   // 8 partial slices
static constexpr size_t FTOTAL   = OFF_ZP   + 8 * ZSZ;
__device__ float g_f[FTOTAL];

// ---------------- bf16/fp16 scratch ------------------------------------------
static constexpr size_t XSZ  = (size_t)NN * KP1;
static constexpr size_t HSZ  = (size_t)NN * HID;
static constexpr size_t FSZ  = (size_t)BATCH * KP0;
static constexpr size_t W1SZ = (size_t)KP1 * HID;
static constexpr size_t W2SZ = (size_t)HID * HID;
static constexpr size_t F0SZ = (size_t)KP0 * HID;
static constexpr size_t OFF_XH  = 0;
static constexpr size_t OFF_XL  = OFF_XH  + XSZ;
static constexpr size_t OFF_HH  = OFF_XL  + XSZ;   // fp16 h (HSZ 2B slots)
static constexpr size_t OFF_AH  = OFF_HH  + HSZ;
static constexpr size_t OFF_AL  = OFF_AH  + HSZ;
static constexpr size_t OFF_FH  = OFF_AL  + HSZ;
static constexpr size_t OFF_FL  = OFF_FH  + FSZ;
static constexpr size_t OFF_W1H = OFF_FL  + FSZ;
static constexpr size_t OFF_W1L = OFF_W1H + W1SZ;
static constexpr size_t OFF_W2H = OFF_W1L + W1SZ;
static constexpr size_t OFF_W2L = OFF_W2H + W2SZ;
static constexpr size_t OFF_F0H = OFF_W2L + W2SZ;
static constexpr size_t OFF_F0L = OFF_F0H + F0SZ;
static constexpr size_t OFF_F1H = OFF_F0L + F0SZ;
static constexpr size_t OFF_F1L = OFF_F1H + W2SZ;
static constexpr size_t OFF_F2H = OFF_F1L + W2SZ;
static constexpr size_t OFF_F2L = OFF_F2H + W2SZ;
static constexpr size_t OFF_ZH  = OFF_F2L + W2SZ;
static constexpr size_t OFF_ZL  = OFF_ZH  + ZSZ;
static constexpr size_t HTOTAL  = OFF_ZL  + ZSZ;
__device__ __align__(16) __nv_bfloat16 g_h[HTOTAL];

__device__ int g_i[(size_t)NN * (CAP + 1)];
__device__ int g_is32;

// ---------------- helpers ----------------------------------------------------
__device__ __forceinline__ void split2(float v, __nv_bfloat16* hi, __nv_bfloat16* lo) {
    __nv_bfloat16 h = __float2bfloat16(v);
    *hi = h;
    *lo = __float2bfloat16(v - __bfloat162float(h));
}
__device__ __forceinline__ u32 smem_u32(const void* p) {
    return (u32)__cvta_generic_to_shared(p);
}
__device__ __forceinline__ void cp16(u32 dst, const void* src) {
    asm volatile("cp.async.cg.shared.global [%0], [%1], 16;" :: "r"(dst), "l"(src));
}
__device__ __forceinline__ void ldsm_x4(u32* r, u32 a) {
    asm volatile("ldmatrix.sync.aligned.m8n8.x4.shared.b16 {%0,%1,%2,%3}, [%4];"
        : "=r"(r[0]), "=r"(r[1]), "=r"(r[2]), "=r"(r[3]) : "r"(a));
}
__device__ __forceinline__ void ldsm_x4_t(u32* r, u32 a) {
    asm volatile("ldmatrix.sync.aligned.m8n8.x4.trans.shared.b16 {%0,%1,%2,%3}, [%4];"
        : "=r"(r[0]), "=r"(r[1]), "=r"(r[2]), "=r"(r[3]) : "r"(a));
}
__device__ __forceinline__ void mma16816(float* c, const u32* a, const u32* b) {
    asm volatile(
        "mma.sync.aligned.m16n8k16.row.col.f32.bf16.bf16.f32 "
        "{%0,%1,%2,%3}, {%4,%5,%6,%7}, {%8,%9}, {%0,%1,%2,%3};"
        : "+f"(c[0]), "+f"(c[1]), "+f"(c[2]), "+f"(c[3])
        : "r"(a[0]), "r"(a[1]), "r"(a[2]), "r"(a[3]), "r"(b[0]), "r"(b[1]));
}

// ---------------- init: detect dtype + zero deg/cnt --------------------------
__global__ void k_init(const void* __restrict__ ei,
                       float* __restrict__ deg, int* __restrict__ cnt) {
    int i = blockIdx.x * 256 + threadIdx.x;
    if (i < NN) { deg[i] = 0.f; cnt[i] = 0; }
    if (i == 0) {
        const long long* p = (const long long*)ei;
        int is32 = 0;
        for (int q = 0; q < 64; q++) {
            long long v = p[q];
            if (v < 0 || v >= NN) { is32 = 1; break; }
        }
        g_is32 = is32;
    }
}
__device__ __forceinline__ int edge_idx(const void* ei, int half, int e, int is32) {
    if (is32) return ((const int*)ei)[(size_t)half * EE + e];
    return (int)((const long long*)ei)[(size_t)half * EE + e];
}
__global__ void k_degfill(const void* __restrict__ ei, const float* __restrict__ ew,
                          float* __restrict__ deg, int* __restrict__ cnt,
                          int* __restrict__ src, float* __restrict__ sew) {
    int e = blockIdx.x * 256 + threadIdx.x;
    if (e >= EE) return;
    int is32 = g_is32;
    int r = edge_idx(ei, 0, e, is32);
    int c = edge_idx(ei, 1, e, is32);
    if ((unsigned)r >= (unsigned)NN || (unsigned)c >= (unsigned)NN) return;
    float w = ew[e];
    atomicAdd(&deg[c], w);
    int p = atomicAdd(&cnt[c], 1);
    if (p < CAP) {
        src[(size_t)c * CAP + p] = r;
        sew[(size_t)c * CAP + p] = w;
    }
}
__global__ void k_dinv(const float* __restrict__ deg, float* __restrict__ dinv) {
    int i = blockIdx.x * 256 + threadIdx.x;
    if (i < NN) dinv[i] = rsqrtf(deg[i] + 1.0f);
}

// ---------------- merged weight conversion -----------------------------------
#define CVT_ROWS 7792
__global__ void k_cvt_all(const float* __restrict__ W1, const float* __restrict__ W2,
                          const float* __restrict__ Wf0, const float* __restrict__ Wf1,
                          const float* __restrict__ Wf2,
                          __nv_bfloat16* __restrict__ gh_base) {
    int r = blockIdx.x, t = threadIdx.x;
    float v; size_t off;
    __nv_bfloat16 *dh, *dl;
    if (r < 64) {
        v = (r < FEA) ? W1[(size_t)r * 256 + t] : 0.f;
        dh = gh_base + OFF_W1H; dl = gh_base + OFF_W1L;
        off = (size_t)r * 256 + t;
    } else if (r < 320) {
        int k = r - 64;
        v = W2[(size_t)k * 256 + t];
        dh = gh_base + OFF_W2H; dl = gh_base + OFF_W2L;
        off = (size_t)k * 256 + t;
    } else if (r < 7280) {
        int k = r - 320;
        v = (k < MLP_IN) ? Wf0[(size_t)k * 256 + t] : 0.f;
        dh = gh_base + OFF_F0H; dl = gh_base + OFF_F0L;
        off = (size_t)k * 256 + t;
    } else if (r < 7536) {
        int k = r - 7280;
        v = Wf1[(size_t)k * 256 + t];
        dh = gh_base + OFF_F1H; dl = gh_base + OFF_F1L;
        off = (size_t)k * 256 + t;
    } else {
        int k = r - 7536;
        v = Wf2[(size_t)k * 256 + t];
        dh = gh_base + OFF_F2H; dl = gh_base + OFF_F2L;
        off = (size_t)k * 256 + t;
    }
    split2(v, &dh[off], &dl[off]);
}

// ---------------- gather of raw x (pre-conv1): 4 nodes/block ----------------
__global__ __launch_bounds__(256)
void k_gather_x(const float* __restrict__ x, const float* __restrict__ dinv,
                const int* __restrict__ cnt, const int* __restrict__ src,
                const float* __restrict__ sew,
                __nv_bfloat16* __restrict__ oh, __nv_bfloat16* __restrict__ ol) {
    int sub = threadIdx.x >> 6, lane = threadIdx.x & 63;
    int i = blockIdx.x * 4 + sub;
    __shared__ int   ssrc[4][CAP];
    __shared__ float snrm[4][CAP];
    int c = cnt[i]; if (c > CAP) c = CAP;
    float di = dinv[i];
    for (int e = lane; e < c; e += 64) {
        int s = src[(size_t)i * CAP + e];
        ssrc[sub][e] = s;
        snrm[sub][e] = dinv[s] * sew[(size_t)i * CAP + e] * di;
    }
    __syncthreads();
    float acc = 0.f;
    if (lane < FEA) {
        acc = di * di * x[(size_t)i * FEA + lane];
        int e = 0;
        for (; e + 2 <= c; e += 2) {
            float v0 = x[(size_t)ssrc[sub][e]     * FEA + lane];
            float v1 = x[(size_t)ssrc[sub][e + 1] * FEA + lane];
            acc = fmaf(snrm[sub][e],     v0, acc);
            acc = fmaf(snrm[sub][e + 1], v1, acc);
        }
        if (e < c)
            acc = fmaf(snrm[sub][e], x[(size_t)ssrc[sub][e] * FEA + lane], acc);
    }
    size_t p = (size_t)i * KP1 + lane;
    split2(acc, &oh[p], &ol[p]);
}

// ---------------- gather of fp16 h (pre-conv2): 2 nodes/block ---------------
__global__ __launch_bounds__(256)
void k_gather_h(const __half* __restrict__ h,
                const float* __restrict__ dinv, const int* __restrict__ cnt,
                const int* __restrict__ src, const float* __restrict__ sew,
                __nv_bfloat16* __restrict__ ah, __nv_bfloat16* __restrict__ al) {
    int sub = threadIdx.x >> 7, lane = threadIdx.x & 127;
    int i = blockIdx.x * 2 + sub;
    __shared__ int   ssrc[2][CAP];
    __shared__ float snrm[2][CAP];
    int c = cnt[i]; if (c > CAP) c = CAP;
    float di = dinv[i];
    if (lane < c) {
        int s = src[(size_t)i * CAP + lane];
        ssrc[sub][lane] = s;
        snrm[sub][lane] = dinv[s] * sew[(size_t)i * CAP + lane] * di;
    }
    __syncthreads();

    const int col = lane * 2;
    float ax, ay;
    {
        float2 v = __half22float2(*(const __half2*)&h[(size_t)i * HID + col]);
        float s = di * di;
        ax = s * v.x;
        ay = s * v.y;
    }
    int e = 0;
    for (; e + 4 <= c; e += 4) {
        float2 v0 = __half22float2(*(const __half2*)&h[(size_t)ssrc[sub][e]     * HID + col]);
        float2 v1 = __half22float2(*(const __half2*)&h[(size_t)ssrc[sub][e + 1] * HID + col]);
        float2 v2 = __half22float2(*(const __half2*)&h[(size_t)ssrc[sub][e + 2] * HID + col]);
        float2 v3 = __half22float2(*(const __half2*)&h[(size_t)ssrc[sub][e + 3] * HID + col]);
        float w0 = snrm[sub][e],     w1 = snrm[sub][e + 1];
        float w2 = snrm[sub][e + 2], w3 = snrm[sub][e + 3];
        ax = fmaf(w0, v0.x, ax); ay = fmaf(w0, v0.y, ay);
        ax = fmaf(w1, v1.x, ax); ay = fmaf(w1, v1.y, ay);
        ax = fmaf(w2, v2.x, ax); ay = fmaf(w2, v2.y, ay);
        ax = fmaf(w3, v3.x, ax); ay = fmaf(w3, v3.y, ay);
    }
    for (; e < c; e++) {
        float2 v0 = __half22float2(*(const __half2*)&h[(size_t)ssrc[sub][e] * HID + col]);
        float w0 = snrm[sub][e];
        ax = fmaf(w0, v0.x, ax); ay = fmaf(w0, v0.y, ay);
    }

    __nv_bfloat16 hx, lx, hy, ly;
    split2(ax, &hx, &lx);
    split2(ay, &hy, &ly);
    size_t p = (size_t)i * HID + col;
    *(__nv_bfloat162*)&ah[p] = __nv_bfloat162(hx, hy);
    *(__nv_bfloat162*)&al[p] = __nv_bfloat162(lx, ly);
}

// ---------------- tensor-core GEMM (cp.async double-buffered) ---------------
// MODE 0: store partials to C + blockIdx.z*ZSZ (split-K, no atomics)
// MODE 1: bias + leaky + fp16 store, linear stride 256 (conv1 -> h)
// MODE 2: bias + leaky + split-bf16 store, flat-mapped (conv2 -> flat)
template<int MODE>
__global__ __launch_bounds__(256)
void bmma(const __nv_bfloat16* __restrict__ Ah, const __nv_bfloat16* __restrict__ Al,
          const __nv_bfloat16* __restrict__ Bh, const __nv_bfloat16* __restrict__ Bl,
          float* __restrict__ C, const float* __restrict__ bias,
          __nv_bfloat16* __restrict__ oh, __nv_bfloat16* __restrict__ ol,
          int K, int kstep) {
    __shared__ __align__(16) __nv_bfloat16 As_h[2][128][24], As_l[2][128][24];
    __shared__ __align__(16) __nv_bfloat16 Bs_h[2][16][136], Bs_l[2][16][136];
    constexpr u32 ABUF = 128 * 24 * 2;
    constexpr u32 BBUF = 16 * 136 * 2;

    const int tid = threadIdx.x;
    const int lane = tid & 31, warp = tid >> 5;
    const int wm = warp >> 2, wn = warp & 3;
    const int row0 = blockIdx.y * 128, col0 = blockIdx.x * 128;
    const int kb = blockIdx.z * kstep;
    const int ke = min(kb + kstep, K);

    const int ar = tid >> 1, ac = (tid & 1) * 8;
    const int bkr = tid >> 4, bc = (tid & 15) * 8;
    const size_t a_base = (size_t)(row0 + ar) * K + ac;

    const u32 a_h_dst = smem_u32(&As_h[0][ar][ac]);
    const u32 a_l_dst = smem_u32(&As_l[0][ar][ac]);
    const u32 b_h_dst = smem_u32(&Bs_h[0][bkr][bc]);
    const u32 b_l_dst = smem_u32(&Bs_l[0][bkr][bc]);

    float acc[4][4][4];
#pragma unroll
    for (int i = 0; i < 4; i++)
#pragma unroll
        for (int j = 0; j < 4; j++)
#pragma unroll
            for (int q = 0; q < 4; q++) acc[i][j][q] = 0.f;

    const int lr = (lane & 7) + ((lane >> 3) & 1) * 8;
    const int lc = (lane >> 4) * 8;
    u32 aaddr_h[4], aaddr_l[4], baddr_h[2], baddr_l[2];
#pragma unroll
    for (int mf = 0; mf < 4; mf++) {
        int r = wm * 64 + mf * 16 + lr;
        aaddr_h[mf] = smem_u32(&As_h[0][r][lc]);
        aaddr_l[mf] = smem_u32(&As_l[0][r][lc]);
    }
#pragma unroll
    for (int g = 0; g < 2; g++) {
        int n = wn * 32 + g * 16 + lc;
        baddr_h[g] = smem_u32(&Bs_h[0][lr][n]);
        baddr_l[g] = smem_u32(&Bs_l[0][lr][n]);
    }

    auto load_stage = [&](int buf, int k0) {
        if (k0 < ke) {
            cp16(a_h_dst + buf * ABUF, Ah + a_base + k0);
            cp16(a_l_dst + buf * ABUF, Al + a_base + k0);
            cp16(b_h_dst + buf * BBUF, Bh + (size_t)(k0 + bkr) * 256 + col0 + bc);
            cp16(b_l_dst + buf * BBUF, Bl + (size_t)(k0 + bkr) * 256 + col0 + bc);
        }
        asm volatile("cp.async.commit_group;");
    };

    load_stage(0, kb);
    load_stage(1, kb + 16);

    int buf = 0;
    for (int k0 = kb; k0 < ke; k0 += 16, buf ^= 1) {
        asm volatile("cp.async.wait_group 1;");
        __syncthreads();

        u32 a_h[4][4], a_l[4][4], b_h[4][2], b_l[4][2];
#pragma unroll
        for (int mf = 0; mf < 4; mf++) {
            ldsm_x4(a_h[mf], aaddr_h[mf] + buf * ABUF);
            ldsm_x4(a_l[mf], aaddr_l[mf] + buf * ABUF);
        }
#pragma unroll
        for (int g = 0; g < 2; g++) {
            u32 t[4];
            ldsm_x4_t(t, baddr_h[g] + buf * BBUF);
            b_h[2*g][0] = t[0]; b_h[2*g][1] = t[1];
            b_h[2*g+1][0] = t[2]; b_h[2*g+1][1] = t[3];
            ldsm_x4_t(t, baddr_l[g] + buf * BBUF);
            b_l[2*g][0] = t[0]; b_l[2*g][1] = t[1];
            b_l[2*g+1][0] = t[2]; b_l[2*g+1][1] = t[3];
        }
#pragma unroll
        for (int mf = 0; mf < 4; mf++)
#pragma unroll
            for (int nf = 0; nf < 4; nf++) {
                mma16816(acc[mf][nf], a_h[mf], b_h[nf]);
                mma16816(acc[mf][nf], a_h[mf], b_l[nf]);
                mma16816(acc[mf][nf], a_l[mf], b_h[nf]);
            }
        __syncthreads();
        load_stage(buf, k0 + 32);
    }

    const int er = lane >> 2, ec = (lane & 3) * 2;
    float* Cz = (MODE == 0) ? C + (size_t)blockIdx.z * ZSZ : C;
#pragma unroll
    for (int mf = 0; mf < 4; mf++)
#pragma unroll
        for (int nf = 0; nf < 4; nf++) {
            int r = row0 + wm * 64 + mf * 16 + er;
            int c = col0 + wn * 32 + nf * 8 + ec;
            if (MODE == 0) {
                float* p0 = &Cz[(size_t)r * 256 + c];
                float* p1 = &Cz[(size_t)(r + 8) * 256 + c];
                p0[0] = acc[mf][nf][0]; p0[1] = acc[mf][nf][1];
                p1[0] = acc[mf][nf][2]; p1[1] = acc[mf][nf][3];
            } else {
                float bv0 = bias[c], bv1 = bias[c + 1];
#pragma unroll
                for (int half = 0; half < 2; half++) {
                    int rr = r + half * 8;
                    float v0 = acc[mf][nf][half * 2]     + bv0;
                    float v1 = acc[mf][nf][half * 2 + 1] + bv1;
                    v0 = v0 > 0.f ? v0 : NEG_SLOPE * v0;
                    v1 = v1 > 0.f ? v1 : NEG_SLOPE * v1;
                    if (MODE == 1) {
                        size_t p = (size_t)rr * 256 + c;
                        *(__half2*)&((__half*)oh)[p] = __floats2half2_rn(v0, v1);
                    } else {
                        int b = rr / MACH, m = rr - b * MACH;
                        size_t p = (size_t)b * KP0 + (size_t)m * (HID + FEA) + c;
                        __nv_bfloat16 h0, l0, h1, l1;
                        split2(v0, &h0, &l0);
                        split2(v1, &h1, &l1);
                        *(__nv_bfloat162*)&oh[p] = __nv_bfloat162(h0, h1);
                        *(__nv_bfloat162*)&ol[p] = __nv_bfloat162(l0, l1);
                    }
                }
            }
        }
}

// ---------------- split-K reduce + bias + leaky + bf16 split -----------------
template<int S>
__global__ void k_epi(const float* __restrict__ zp, const float* __restrict__ bias,
                      __nv_bfloat16* __restrict__ zh, __nv_bfloat16* __restrict__ zl) {
    size_t i = (size_t)blockIdx.x * 256 + threadIdx.x;
    float v = bias[i & (HID - 1)];
#pragma unroll
    for (int s = 0; s < S; s++) v += zp[s * ZSZ + i];
    v = v > 0.f ? v : NEG_SLOPE * v;
    split2(v, &zh[i], &zl[i]);
}

// ---------------- final: reduce + bias + leaky + head GEMV -------------------
__global__ __launch_bounds__(256)
void k_epihead(const float* __restrict__ zp, const float* __restrict__ bias,
               const float* __restrict__ Wo, const float* __restrict__ bo,
               float* __restrict__ out) {
    __shared__ float zrow[HID];
    int b = blockIdx.x, t = threadIdx.x;
    size_t i = (size_t)b * HID + t;
    float v = bias[t];
#pragma unroll
    for (int s = 0; s < 4; s++) v += zp[s * ZSZ + i];
    v = v > 0.f ? v : NEG_SLOPE * v;
    zrow[t] = v;
    __syncthreads();
    if (t < 128) {
        int j = t >> 5, lane = t & 31;
        float a = 0.f;
#pragma unroll
        for (int q = 0; q < 8; q++) {
            int k = lane + q * 32;
            a = fmaf(zrow[k], Wo[k * 4 + j], a);
        }
#pragma unroll
        for (int o = 16; o > 0; o >>= 1)
            a += __shfl_down_sync(0xffffffffu, a, o);
        if (lane == 0) out[(size_t)b * 4 + j] = a + bo[j];
    }
}

// ---------------- x -> flat (split) + tail padding ---------------------------
#define NNFEA ((long long)NN * FEA)
__global__ void k_xpad(const float* __restrict__ x,
                       __nv_bfloat16* __restrict__ fh, __nv_bfloat16* __restrict__ fl) {
    long long idx = (long long)blockIdx.x * 256 + threadIdx.x;
    if (idx < NNFEA) {
        int i = (int)(idx / FEA);
        int j = (int)(idx - (long long)i * FEA);
        int b = i / MACH, m = i - b * MACH;
        size_t p = (size_t)b * KP0 + (size_t)m * (HID + FEA) + HID + j;
        split2(x[idx], &fh[p], &fl[p]);
    } else {
        long long q = idx - NNFEA;
        int b = (int)(q >> 3), j = (int)(q & 7);
        size_t p = (size_t)b * KP0 + MLP_IN + j;
        fh[p] = __float2bfloat16(0.f);
        fl[p] = __float2bfloat16(0.f);
    }
}

// ---------------- launcher ---------------------------------------------------
extern "C" void kernel_launch(void* const* d_in, const int* in_sizes, int n_in,
                              void* d_out, int out_size) {
    const float* x   = (const float*)d_in[0];
    const void*  ei  = d_in[1];
    const float* ew  = (const float*)d_in[2];
    const float* W1  = (const float*)d_in[3];
    const float* b1  = (const float*)d_in[4];
    const float* W2  = (const float*)d_in[5];
    const float* b2  = (const float*)d_in[6];
    const float* Wf0 = (const float*)d_in[7];
    const float* bf0 = (const float*)d_in[8];
    const float* Wf1 = (const float*)d_in[9];
    const float* bf1 = (const float*)d_in[10];
    const float* Wf2 = (const float*)d_in[11];
    const float* bf2 = (const float*)d_in[12];
    const float* Wo  = (const float*)d_in[13];
    const float* bo  = (const float*)d_in[14];
    float* out = (float*)d_out;

    float* gf = nullptr; int* gi = nullptr; __nv_bfloat16* gh = nullptr;
    cudaGetSymbolAddress((void**)&gf, g_f);
    cudaGetSymbolAddress((void**)&gi, g_i);
    cudaGetSymbolAddress((void**)&gh, g_h);

    float* deg  = gf + OFF_DEG;
    float* dinv = gf + OFF_DINV;
    float* sew  = gf + OFF_SEW;
    float* zp   = gf + OFF_ZP;
    int*   cnt  = gi;
    int*   src  = gi + NN;

    __nv_bfloat16 *xh = gh + OFF_XH,  *xl = gh + OFF_XL;
    __nv_bfloat16 *hh = gh + OFF_HH;
    __nv_bfloat16 *ah = gh + OFF_AH,  *al = gh + OFF_AL;
    __nv_bfloat16 *fh = gh + OFF_FH,  *fl = gh + OFF_FL;
    __nv_bfloat16 *w1h = gh + OFF_W1H, *w1l = gh + OFF_W1L;
    __nv_bfloat16 *w2h = gh + OFF_W2H, *w2l = gh + OFF_W2L;
    __nv_bfloat16 *f0h = gh + OFF_F0H, *f0l = gh + OFF_F0L;
    __nv_bfloat16 *f1h = gh + OFF_F1H, *f1l = gh + OFF_F1L;
    __nv_bfloat16 *f2h = gh + OFF_F2H, *f2l = gh + OFF_F2L;
    __nv_bfloat16 *zh = gh + OFF_ZH,   *zl = gh + OFF_ZL;

    const int NB_N = (NN + 255) / 256;
    const int NB_E = (EE + 255) / 256;

    // 4th launch is the profiled one: k_gather_x this round
    k_init<<<NB_N, 256>>>(ei, deg, cnt);                               // 1
    k_degfill<<<NB_E, 256>>>(ei, ew, deg, cnt, src, sew);              // 2
    k_dinv<<<NB_N, 256>>>(deg, dinv);                                  // 3
    k_gather_x<<<NN / 4, 256>>>(x, dinv, cnt, src, sew, xh, xl);       // 4 <- profiled
    k_cvt_all<<<CVT_ROWS, 256>>>(W1, W2, Wf0, Wf1, Wf2, gh);           // 5

    // conv1: h = leaky(aggx @ W1 + b1) -> fp16
    bmma<1><<<dim3(2, NN / 128, 1), 256>>>(xh, xl, w1h, w1l,
                                           nullptr, b1, hh, nullptr, KP1, KP1);

    // conv2: flat[h-part] = leaky(agg(h) @ W2 + b2)
    k_gather_h<<<NN / 2, 256>>>((const __half*)hh, dinv, cnt, src, sew, ah, al);
    bmma<2><<<dim3(2, NN / 128, 1), 256>>>(ah, al, w2h, w2l,
                                           nullptr, b2, fh, fl, HID, HID);

    // flat[x-part] = x ; pad tail
    k_xpad<<<(int)((NNFEA + BATCH * 8) / 256), 256>>>(x, fh, fl);

    // MLP0: split-K=8 -> partial stores -> reduce epi
    bmma<0><<<dim3(2, BATCH / 128, 8), 256>>>(fh, fl, f0h, f0l,
                                              zp, nullptr, nullptr, nullptr, KP0, 880);
    k_epi<8><<<(int)(ZSZ / 256), 256>>>(zp, bf0, zh, zl);

    // MLP1: split-K=4
    bmma<0><<<dim3(2, BATCH / 128, 4), 256>>>(zh, zl, f1h, f1l,
                                              zp, nullptr, nullptr, nullptr, HID, 64);
    k_epi<4><<<(int)(ZSZ / 256), 256>>>(zp, bf1, zh, zl);

    // MLP2: split-K=4 -> fused reduce + head
    bmma<0><<<dim3(2, BATCH / 128, 4), 256>>>(zh, zl, f2h, f2l,
                                              zp, nullptr, nullptr, nullptr, HID, 64);
    k_epihead<<<BATCH, 256>>>(zp, bf2, Wo, bo, out);
}

// round 10
// speedup vs baseline: 4.2446x; 1.0902x over previous
#include <cuda_runtime.h>
#include <cuda_bf16.h>
#include <cuda_fp16.h>
#include <cstdint>

typedef unsigned int u32;

#define NN 45056
#define EE 720896
#define FEA 60
#define HID 256
#define MACH 22
#define BATCH 2048
#define CAP 96
#define MLP_IN 6952
#define KP0 6960
#define KP1 64
#define NEG_SLOPE 0.01f

// ---------------- fp32 scratch ----------------------------------------------
static constexpr size_t ZSZ  = (size_t)BATCH * HID;
static constexpr size_t OFF_DINV = 0;
static constexpr size_t OFF_SEW  = OFF_DINV + (size_t)NN;
static constexpr size_t OFF_ZP   = OFF_SEW  + (size_t)NN * CAP;
static constexpr size_t FTOTAL   = OFF_ZP   + 8 * ZSZ;
__device__ float g_f[FTOTAL];

// ---------------- bf16/fp16 scratch ------------------------------------------
static constexpr size_t XSZ  = (size_t)NN * KP1;
static constexpr size_t HSZ  = (size_t)NN * HID;
static constexpr size_t FSZ  = (size_t)BATCH * KP0;
static constexpr size_t W1SZ = (size_t)KP1 * HID;
static constexpr size_t W2SZ = (size_t)HID * HID;
static constexpr size_t F0SZ = (size_t)KP0 * HID;
static constexpr size_t OFF_XH  = 0;
static constexpr size_t OFF_XL  = OFF_XH  + XSZ;
static constexpr size_t OFF_HH  = OFF_XL  + XSZ;   // fp16 h (HSZ 2B slots)
static constexpr size_t OFF_AH  = OFF_HH  + HSZ;
static constexpr size_t OFF_AL  = OFF_AH  + HSZ;
static constexpr size_t OFF_FH  = OFF_AL  + HSZ;
static constexpr size_t OFF_FL  = OFF_FH  + FSZ;
static constexpr size_t OFF_W1H = OFF_FL  + FSZ;
static constexpr size_t OFF_W1L = OFF_W1H + W1SZ;
static constexpr size_t OFF_W2H = OFF_W1L + W1SZ;
static constexpr size_t OFF_W2L = OFF_W2H + W2SZ;
static constexpr size_t OFF_F0H = OFF_W2L + W2SZ;
static constexpr size_t OFF_F0L = OFF_F0H + F0SZ;
static constexpr size_t OFF_F1H = OFF_F0L + F0SZ;
static constexpr size_t OFF_F1L = OFF_F1H + W2SZ;
static constexpr size_t OFF_F2H = OFF_F1L + W2SZ;
static constexpr size_t OFF_F2L = OFF_F2H + W2SZ;
static constexpr size_t OFF_ZH  = OFF_F2L + W2SZ;
static constexpr size_t OFF_ZL  = OFF_ZH  + ZSZ;
static constexpr size_t HTOTAL  = OFF_ZL  + ZSZ;
__device__ __align__(16) __nv_bfloat16 g_h[HTOTAL];

__device__ int g_i[(size_t)NN * (CAP + 1)];
__device__ int g_is32;

// ---------------- helpers ----------------------------------------------------
__device__ __forceinline__ void split2(float v, __nv_bfloat16* hi, __nv_bfloat16* lo) {
    __nv_bfloat16 h = __float2bfloat16(v);
    *hi = h;
    *lo = __float2bfloat16(v - __bfloat162float(h));
}
__device__ __forceinline__ u32 smem_u32(const void* p) {
    return (u32)__cvta_generic_to_shared(p);
}
__device__ __forceinline__ void cp16(u32 dst, const void* src) {
    asm volatile("cp.async.cg.shared.global [%0], [%1], 16;" :: "r"(dst), "l"(src));
}
__device__ __forceinline__ void ldsm_x4(u32* r, u32 a) {
    asm volatile("ldmatrix.sync.aligned.m8n8.x4.shared.b16 {%0,%1,%2,%3}, [%4];"
        : "=r"(r[0]), "=r"(r[1]), "=r"(r[2]), "=r"(r[3]) : "r"(a));
}
__device__ __forceinline__ void ldsm_x4_t(u32* r, u32 a) {
    asm volatile("ldmatrix.sync.aligned.m8n8.x4.trans.shared.b16 {%0,%1,%2,%3}, [%4];"
        : "=r"(r[0]), "=r"(r[1]), "=r"(r[2]), "=r"(r[3]) : "r"(a));
}
__device__ __forceinline__ void mma16816(float* c, const u32* a, const u32* b) {
    asm volatile(
        "mma.sync.aligned.m16n8k16.row.col.f32.bf16.bf16.f32 "
        "{%0,%1,%2,%3}, {%4,%5,%6,%7}, {%8,%9}, {%0,%1,%2,%3};"
        : "+f"(c[0]), "+f"(c[1]), "+f"(c[2]), "+f"(c[3])
        : "r"(a[0]), "r"(a[1]), "r"(a[2]), "r"(a[3]), "r"(b[0]), "r"(b[1]));
}
__device__ __forceinline__ void h8_to_f8(uint4 v, float* f) {
    float2 p;
    p = __half22float2(*(__half2*)&v.x); f[0] = p.x; f[1] = p.y;
    p = __half22float2(*(__half2*)&v.y); f[2] = p.x; f[3] = p.y;
    p = __half22float2(*(__half2*)&v.z); f[4] = p.x; f[5] = p.y;
    p = __half22float2(*(__half2*)&v.w); f[6] = p.x; f[7] = p.y;
}

// ---------------- init: detect dtype + zero cnt -------------------------------
__global__ void k_init(const void* __restrict__ ei, int* __restrict__ cnt) {
    int i = blockIdx.x * 256 + threadIdx.x;
    if (i < NN) cnt[i] = 0;
    if (i == 0) {
        const long long* p = (const long long*)ei;
        int is32 = 0;
        for (int q = 0; q < 64; q++) {
            long long v = p[q];
            if (v < 0 || v >= NN) { is32 = 1; break; }
        }
        g_is32 = is32;
    }
}
__device__ __forceinline__ int edge_idx(const void* ei, int half, int e, int is32) {
    if (is32) return ((const int*)ei)[(size_t)half * EE + e];
    return (int)((const long long*)ei)[(size_t)half * EE + e];
}
__global__ void k_degfill(const void* __restrict__ ei, const float* __restrict__ ew,
                          int* __restrict__ cnt,
                          int* __restrict__ src, float* __restrict__ sew) {
    int e = blockIdx.x * 256 + threadIdx.x;
    if (e >= EE) return;
    int is32 = g_is32;
    int r = edge_idx(ei, 0, e, is32);
    int c = edge_idx(ei, 1, e, is32);
    if ((unsigned)r >= (unsigned)NN || (unsigned)c >= (unsigned)NN) return;
    float w = ew[e];
    int p = atomicAdd(&cnt[c], 1);
    if (p < CAP) {
        src[c * CAP + p] = r;
        sew[c * CAP + p] = w;
    }
}
// warp-per-node degree reduce + rsqrt
__global__ void k_dinv(const float* __restrict__ sew, const int* __restrict__ cnt,
                       float* __restrict__ dinv) {
    int node = (blockIdx.x * 256 + threadIdx.x) >> 5;
    int lane = threadIdx.x & 31;
    if (node >= NN) return;
    int c = cnt[node]; if (c > CAP) c = CAP;
    float s = 0.f;
    for (int e = lane; e < c; e += 32) s += sew[node * CAP + e];
#pragma unroll
    for (int o = 16; o; o >>= 1) s += __shfl_xor_sync(0xffffffffu, s, o);
    if (lane == 0) dinv[node] = rsqrtf(s + 1.0f);
}

// ---------------- merged weight conversion -----------------------------------
#define CVT_ROWS 7792
__global__ void k_cvt_all(const float* __restrict__ W1, const float* __restrict__ W2,
                          const float* __restrict__ Wf0, const float* __restrict__ Wf1,
                          const float* __restrict__ Wf2,
                          __nv_bfloat16* __restrict__ gh_base) {
    int r = blockIdx.x, t = threadIdx.x;
    float v; size_t off;
    __nv_bfloat16 *dh, *dl;
    if (r < 64) {
        v = (r < FEA) ? W1[(size_t)r * 256 + t] : 0.f;
        dh = gh_base + OFF_W1H; dl = gh_base + OFF_W1L;
        off = (size_t)r * 256 + t;
    } else if (r < 320) {
        int k = r - 64;
        v = W2[(size_t)k * 256 + t];
        dh = gh_base + OFF_W2H; dl = gh_base + OFF_W2L;
        off = (size_t)k * 256 + t;
    } else if (r < 7280) {
        int k = r - 320;
        v = (k < MLP_IN) ? Wf0[(size_t)k * 256 + t] : 0.f;
        dh = gh_base + OFF_F0H; dl = gh_base + OFF_F0L;
        off = (size_t)k * 256 + t;
    } else if (r < 7536) {
        int k = r - 7280;
        v = Wf1[(size_t)k * 256 + t];
        dh = gh_base + OFF_F1H; dl = gh_base + OFF_F1L;
        off = (size_t)k * 256 + t;
    } else {
        int k = r - 7536;
        v = Wf2[(size_t)k * 256 + t];
        dh = gh_base + OFF_F2H; dl = gh_base + OFF_F2L;
        off = (size_t)k * 256 + t;
    }
    split2(v, &dh[off], &dl[off]);
}

// ---------------- gather x (float4, 16 lanes/node, 16 nodes/block) ----------
__global__ __launch_bounds__(256)
void k_gather_x(const float4* __restrict__ x4, const float* __restrict__ dinv,
                const int* __restrict__ cnt, const int* __restrict__ src,
                const float* __restrict__ sew,
                __nv_bfloat16* __restrict__ oh, __nv_bfloat16* __restrict__ ol) {
    int sub = threadIdx.x >> 4, lane = threadIdx.x & 15;
    int i = blockIdx.x * 16 + sub;
    __shared__ int   ssrc[16][CAP];
    __shared__ float snrm[16][CAP];
    int c = cnt[i]; if (c > CAP) c = CAP;
    float di = dinv[i];
    for (int e = lane; e < c; e += 16) {
        int s = src[i * CAP + e];
        ssrc[sub][e] = s * 15;                  // float4 row offset
        snrm[sub][e] = dinv[s] * sew[i * CAP + e] * di;
    }
    __syncwarp();

    float a0 = 0.f, a1 = 0.f, a2 = 0.f, a3 = 0.f;
    if (lane < 15) {
        float4 v = x4[i * 15 + lane];
        float s = di * di;
        a0 = s * v.x; a1 = s * v.y; a2 = s * v.z; a3 = s * v.w;
#pragma unroll 2
        for (int e = 0; e < c; e++) {
            float w = snrm[sub][e];
            float4 u = x4[ssrc[sub][e] + lane];
            a0 = fmaf(w, u.x, a0); a1 = fmaf(w, u.y, a1);
            a2 = fmaf(w, u.z, a2); a3 = fmaf(w, u.w, a3);
        }
    }
    int p = i * KP1 + lane * 4;
    __nv_bfloat16 h0, l0, h1, l1, h2, l2, h3, l3;
    split2(a0, &h0, &l0); split2(a1, &h1, &l1);
    split2(a2, &h2, &l2); split2(a3, &h3, &l3);
    *(__nv_bfloat162*)&oh[p]     = __nv_bfloat162(h0, h1);
    *(__nv_bfloat162*)&oh[p + 2] = __nv_bfloat162(h2, h3);
    *(__nv_bfloat162*)&ol[p]     = __nv_bfloat162(l0, l1);
    *(__nv_bfloat162*)&ol[p + 2] = __nv_bfloat162(l2, l3);
}

// ---------------- gather h (uint4 fp16, 1 warp/node, 8 nodes/block) ---------
__global__ __launch_bounds__(256)
void k_gather_h(const uint4* __restrict__ h4,
                const float* __restrict__ dinv, const int* __restrict__ cnt,
                const int* __restrict__ src, const float* __restrict__ sew,
                __nv_bfloat16* __restrict__ ah, __nv_bfloat16* __restrict__ al) {
    int sub = threadIdx.x >> 5, lane = threadIdx.x & 31;
    int i = blockIdx.x * 8 + sub;
    __shared__ int   ssrc[8][CAP];
    __shared__ float snrm[8][CAP];
    int c = cnt[i]; if (c > CAP) c = CAP;
    float di = dinv[i];
    for (int e = lane; e < c; e += 32) {
        int s = src[i * CAP + e];
        ssrc[sub][e] = s * 32;                  // uint4 row offset (256 halves / 8)
        snrm[sub][e] = dinv[s] * sew[i * CAP + e] * di;
    }
    __syncwarp();

    float acc[8];
    {
        float f[8];
        h8_to_f8(h4[i * 32 + lane], f);
        float s = di * di;
#pragma unroll
        for (int q = 0; q < 8; q++) acc[q] = s * f[q];
    }
#pragma unroll 2
    for (int e = 0; e < c; e++) {
        float w = snrm[sub][e];
        float f[8];
        h8_to_f8(h4[ssrc[sub][e] + lane], f);
#pragma unroll
        for (int q = 0; q < 8; q++) acc[q] = fmaf(w, f[q], acc[q]);
    }

    int p = i * HID + lane * 8;
#pragma unroll
    for (int q = 0; q < 4; q++) {
        __nv_bfloat16 hx, lx, hy, ly;
        split2(acc[2 * q],     &hx, &lx);
        split2(acc[2 * q + 1], &hy, &ly);
        *(__nv_bfloat162*)&ah[p + 2 * q] = __nv_bfloat162(hx, hy);
        *(__nv_bfloat162*)&al[p + 2 * q] = __nv_bfloat162(lx, ly);
    }
}

// ---------------- tensor-core GEMM (cp.async double-buffered) ---------------
// MODE 0: store partials to C + blockIdx.z*ZSZ (split-K)
// MODE 1: bias + leaky + fp16 store, linear stride 256 (conv1 -> h)
// MODE 2: bias + leaky + split-bf16 store, flat-mapped (conv2 -> flat)
template<int MODE>
__global__ __launch_bounds__(256)
void bmma(const __nv_bfloat16* __restrict__ Ah, const __nv_bfloat16* __restrict__ Al,
          const __nv_bfloat16* __restrict__ Bh, const __nv_bfloat16* __restrict__ Bl,
          float* __restrict__ C, const float* __restrict__ bias,
          __nv_bfloat16* __restrict__ oh, __nv_bfloat16* __restrict__ ol,
          int K, int kstep) {
    __shared__ __align__(16) __nv_bfloat16 As_h[2][128][24], As_l[2][128][24];
    __shared__ __align__(16) __nv_bfloat16 Bs_h[2][16][136], Bs_l[2][16][136];
    constexpr u32 ABUF = 128 * 24 * 2;
    constexpr u32 BBUF = 16 * 136 * 2;

    const int tid = threadIdx.x;
    const int lane = tid & 31, warp = tid >> 5;
    const int wm = warp >> 2, wn = warp & 3;
    const int row0 = blockIdx.y * 128, col0 = blockIdx.x * 128;
    const int kb = blockIdx.z * kstep;
    const int ke = min(kb + kstep, K);

    const int ar = tid >> 1, ac = (tid & 1) * 8;
    const int bkr = tid >> 4, bc = (tid & 15) * 8;
    const size_t a_base = (size_t)(row0 + ar) * K + ac;

    const u32 a_h_dst = smem_u32(&As_h[0][ar][ac]);
    const u32 a_l_dst = smem_u32(&As_l[0][ar][ac]);
    const u32 b_h_dst = smem_u32(&Bs_h[0][bkr][bc]);
    const u32 b_l_dst = smem_u32(&Bs_l[0][bkr][bc]);

    float acc[4][4][4];
#pragma unroll
    for (int i = 0; i < 4; i++)
#pragma unroll
        for (int j = 0; j < 4; j++)
#pragma unroll
            for (int q = 0; q < 4; q++) acc[i][j][q] = 0.f;

    const int lr = (lane & 7) + ((lane >> 3) & 1) * 8;
    const int lc = (lane >> 4) * 8;
    u32 aaddr_h[4], aaddr_l[4], baddr_h[2], baddr_l[2];
#pragma unroll
    for (int mf = 0; mf < 4; mf++) {
        int r = wm * 64 + mf * 16 + lr;
        aaddr_h[mf] = smem_u32(&As_h[0][r][lc]);
        aaddr_l[mf] = smem_u32(&As_l[0][r][lc]);
    }
#pragma unroll
    for (int g = 0; g < 2; g++) {
        int n = wn * 32 + g * 16 + lc;
        baddr_h[g] = smem_u32(&Bs_h[0][lr][n]);
        baddr_l[g] = smem_u32(&Bs_l[0][lr][n]);
    }

    auto load_stage = [&](int buf, int k0) {
        if (k0 < ke) {
            cp16(a_h_dst + buf * ABUF, Ah + a_base + k0);
            cp16(a_l_dst + buf * ABUF, Al + a_base + k0);
            cp16(b_h_dst + buf * BBUF, Bh + (size_t)(k0 + bkr) * 256 + col0 + bc);
            cp16(b_l_dst + buf * BBUF, Bl + (size_t)(k0 + bkr) * 256 + col0 + bc);
        }
        asm volatile("cp.async.commit_group;");
    };

    load_stage(0, kb);
    load_stage(1, kb + 16);

    int buf = 0;
    for (int k0 = kb; k0 < ke; k0 += 16, buf ^= 1) {
        asm volatile("cp.async.wait_group 1;");
        __syncthreads();

        u32 a_h[4][4], a_l[4][4], b_h[4][2], b_l[4][2];
#pragma unroll
        for (int mf = 0; mf < 4; mf++) {
            ldsm_x4(a_h[mf], aaddr_h[mf] + buf * ABUF);
            ldsm_x4(a_l[mf], aaddr_l[mf] + buf * ABUF);
        }
#pragma unroll
        for (int g = 0; g < 2; g++) {
            u32 t[4];
            ldsm_x4_t(t, baddr_h[g] + buf * BBUF);
            b_h[2*g][0] = t[0]; b_h[2*g][1] = t[1];
            b_h[2*g+1][0] = t[2]; b_h[2*g+1][1] = t[3];
            ldsm_x4_t(t, baddr_l[g] + buf * BBUF);
            b_l[2*g][0] = t[0]; b_l[2*g][1] = t[1];
            b_l[2*g+1][0] = t[2]; b_l[2*g+1][1] = t[3];
        }
#pragma unroll
        for (int mf = 0; mf < 4; mf++)
#pragma unroll
            for (int nf = 0; nf < 4; nf++) {
                mma16816(acc[mf][nf], a_h[mf], b_h[nf]);
                mma16816(acc[mf][nf], a_h[mf], b_l[nf]);
                mma16816(acc[mf][nf], a_l[mf], b_h[nf]);
            }
        __syncthreads();
        load_stage(buf, k0 + 32);
    }

    const int er = lane >> 2, ec = (lane & 3) * 2;
    float* Cz = (MODE == 0) ? C + (size_t)blockIdx.z * ZSZ : C;
#pragma unroll
    for (int mf = 0; mf < 4; mf++)
#pragma unroll
        for (int nf = 0; nf < 4; nf++) {
            int r = row0 + wm * 64 + mf * 16 + er;
            int c = col0 + wn * 32 + nf * 8 + ec;
            if (MODE == 0) {
                float* p0 = &Cz[(size_t)r * 256 + c];
                float* p1 = &Cz[(size_t)(r + 8) * 256 + c];
                p0[0] = acc[mf][nf][0]; p0[1] = acc[mf][nf][1];
                p1[0] = acc[mf][nf][2]; p1[1] = acc[mf][nf][3];
            } else {
                float bv0 = bias[c], bv1 = bias[c + 1];
#pragma unroll
                for (int half = 0; half < 2; half++) {
                    int rr = r + half * 8;
                    float v0 = acc[mf][nf][half * 2]     + bv0;
                    float v1 = acc[mf][nf][half * 2 + 1] + bv1;
                    v0 = v0 > 0.f ? v0 : NEG_SLOPE * v0;
                    v1 = v1 > 0.f ? v1 : NEG_SLOPE * v1;
                    if (MODE == 1) {
                        size_t p = (size_t)rr * 256 + c;
                        *(__half2*)&((__half*)oh)[p] = __floats2half2_rn(v0, v1);
                    } else {
                        int b = rr / MACH, m = rr - b * MACH;
                        size_t p = (size_t)b * KP0 + (size_t)m * (HID + FEA) + c;
                        __nv_bfloat16 h0, l0, h1, l1;
                        split2(v0, &h0, &l0);
                        split2(v1, &h1, &l1);
                        *(__nv_bfloat162*)&oh[p] = __nv_bfloat162(h0, h1);
                        *(__nv_bfloat162*)&ol[p] = __nv_bfloat162(l0, l1);
                    }
                }
            }
        }
}

// ---------------- split-K reduce + bias + leaky + bf16 split -----------------
template<int S>
__global__ void k_epi(const float* __restrict__ zp, const float* __restrict__ bias,
                      __nv_bfloat16* __restrict__ zh, __nv_bfloat16* __restrict__ zl) {
    size_t i = (size_t)blockIdx.x * 256 + threadIdx.x;
    float v = bias[i & (HID - 1)];
#pragma unroll
    for (int s = 0; s < S; s++) v += zp[s * ZSZ + i];
    v = v > 0.f ? v : NEG_SLOPE * v;
    split2(v, &zh[i], &zl[i]);
}

// ---------------- final: reduce + bias + leaky + head GEMV -------------------
__global__ __launch_bounds__(256)
void k_epihead(const float* __restrict__ zp, const float* __restrict__ bias,
               const float* __restrict__ Wo, const float* __restrict__ bo,
               float* __restrict__ out) {
    __shared__ float zrow[HID];
    int b = blockIdx.x, t = threadIdx.x;
    size_t i = (size_t)b * HID + t;
    float v = bias[t];
#pragma unroll
    for (int s = 0; s < 4; s++) v += zp[s * ZSZ + i];
    v = v > 0.f ? v : NEG_SLOPE * v;
    zrow[t] = v;
    __syncthreads();
    if (t < 128) {
        int j = t >> 5, lane = t & 31;
        float a = 0.f;
#pragma unroll
        for (int q = 0; q < 8; q++) {
            int k = lane + q * 32;
            a = fmaf(zrow[k], Wo[k * 4 + j], a);
        }
#pragma unroll
        for (int o = 16; o > 0; o >>= 1)
            a += __shfl_down_sync(0xffffffffu, a, o);
        if (lane == 0) out[(size_t)b * 4 + j] = a + bo[j];
    }
}

// ---------------- x -> flat (split) + tail padding ---------------------------
#define NNFEA ((long long)NN * FEA)
__global__ void k_xpad(const float* __restrict__ x,
                       __nv_bfloat16* __restrict__ fh, __nv_bfloat16* __restrict__ fl) {
    long long idx = (long long)blockIdx.x * 256 + threadIdx.x;
    if (idx < NNFEA) {
        int i = (int)(idx / FEA);
        int j = (int)(idx - (long long)i * FEA);
        int b = i / MACH, m = i - b * MACH;
        size_t p = (size_t)b * KP0 + (size_t)m * (HID + FEA) + HID + j;
        split2(x[idx], &fh[p], &fl[p]);
    } else {
        long long q = idx - NNFEA;
        int b = (int)(q >> 3), j = (int)(q & 7);
        size_t p = (size_t)b * KP0 + MLP_IN + j;
        fh[p] = __float2bfloat16(0.f);
        fl[p] = __float2bfloat16(0.f);
    }
}

// ---------------- launcher ---------------------------------------------------
extern "C" void kernel_launch(void* const* d_in, const int* in_sizes, int n_in,
                              void* d_out, int out_size) {
    const float* x   = (const float*)d_in[0];
    const void*  ei  = d_in[1];
    const float* ew  = (const float*)d_in[2];
    const float* W1  = (const float*)d_in[3];
    const float* b1  = (const float*)d_in[4];
    const float* W2  = (const float*)d_in[5];
    const float* b2  = (const float*)d_in[6];
    const float* Wf0 = (const float*)d_in[7];
    const float* bf0 = (const float*)d_in[8];
    const float* Wf1 = (const float*)d_in[9];
    const float* bf1 = (const float*)d_in[10];
    const float* Wf2 = (const float*)d_in[11];
    const float* bf2 = (const float*)d_in[12];
    const float* Wo  = (const float*)d_in[13];
    const float* bo  = (const float*)d_in[14];
    float* out = (float*)d_out;

    float* gf = nullptr; int* gi = nullptr; __nv_bfloat16* gh = nullptr;
    cudaGetSymbolAddress((void**)&gf, g_f);
    cudaGetSymbolAddress((void**)&gi, g_i);
    cudaGetSymbolAddress((void**)&gh, g_h);

    float* dinv = gf + OFF_DINV;
    float* sew  = gf + OFF_SEW;
    float* zp   = gf + OFF_ZP;
    int*   cnt  = gi;
    int*   src  = gi + NN;

    __nv_bfloat16 *xh = gh + OFF_XH,  *xl = gh + OFF_XL;
    __nv_bfloat16 *hh = gh + OFF_HH;
    __nv_bfloat16 *ah = gh + OFF_AH,  *al = gh + OFF_AL;
    __nv_bfloat16 *fh = gh + OFF_FH,  *fl = gh + OFF_FL;
    __nv_bfloat16 *w1h = gh + OFF_W1H, *w1l = gh + OFF_W1L;
    __nv_bfloat16 *w2h = gh + OFF_W2H, *w2l = gh + OFF_W2L;
    __nv_bfloat16 *f0h = gh + OFF_F0H, *f0l = gh + OFF_F0L;
    __nv_bfloat16 *f1h = gh + OFF_F1H, *f1l = gh + OFF_F1L;
    __nv_bfloat16 *f2h = gh + OFF_F2H, *f2l = gh + OFF_F2L;
    __nv_bfloat16 *zh = gh + OFF_ZH,   *zl = gh + OFF_ZL;

    const int NB_N = (NN + 255) / 256;
    const int NB_E = (EE + 255) / 256;

    // 4th launch is the profiled one: k_gather_x (verify float4 speedup)
    k_init<<<NB_N, 256>>>(ei, cnt);                                    // 1
    k_degfill<<<NB_E, 256>>>(ei, ew, cnt, src, sew);                   // 2
    k_dinv<<<NN / 8, 256>>>(sew, cnt, dinv);                           // 3
    k_gather_x<<<NN / 16, 256>>>((const float4*)x, dinv, cnt, src, sew,
                                 xh, xl);                              // 4 <- profiled
    k_cvt_all<<<CVT_ROWS, 256>>>(W1, W2, Wf0, Wf1, Wf2, gh);           // 5

    // conv1: h = leaky(aggx @ W1 + b1) -> fp16
    bmma<1><<<dim3(2, NN / 128, 1), 256>>>(xh, xl, w1h, w1l,
                                           nullptr, b1, hh, nullptr, KP1, KP1);

    // conv2: flat[h-part] = leaky(agg(h) @ W2 + b2)
    k_gather_h<<<NN / 8, 256>>>((const uint4*)hh, dinv, cnt, src, sew, ah, al);
    bmma<2><<<dim3(2, NN / 128, 1), 256>>>(ah, al, w2h, w2l,
                                           nullptr, b2, fh, fl, HID, HID);

    // flat[x-part] = x ; pad tail
    k_xpad<<<(int)((NNFEA + BATCH * 8) / 256), 256>>>(x, fh, fl);

    // MLP0: split-K=8 -> partial stores -> reduce epi
    bmma<0><<<dim3(2, BATCH / 128, 8), 256>>>(fh, fl, f0h, f0l,
                                              zp, nullptr, nullptr, nullptr, KP0, 880);
    k_epi<8><<<(int)(ZSZ / 256), 256>>>(zp, bf0, zh, zl);

    // MLP1: split-K=4
    bmma<0><<<dim3(2, BATCH / 128, 4), 256>>>(zh, zl, f1h, f1l,
                                              zp, nullptr, nullptr, nullptr, HID, 64);
    k_epi<4><<<(int)(ZSZ / 256), 256>>>(zp, bf1, zh, zl);

    // MLP2: split-K=4 -> fused reduce + head
    bmma<0><<<dim3(2, BATCH / 128, 4), 256>>>(zh, zl, f2h, f2l,
                                              zp, nullptr, nullptr, nullptr, HID, 64);
    k_epihead<<<BATCH, 256>>>(zp, bf2, Wo, bo, out);
}

// round 11
// speedup vs baseline: 6.7335x; 1.5863x over previous
#include <cuda_runtime.h>
#include <cuda_fp16.h>
#include <cstdint>

typedef unsigned int u32;

#define NN 45056
#define EE 720896
#define FEA 60
#define HID 256
#define MACH 22
#define BATCH 2048
#define CAP 96
#define MLP_IN 6952
#define KP0 6960
#define KP1 64
#define NEG_SLOPE 0.01f

// ---------------- fp32 scratch ----------------------------------------------
static constexpr size_t ZSZ  = (size_t)BATCH * HID;
static constexpr size_t OFF_DINV = 0;
static constexpr size_t OFF_SEW  = OFF_DINV + (size_t)NN;
static constexpr size_t OFF_ZP   = OFF_SEW  + (size_t)NN * CAP;
static constexpr size_t FTOTAL   = OFF_ZP   + 8 * ZSZ;
__device__ float g_f[FTOTAL];

// ---------------- fp16 scratch ------------------------------------------------
static constexpr size_t XSZ  = (size_t)NN * KP1;
static constexpr size_t HSZ  = (size_t)NN * HID;
static constexpr size_t FSZ  = (size_t)BATCH * KP0;
static constexpr size_t W1SZ = (size_t)KP1 * HID;
static constexpr size_t W2SZ = (size_t)HID * HID;
static constexpr size_t F0SZ = (size_t)KP0 * HID;
static constexpr size_t OFF_XP  = 0;                 // x padded fp16 [NN,64]
static constexpr size_t OFF_XQ  = OFF_XP + XSZ;      // aggregated x   [NN,64]
static constexpr size_t OFF_H   = OFF_XQ + XSZ;      // h fp16         [NN,256]
static constexpr size_t OFF_A   = OFF_H  + HSZ;      // agg h          [NN,256]
static constexpr size_t OFF_F   = OFF_A  + HSZ;      // flat           [BATCH,KP0]
static constexpr size_t OFF_W1  = OFF_F  + FSZ;
static constexpr size_t OFF_W2  = OFF_W1 + W1SZ;
static constexpr size_t OFF_F0  = OFF_W2 + W2SZ;
static constexpr size_t OFF_F1  = OFF_F0 + F0SZ;
static constexpr size_t OFF_F2  = OFF_F1 + W2SZ;
static constexpr size_t OFF_Z   = OFF_F2 + W2SZ;
static constexpr size_t HTOTAL  = OFF_Z  + ZSZ;
__device__ __align__(16) __half g_h[HTOTAL];

__device__ int g_i[(size_t)NN * (CAP + 1)];
__device__ int g_is32;

// ---------------- helpers ----------------------------------------------------
__device__ __forceinline__ u32 smem_u32(const void* p) {
    return (u32)__cvta_generic_to_shared(p);
}
__device__ __forceinline__ void cp16(u32 dst, const void* src) {
    asm volatile("cp.async.cg.shared.global [%0], [%1], 16;" :: "r"(dst), "l"(src));
}
__device__ __forceinline__ void ldsm_x4(u32* r, u32 a) {
    asm volatile("ldmatrix.sync.aligned.m8n8.x4.shared.b16 {%0,%1,%2,%3}, [%4];"
        : "=r"(r[0]), "=r"(r[1]), "=r"(r[2]), "=r"(r[3]) : "r"(a));
}
__device__ __forceinline__ void ldsm_x4_t(u32* r, u32 a) {
    asm volatile("ldmatrix.sync.aligned.m8n8.x4.trans.shared.b16 {%0,%1,%2,%3}, [%4];"
        : "=r"(r[0]), "=r"(r[1]), "=r"(r[2]), "=r"(r[3]) : "r"(a));
}
__device__ __forceinline__ void mmaf16(float* c, const u32* a, const u32* b) {
    asm volatile(
        "mma.sync.aligned.m16n8k16.row.col.f32.f16.f16.f32 "
        "{%0,%1,%2,%3}, {%4,%5,%6,%7}, {%8,%9}, {%0,%1,%2,%3};"
        : "+f"(c[0]), "+f"(c[1]), "+f"(c[2]), "+f"(c[3])
        : "r"(a[0]), "r"(a[1]), "r"(a[2]), "r"(a[3]), "r"(b[0]), "r"(b[1]));
}
__device__ __forceinline__ void h8_to_f8(uint4 v, float* f) {
    float2 p;
    p = __half22float2(*(__half2*)&v.x); f[0] = p.x; f[1] = p.y;
    p = __half22float2(*(__half2*)&v.y); f[2] = p.x; f[3] = p.y;
    p = __half22float2(*(__half2*)&v.z); f[4] = p.x; f[5] = p.y;
    p = __half22float2(*(__half2*)&v.w); f[6] = p.x; f[7] = p.y;
}
__device__ __forceinline__ uint4 f8_to_h8(const float* f) {
    uint4 o;
    *(__half2*)&o.x = __floats2half2_rn(f[0], f[1]);
    *(__half2*)&o.y = __floats2half2_rn(f[2], f[3]);
    *(__half2*)&o.z = __floats2half2_rn(f[4], f[5]);
    *(__half2*)&o.w = __floats2half2_rn(f[6], f[7]);
    return o;
}

// ---------------- init: detect dtype + zero cnt + x->fp16 pad ----------------
__global__ void k_init(const void* __restrict__ ei, const float* __restrict__ x,
                       int* __restrict__ cnt, __half* __restrict__ xp) {
    size_t idx = (size_t)blockIdx.x * 256 + threadIdx.x;   // NN*64 threads
    int i = (int)(idx >> 6), k = (int)(idx & 63);
    xp[idx] = __float2half((k < FEA) ? x[(size_t)i * FEA + k] : 0.f);
    if (idx < NN) cnt[idx] = 0;
    if (idx == 0) {
        const long long* p = (const long long*)ei;
        int is32 = 0;
        for (int q = 0; q < 64; q++) {
            long long v = p[q];
            if (v < 0 || v >= NN) { is32 = 1; break; }
        }
        g_is32 = is32;
    }
}
__device__ __forceinline__ int edge_idx(const void* ei, int half, int e, int is32) {
    if (is32) return ((const int*)ei)[(size_t)half * EE + e];
    return (int)((const long long*)ei)[(size_t)half * EE + e];
}
__global__ void k_degfill(const void* __restrict__ ei, const float* __restrict__ ew,
                          int* __restrict__ cnt,
                          int* __restrict__ src, float* __restrict__ sew) {
    int e = blockIdx.x * 256 + threadIdx.x;
    if (e >= EE) return;
    int is32 = g_is32;
    int r = edge_idx(ei, 0, e, is32);
    int c = edge_idx(ei, 1, e, is32);
    if ((unsigned)r >= (unsigned)NN || (unsigned)c >= (unsigned)NN) return;
    float w = ew[e];
    int p = atomicAdd(&cnt[c], 1);
    if (p < CAP) {
        src[c * CAP + p] = r;
        sew[c * CAP + p] = w;
    }
}
__global__ void k_dinv(const float* __restrict__ sew, const int* __restrict__ cnt,
                       float* __restrict__ dinv) {
    int node = (blockIdx.x * 256 + threadIdx.x) >> 5;
    int lane = threadIdx.x & 31;
    if (node >= NN) return;
    int c = cnt[node]; if (c > CAP) c = CAP;
    float s = 0.f;
    for (int e = lane; e < c; e += 32) s += sew[node * CAP + e];
#pragma unroll
    for (int o = 16; o; o >>= 1) s += __shfl_xor_sync(0xffffffffu, s, o);
    if (lane == 0) dinv[node] = rsqrtf(s + 1.0f);
}

// ---------------- merged weight conversion (fp16 single) ---------------------
#define CVT_ROWS 7792
__global__ void k_cvt_all(const float* __restrict__ W1, const float* __restrict__ W2,
                          const float* __restrict__ Wf0, const float* __restrict__ Wf1,
                          const float* __restrict__ Wf2,
                          __half* __restrict__ gh_base) {
    int r = blockIdx.x, t = threadIdx.x;
    float v; size_t off;
    __half* d;
    if (r < 64) {
        v = (r < FEA) ? W1[(size_t)r * 256 + t] : 0.f;
        d = gh_base + OFF_W1; off = (size_t)r * 256 + t;
    } else if (r < 320) {
        int k = r - 64;
        v = W2[(size_t)k * 256 + t];
        d = gh_base + OFF_W2; off = (size_t)k * 256 + t;
    } else if (r < 7280) {
        int k = r - 320;
        v = (k < MLP_IN) ? Wf0[(size_t)k * 256 + t] : 0.f;
        d = gh_base + OFF_F0; off = (size_t)k * 256 + t;
    } else if (r < 7536) {
        int k = r - 7280;
        v = Wf1[(size_t)k * 256 + t];
        d = gh_base + OFF_F1; off = (size_t)k * 256 + t;
    } else {
        int k = r - 7536;
        v = Wf2[(size_t)k * 256 + t];
        d = gh_base + OFF_F2; off = (size_t)k * 256 + t;
    }
    d[off] = __float2half(v);
}

// ---------------- gather x (fp16 uint4, 8 lanes/node, 32 nodes/block) --------
__global__ __launch_bounds__(256)
void k_gather_x(const uint4* __restrict__ xp4, const float* __restrict__ dinv,
                const int* __restrict__ cnt, const int* __restrict__ src,
                const float* __restrict__ sew, uint4* __restrict__ xq4) {
    int sub = threadIdx.x >> 3, lane = threadIdx.x & 7;
    int i = blockIdx.x * 32 + sub;
    __shared__ int   ssrc[32][CAP];
    __shared__ float snrm[32][CAP];
    int c = cnt[i]; if (c > CAP) c = CAP;
    float di = dinv[i];
    for (int e = lane; e < c; e += 8) {
        int s = src[i * CAP + e];
        ssrc[sub][e] = s * 8;                  // uint4 row offset (64 halves / 8)
        snrm[sub][e] = dinv[s] * sew[i * CAP + e] * di;
    }
    __syncwarp();

    float acc[8];
    {
        float f[8];
        h8_to_f8(xp4[i * 8 + lane], f);
        float s = di * di;
#pragma unroll
        for (int q = 0; q < 8; q++) acc[q] = s * f[q];
    }
#pragma unroll 2
    for (int e = 0; e < c; e++) {
        float w = snrm[sub][e];
        float f[8];
        h8_to_f8(xp4[ssrc[sub][e] + lane], f);
#pragma unroll
        for (int q = 0; q < 8; q++) acc[q] = fmaf(w, f[q], acc[q]);
    }
    xq4[i * 8 + lane] = f8_to_h8(acc);
}

// ---------------- gather h (fp16 uint4, 1 warp/node, 8 nodes/block) ----------
__global__ __launch_bounds__(256)
void k_gather_h(const uint4* __restrict__ h4,
                const float* __restrict__ dinv, const int* __restrict__ cnt,
                const int* __restrict__ src, const float* __restrict__ sew,
                uint4* __restrict__ a4) {
    int sub = threadIdx.x >> 5, lane = threadIdx.x & 31;
    int i = blockIdx.x * 8 + sub;
    __shared__ int   ssrc[8][CAP];
    __shared__ float snrm[8][CAP];
    int c = cnt[i]; if (c > CAP) c = CAP;
    float di = dinv[i];
    for (int e = lane; e < c; e += 32) {
        int s = src[i * CAP + e];
        ssrc[sub][e] = s * 32;                 // uint4 row offset (256 halves / 8)
        snrm[sub][e] = dinv[s] * sew[i * CAP + e] * di;
    }
    __syncwarp();

    float acc[8];
    {
        float f[8];
        h8_to_f8(h4[i * 32 + lane], f);
        float s = di * di;
#pragma unroll
        for (int q = 0; q < 8; q++) acc[q] = s * f[q];
    }
#pragma unroll 2
    for (int e = 0; e < c; e++) {
        float w = snrm[sub][e];
        float f[8];
        h8_to_f8(h4[ssrc[sub][e] + lane], f);
#pragma unroll
        for (int q = 0; q < 8; q++) acc[q] = fmaf(w, f[q], acc[q]);
    }
    a4[i * 32 + lane] = f8_to_h8(acc);
}

// ---------------- fp16 tensor-core GEMM (cp.async double-buffered) -----------
// C/out[M,256] = A[M,K] @ B[K,256]
// MODE 0: fp32 partial store to C + blockIdx.z*ZSZ (split-K)
// MODE 1: bias + leaky + fp16 store, linear stride 256 (conv1 -> h)
// MODE 2: bias + leaky + fp16 store, flat-mapped (conv2 -> flat)
template<int MODE>
__global__ __launch_bounds__(256)
void bmma(const __half* __restrict__ A, const __half* __restrict__ B,
          float* __restrict__ C, const float* __restrict__ bias,
          __half* __restrict__ o, int K, int kstep) {
    __shared__ __align__(16) __half As[2][128][24];
    __shared__ __align__(16) __half Bs[2][16][136];
    constexpr u32 ABUF = 128 * 24 * 2;
    constexpr u32 BBUF = 16 * 136 * 2;

    const int tid = threadIdx.x;
    const int lane = tid & 31, warp = tid >> 5;
    const int wm = warp >> 2, wn = warp & 3;
    const int row0 = blockIdx.y * 128, col0 = blockIdx.x * 128;
    const int kb = blockIdx.z * kstep;
    const int ke = min(kb + kstep, K);

    const int ar = tid >> 1, ac = (tid & 1) * 8;
    const int bkr = tid >> 4, bc = (tid & 15) * 8;
    const size_t a_base = (size_t)(row0 + ar) * K + ac;

    const u32 a_dst = smem_u32(&As[0][ar][ac]);
    const u32 b_dst = smem_u32(&Bs[0][bkr][bc]);

    float acc[4][4][4];
#pragma unroll
    for (int i = 0; i < 4; i++)
#pragma unroll
        for (int j = 0; j < 4; j++)
#pragma unroll
            for (int q = 0; q < 4; q++) acc[i][j][q] = 0.f;

    const int lr = (lane & 7) + ((lane >> 3) & 1) * 8;
    const int lc = (lane >> 4) * 8;
    u32 aaddr[4], baddr[2];
#pragma unroll
    for (int mf = 0; mf < 4; mf++)
        aaddr[mf] = smem_u32(&As[0][wm * 64 + mf * 16 + lr][lc]);
#pragma unroll
    for (int g = 0; g < 2; g++)
        baddr[g] = smem_u32(&Bs[0][lr][wn * 32 + g * 16 + lc]);

    auto load_stage = [&](int buf, int k0) {
        if (k0 < ke) {
            cp16(a_dst + buf * ABUF, A + a_base + k0);
            cp16(b_dst + buf * BBUF, B + (size_t)(k0 + bkr) * 256 + col0 + bc);
        }
        asm volatile("cp.async.commit_group;");
    };

    load_stage(0, kb);
    load_stage(1, kb + 16);

    int buf = 0;
    for (int k0 = kb; k0 < ke; k0 += 16, buf ^= 1) {
        asm volatile("cp.async.wait_group 1;");
        __syncthreads();

        u32 a[4][4], b[4][2];
#pragma unroll
        for (int mf = 0; mf < 4; mf++)
            ldsm_x4(a[mf], aaddr[mf] + buf * ABUF);
#pragma unroll
        for (int g = 0; g < 2; g++) {
            u32 t[4];
            ldsm_x4_t(t, baddr[g] + buf * BBUF);
            b[2*g][0] = t[0]; b[2*g][1] = t[1];
            b[2*g+1][0] = t[2]; b[2*g+1][1] = t[3];
        }
#pragma unroll
        for (int mf = 0; mf < 4; mf++)
#pragma unroll
            for (int nf = 0; nf < 4; nf++)
                mmaf16(acc[mf][nf], a[mf], b[nf]);
        __syncthreads();
        load_stage(buf, k0 + 32);
    }

    const int er = lane >> 2, ec = (lane & 3) * 2;
    float* Cz = (MODE == 0) ? C + (size_t)blockIdx.z * ZSZ : C;
#pragma unroll
    for (int mf = 0; mf < 4; mf++)
#pragma unroll
        for (int nf = 0; nf < 4; nf++) {
            int r = row0 + wm * 64 + mf * 16 + er;
            int c = col0 + wn * 32 + nf * 8 + ec;
            if (MODE == 0) {
                float* p0 = &Cz[(size_t)r * 256 + c];
                float* p1 = &Cz[(size_t)(r + 8) * 256 + c];
                p0[0] = acc[mf][nf][0]; p0[1] = acc[mf][nf][1];
                p1[0] = acc[mf][nf][2]; p1[1] = acc[mf][nf][3];
            } else {
                float bv0 = bias[c], bv1 = bias[c + 1];
#pragma unroll
                for (int half = 0; half < 2; half++) {
                    int rr = r + half * 8;
                    float v0 = acc[mf][nf][half * 2]     + bv0;
                    float v1 = acc[mf][nf][half * 2 + 1] + bv1;
                    v0 = v0 > 0.f ? v0 : NEG_SLOPE * v0;
                    v1 = v1 > 0.f ? v1 : NEG_SLOPE * v1;
                    size_t p;
                    if (MODE == 1) {
                        p = (size_t)rr * 256 + c;
                    } else {
                        int b = rr / MACH, m = rr - b * MACH;
                        p = (size_t)b * KP0 + (size_t)m * (HID + FEA) + c;
                    }
                    *(__half2*)&o[p] = __floats2half2_rn(v0, v1);
                }
            }
        }
}

// ---------------- split-K reduce + bias + leaky + fp16 store -----------------
template<int S>
__global__ void k_epi(const float* __restrict__ zp, const float* __restrict__ bias,
                      __half* __restrict__ z) {
    size_t i = (size_t)blockIdx.x * 256 + threadIdx.x;
    float v = bias[i & (HID - 1)];
#pragma unroll
    for (int s = 0; s < S; s++) v += zp[s * ZSZ + i];
    v = v > 0.f ? v : NEG_SLOPE * v;
    z[i] = __float2half(v);
}

// ---------------- final: reduce + bias + leaky + head GEMV -------------------
__global__ __launch_bounds__(256)
void k_epihead(const float* __restrict__ zp, const float* __restrict__ bias,
               const float* __restrict__ Wo, const float* __restrict__ bo,
               float* __restrict__ out) {
    __shared__ float zrow[HID];
    int b = blockIdx.x, t = threadIdx.x;
    size_t i = (size_t)b * HID + t;
    float v = bias[t];
#pragma unroll
    for (int s = 0; s < 4; s++) v += zp[s * ZSZ + i];
    v = v > 0.f ? v : NEG_SLOPE * v;
    zrow[t] = v;
    __syncthreads();
    if (t < 128) {
        int j = t >> 5, lane = t & 31;
        float a = 0.f;
#pragma unroll
        for (int q = 0; q < 8; q++) {
            int k = lane + q * 32;
            a = fmaf(zrow[k], Wo[k * 4 + j], a);
        }
#pragma unroll
        for (int o = 16; o > 0; o >>= 1)
            a += __shfl_down_sync(0xffffffffu, a, o);
        if (lane == 0) out[(size_t)b * 4 + j] = a + bo[j];
    }
}

// ---------------- x -> flat (fp16) + tail padding ----------------------------
#define NNFEA ((long long)NN * FEA)
__global__ void k_xpad(const float* __restrict__ x, __half* __restrict__ f) {
    long long idx = (long long)blockIdx.x * 256 + threadIdx.x;
    if (idx < NNFEA) {
        int i = (int)(idx / FEA);
        int j = (int)(idx - (long long)i * FEA);
        int b = i / MACH, m = i - b * MACH;
        f[(size_t)b * KP0 + (size_t)m * (HID + FEA) + HID + j] = __float2half(x[idx]);
    } else {
        long long q = idx - NNFEA;
        int b = (int)(q >> 3), j = (int)(q & 7);
        f[(size_t)b * KP0 + MLP_IN + j] = __float2half(0.f);
    }
}

// ---------------- launcher ---------------------------------------------------
extern "C" void kernel_launch(void* const* d_in, const int* in_sizes, int n_in,
                              void* d_out, int out_size) {
    const float* x   = (const float*)d_in[0];
    const void*  ei  = d_in[1];
    const float* ew  = (const float*)d_in[2];
    const float* W1  = (const float*)d_in[3];
    const float* b1  = (const float*)d_in[4];
    const float* W2  = (const float*)d_in[5];
    const float* b2  = (const float*)d_in[6];
    const float* Wf0 = (const float*)d_in[7];
    const float* bf0 = (const float*)d_in[8];
    const float* Wf1 = (const float*)d_in[9];
    const float* bf1 = (const float*)d_in[10];
    const float* Wf2 = (const float*)d_in[11];
    const float* bf2 = (const float*)d_in[12];
    const float* Wo  = (const float*)d_in[13];
    const float* bo  = (const float*)d_in[14];
    float* out = (float*)d_out;

    float* gf = nullptr; int* gi = nullptr; __half* gh = nullptr;
    cudaGetSymbolAddress((void**)&gf, g_f);
    cudaGetSymbolAddress((void**)&gi, g_i);
    cudaGetSymbolAddress((void**)&gh, g_h);

    float* dinv = gf + OFF_DINV;
    float* sew  = gf + OFF_SEW;
    float* zp   = gf + OFF_ZP;
    int*   cnt  = gi;
    int*   src  = gi + NN;

    __half *xp = gh + OFF_XP, *xq = gh + OFF_XQ;
    __half *h  = gh + OFF_H,  *a  = gh + OFF_A;
    __half *f  = gh + OFF_F;
    __half *w1 = gh + OFF_W1, *w2 = gh + OFF_W2;
    __half *f0 = gh + OFF_F0, *f1 = gh + OFF_F1, *f2 = gh + OFF_F2;
    __half *z  = gh + OFF_Z;

    const int NB_E = (EE + 255) / 256;

    // slot 4 (profiled) = k_gather_x, to verify the fp16-row prediction
    k_init<<<(int)(XSZ / 256), 256>>>(ei, x, cnt, xp);                 // 1
    k_degfill<<<NB_E, 256>>>(ei, ew, cnt, src, sew);                   // 2
    k_dinv<<<NN / 8, 256>>>(sew, cnt, dinv);                           // 3
    k_gather_x<<<NN / 32, 256>>>((const uint4*)xp, dinv, cnt, src, sew,
                                 (uint4*)xq);                          // 4 <- profiled
    k_cvt_all<<<CVT_ROWS, 256>>>(W1, W2, Wf0, Wf1, Wf2, gh);           // 5

    // conv1: h = leaky(aggx @ W1 + b1)
    bmma<1><<<dim3(2, NN / 128, 1), 256>>>(xq, w1, nullptr, b1, h, KP1, KP1);

    // conv2: flat[h-part] = leaky(agg(h) @ W2 + b2)
    k_gather_h<<<NN / 8, 256>>>((const uint4*)h, dinv, cnt, src, sew, (uint4*)a);
    bmma<2><<<dim3(2, NN / 128, 1), 256>>>(a, w2, nullptr, b2, f, HID, HID);

    // flat[x-part] = x ; pad tail
    k_xpad<<<(int)((NNFEA + BATCH * 8) / 256), 256>>>(x, f);

    // MLP0: split-K=8 -> partial stores -> reduce epi
    bmma<0><<<dim3(2, BATCH / 128, 8), 256>>>(f, f0, zp, nullptr, nullptr, KP0, 880);
    k_epi<8><<<(int)(ZSZ / 256), 256>>>(zp, bf0, z);

    // MLP1: split-K=4
    bmma<0><<<dim3(2, BATCH / 128, 4), 256>>>(z, f1, zp, nullptr, nullptr, HID, 64);
    k_epi<4><<<(int)(ZSZ / 256), 256>>>(zp, bf1, z);

    // MLP2: split-K=4 -> fused reduce + head
    bmma<0><<<dim3(2, BATCH / 128, 4), 256>>>(z, f2, zp, nullptr, nullptr, HID, 64);
    k_epihead<<<BATCH, 256>>>(zp, bf2, Wo, bo, out);
}

// round 12
// speedup vs baseline: 7.2402x; 1.0752x over previous
#include <cuda_runtime.h>
#include <cuda_fp16.h>
#include <cstdint>

typedef unsigned int u32;

#define NN 45056
#define EE 720896
#define FEA 60
#define HID 256
#define MACH 22
#define BATCH 2048
#define CAP 96
#define MLP_IN 6952
#define KP0 6960
#define KP1 64
#define NEG_SLOPE 0.01f

// ---------------- fp32 scratch ----------------------------------------------
static constexpr size_t ZSZ  = (size_t)BATCH * HID;
static constexpr size_t OFF_DINV = 0;
static constexpr size_t OFF_ZP   = OFF_DINV + (size_t)NN;
static constexpr size_t FTOTAL   = OFF_ZP   + 8 * ZSZ;
__device__ float g_f[FTOTAL];

// ---------------- packed adjacency: (src, weight-bits) per slot --------------
__device__ __align__(16) int2 g_srcw[(size_t)NN * CAP];
__device__ int g_cnt[NN];
__device__ int g_is32;

// ---------------- fp16 scratch ------------------------------------------------
static constexpr size_t XSZ  = (size_t)NN * KP1;
static constexpr size_t HSZ  = (size_t)NN * HID;
static constexpr size_t FSZ  = (size_t)BATCH * KP0;
static constexpr size_t W1SZ = (size_t)KP1 * HID;
static constexpr size_t W2SZ = (size_t)HID * HID;
static constexpr size_t F0SZ = (size_t)KP0 * HID;
static constexpr size_t OFF_XP  = 0;
static constexpr size_t OFF_XQ  = OFF_XP + XSZ;
static constexpr size_t OFF_H   = OFF_XQ + XSZ;
static constexpr size_t OFF_A   = OFF_H  + HSZ;
static constexpr size_t OFF_F   = OFF_A  + HSZ;
static constexpr size_t OFF_W1  = OFF_F  + FSZ;
static constexpr size_t OFF_W2  = OFF_W1 + W1SZ;
static constexpr size_t OFF_F0  = OFF_W2 + W2SZ;
static constexpr size_t OFF_F1  = OFF_F0 + F0SZ;
static constexpr size_t OFF_F2  = OFF_F1 + W2SZ;
static constexpr size_t OFF_Z   = OFF_F2 + W2SZ;
static constexpr size_t HTOTAL  = OFF_Z  + ZSZ;
__device__ __align__(16) __half g_h[HTOTAL];

// ---------------- helpers ----------------------------------------------------
__device__ __forceinline__ u32 smem_u32(const void* p) {
    return (u32)__cvta_generic_to_shared(p);
}
__device__ __forceinline__ void cp16(u32 dst, const void* src) {
    asm volatile("cp.async.cg.shared.global [%0], [%1], 16;" :: "r"(dst), "l"(src));
}
__device__ __forceinline__ void ldsm_x4(u32* r, u32 a) {
    asm volatile("ldmatrix.sync.aligned.m8n8.x4.shared.b16 {%0,%1,%2,%3}, [%4];"
        : "=r"(r[0]), "=r"(r[1]), "=r"(r[2]), "=r"(r[3]) : "r"(a));
}
__device__ __forceinline__ void ldsm_x4_t(u32* r, u32 a) {
    asm volatile("ldmatrix.sync.aligned.m8n8.x4.trans.shared.b16 {%0,%1,%2,%3}, [%4];"
        : "=r"(r[0]), "=r"(r[1]), "=r"(r[2]), "=r"(r[3]) : "r"(a));
}
__device__ __forceinline__ void mmaf16(float* c, const u32* a, const u32* b) {
    asm volatile(
        "mma.sync.aligned.m16n8k16.row.col.f32.f16.f16.f32 "
        "{%0,%1,%2,%3}, {%4,%5,%6,%7}, {%8,%9}, {%0,%1,%2,%3};"
        : "+f"(c[0]), "+f"(c[1]), "+f"(c[2]), "+f"(c[3])
        : "r"(a[0]), "r"(a[1]), "r"(a[2]), "r"(a[3]), "r"(b[0]), "r"(b[1]));
}
__device__ __forceinline__ void h8_acc(uint4 v, float w, float* acc) {
    float2 p;
    p = __half22float2(*(__half2*)&v.x); acc[0] = fmaf(w, p.x, acc[0]); acc[1] = fmaf(w, p.y, acc[1]);
    p = __half22float2(*(__half2*)&v.y); acc[2] = fmaf(w, p.x, acc[2]); acc[3] = fmaf(w, p.y, acc[3]);
    p = __half22float2(*(__half2*)&v.z); acc[4] = fmaf(w, p.x, acc[4]); acc[5] = fmaf(w, p.y, acc[5]);
    p = __half22float2(*(__half2*)&v.w); acc[6] = fmaf(w, p.x, acc[6]); acc[7] = fmaf(w, p.y, acc[7]);
}
__device__ __forceinline__ void h8_scale(uint4 v, float s, float* acc) {
    float2 p;
    p = __half22float2(*(__half2*)&v.x); acc[0] = s * p.x; acc[1] = s * p.y;
    p = __half22float2(*(__half2*)&v.y); acc[2] = s * p.x; acc[3] = s * p.y;
    p = __half22float2(*(__half2*)&v.z); acc[4] = s * p.x; acc[5] = s * p.y;
    p = __half22float2(*(__half2*)&v.w); acc[6] = s * p.x; acc[7] = s * p.y;
}
__device__ __forceinline__ uint4 f8_to_h8(const float* f) {
    uint4 o;
    *(__half2*)&o.x = __floats2half2_rn(f[0], f[1]);
    *(__half2*)&o.y = __floats2half2_rn(f[2], f[3]);
    *(__half2*)&o.z = __floats2half2_rn(f[4], f[5]);
    *(__half2*)&o.w = __floats2half2_rn(f[6], f[7]);
    return o;
}

// ---------------- init: detect dtype + zero cnt + x->fp16 pad ----------------
__global__ void k_init(const void* __restrict__ ei, const float* __restrict__ x,
                       int* __restrict__ cnt, __half* __restrict__ xp) {
    size_t idx = (size_t)blockIdx.x * 256 + threadIdx.x;   // NN*64 threads
    int i = (int)(idx >> 6), k = (int)(idx & 63);
    xp[idx] = __float2half((k < FEA) ? x[(size_t)i * FEA + k] : 0.f);
    if (idx < NN) cnt[idx] = 0;
    if (idx == 0) {
        const long long* p = (const long long*)ei;
        int is32 = 0;
        for (int q = 0; q < 64; q++) {
            long long v = p[q];
            if (v < 0 || v >= NN) { is32 = 1; break; }
        }
        g_is32 = is32;
    }
}
__device__ __forceinline__ int edge_idx(const void* ei, int half, int e, int is32) {
    if (is32) return ((const int*)ei)[(size_t)half * EE + e];
    return (int)((const long long*)ei)[(size_t)half * EE + e];
}
// packed fill: single 8B store per edge
__global__ void k_degfill(const void* __restrict__ ei, const float* __restrict__ ew,
                          int* __restrict__ cnt, int2* __restrict__ srcw) {
    int e = blockIdx.x * 256 + threadIdx.x;
    if (e >= EE) return;
    int is32 = g_is32;
    int r = edge_idx(ei, 0, e, is32);
    int c = edge_idx(ei, 1, e, is32);
    if ((unsigned)r >= (unsigned)NN || (unsigned)c >= (unsigned)NN) return;
    float w = ew[e];
    int p = atomicAdd(&cnt[c], 1);
    if (p < CAP) srcw[(size_t)c * CAP + p] = make_int2(r, __float_as_int(w));
}
__global__ void k_dinv(const int2* __restrict__ srcw, const int* __restrict__ cnt,
                       float* __restrict__ dinv) {
    int node = (blockIdx.x * 256 + threadIdx.x) >> 5;
    int lane = threadIdx.x & 31;
    if (node >= NN) return;
    int c = cnt[node]; if (c > CAP) c = CAP;
    float s = 0.f;
    for (int e = lane; e < c; e += 32) s += __int_as_float(srcw[(size_t)node * CAP + e].y);
#pragma unroll
    for (int o = 16; o; o >>= 1) s += __shfl_xor_sync(0xffffffffu, s, o);
    if (lane == 0) dinv[node] = rsqrtf(s + 1.0f);
}

// ---------------- merged weight conversion (fp16) ----------------------------
#define CVT_ROWS 7792
__global__ void k_cvt_all(const float* __restrict__ W1, const float* __restrict__ W2,
                          const float* __restrict__ Wf0, const float* __restrict__ Wf1,
                          const float* __restrict__ Wf2,
                          __half* __restrict__ gh_base) {
    int r = blockIdx.x, t = threadIdx.x;
    float v; size_t off;
    __half* d;
    if (r < 64) {
        v = (r < FEA) ? W1[(size_t)r * 256 + t] : 0.f;
        d = gh_base + OFF_W1; off = (size_t)r * 256 + t;
    } else if (r < 320) {
        int k = r - 64;
        v = W2[(size_t)k * 256 + t];
        d = gh_base + OFF_W2; off = (size_t)k * 256 + t;
    } else if (r < 7280) {
        int k = r - 320;
        v = (k < MLP_IN) ? Wf0[(size_t)k * 256 + t] : 0.f;
        d = gh_base + OFF_F0; off = (size_t)k * 256 + t;
    } else if (r < 7536) {
        int k = r - 7280;
        v = Wf1[(size_t)k * 256 + t];
        d = gh_base + OFF_F1; off = (size_t)k * 256 + t;
    } else {
        int k = r - 7536;
        v = Wf2[(size_t)k * 256 + t];
        d = gh_base + OFF_F2; off = (size_t)k * 256 + t;
    }
    d[off] = __float2half(v);
}

// ---------------- gather x (fp16 uint4, 8 lanes/node, 4-wide batched) --------
__global__ __launch_bounds__(256)
void k_gather_x(const uint4* __restrict__ xp4, const float* __restrict__ dinv,
                const int* __restrict__ cnt, const int2* __restrict__ srcw,
                uint4* __restrict__ xq4) {
    int sub = threadIdx.x >> 3, lane = threadIdx.x & 7;
    int i = blockIdx.x * 32 + sub;
    __shared__ int   ssrc[32][CAP];
    __shared__ float snrm[32][CAP];
    int c = cnt[i]; if (c > CAP) c = CAP;
    float di = dinv[i];
    for (int e = lane; e < c; e += 8) {
        int2 sv = srcw[(size_t)i * CAP + e];
        ssrc[sub][e] = sv.x * 8;               // uint4 row offset (64 halves / 8)
        snrm[sub][e] = dinv[sv.x] * __int_as_float(sv.y) * di;
    }
    __syncwarp();

    float acc[8];
    h8_scale(xp4[i * 8 + lane], di * di, acc);
    int e = 0;
    for (; e + 4 <= c; e += 4) {
        uint4 v0 = xp4[ssrc[sub][e]     + lane];
        uint4 v1 = xp4[ssrc[sub][e + 1] + lane];
        uint4 v2 = xp4[ssrc[sub][e + 2] + lane];
        uint4 v3 = xp4[ssrc[sub][e + 3] + lane];
        h8_acc(v0, snrm[sub][e],     acc);
        h8_acc(v1, snrm[sub][e + 1], acc);
        h8_acc(v2, snrm[sub][e + 2], acc);
        h8_acc(v3, snrm[sub][e + 3], acc);
    }
    for (; e < c; e++)
        h8_acc(xp4[ssrc[sub][e] + lane], snrm[sub][e], acc);
    xq4[i * 8 + lane] = f8_to_h8(acc);
}

// ---------------- gather h (fp16 uint4, 1 warp/node, 4-wide batched) ---------
__global__ __launch_bounds__(256)
void k_gather_h(const uint4* __restrict__ h4,
                const float* __restrict__ dinv, const int* __restrict__ cnt,
                const int2* __restrict__ srcw, uint4* __restrict__ a4) {
    int sub = threadIdx.x >> 5, lane = threadIdx.x & 31;
    int i = blockIdx.x * 8 + sub;
    __shared__ int   ssrc[8][CAP];
    __shared__ float snrm[8][CAP];
    int c = cnt[i]; if (c > CAP) c = CAP;
    float di = dinv[i];
    for (int e = lane; e < c; e += 32) {
        int2 sv = srcw[(size_t)i * CAP + e];
        ssrc[sub][e] = sv.x * 32;              // uint4 row offset (256 halves / 8)
        snrm[sub][e] = dinv[sv.x] * __int_as_float(sv.y) * di;
    }
    __syncwarp();

    float acc[8];
    h8_scale(h4[i * 32 + lane], di * di, acc);
    int e = 0;
    for (; e + 4 <= c; e += 4) {
        uint4 v0 = h4[ssrc[sub][e]     + lane];
        uint4 v1 = h4[ssrc[sub][e + 1] + lane];
        uint4 v2 = h4[ssrc[sub][e + 2] + lane];
        uint4 v3 = h4[ssrc[sub][e + 3] + lane];
        h8_acc(v0, snrm[sub][e],     acc);
        h8_acc(v1, snrm[sub][e + 1], acc);
        h8_acc(v2, snrm[sub][e + 2], acc);
        h8_acc(v3, snrm[sub][e + 3], acc);
    }
    for (; e < c; e++)
        h8_acc(h4[ssrc[sub][e] + lane], snrm[sub][e], acc);
    a4[i * 32 + lane] = f8_to_h8(acc);
}

// ---------------- fp16 tensor-core GEMM (cp.async double-buffered) -----------
// MODE 0: fp32 partial store to C + blockIdx.z*ZSZ (split-K)
// MODE 1: bias + leaky + fp16 store, linear stride 256 (conv1 -> h)
// MODE 2: bias + leaky + fp16 store, flat-mapped (conv2 -> flat)
template<int MODE>
__global__ __launch_bounds__(256)
void bmma(const __half* __restrict__ A, const __half* __restrict__ B,
          float* __restrict__ C, const float* __restrict__ bias,
          __half* __restrict__ o, int K, int kstep) {
    __shared__ __align__(16) __half As[2][128][24];
    __shared__ __align__(16) __half Bs[2][16][136];
    constexpr u32 ABUF = 128 * 24 * 2;
    constexpr u32 BBUF = 16 * 136 * 2;

    const int tid = threadIdx.x;
    const int lane = tid & 31, warp = tid >> 5;
    const int wm = warp >> 2, wn = warp & 3;
    const int row0 = blockIdx.y * 128, col0 = blockIdx.x * 128;
    const int kb = blockIdx.z * kstep;
    const int ke = min(kb + kstep, K);

    const int ar = tid >> 1, ac = (tid & 1) * 8;
    const int bkr = tid >> 4, bc = (tid & 15) * 8;
    const size_t a_base = (size_t)(row0 + ar) * K + ac;

    const u32 a_dst = smem_u32(&As[0][ar][ac]);
    const u32 b_dst = smem_u32(&Bs[0][bkr][bc]);

    float acc[4][4][4];
#pragma unroll
    for (int i = 0; i < 4; i++)
#pragma unroll
        for (int j = 0; j < 4; j++)
#pragma unroll
            for (int q = 0; q < 4; q++) acc[i][j][q] = 0.f;

    const int lr = (lane & 7) + ((lane >> 3) & 1) * 8;
    const int lc = (lane >> 4) * 8;
    u32 aaddr[4], baddr[2];
#pragma unroll
    for (int mf = 0; mf < 4; mf++)
        aaddr[mf] = smem_u32(&As[0][wm * 64 + mf * 16 + lr][lc]);
#pragma unroll
    for (int g = 0; g < 2; g++)
        baddr[g] = smem_u32(&Bs[0][lr][wn * 32 + g * 16 + lc]);

    auto load_stage = [&](int buf, int k0) {
        if (k0 < ke) {
            cp16(a_dst + buf * ABUF, A + a_base + k0);
            cp16(b_dst + buf * BBUF, B + (size_t)(k0 + bkr) * 256 + col0 + bc);
        }
        asm volatile("cp.async.commit_group;");
    };

    load_stage(0, kb);
    load_stage(1, kb + 16);

    int buf = 0;
    for (int k0 = kb; k0 < ke; k0 += 16, buf ^= 1) {
        asm volatile("cp.async.wait_group 1;");
        __syncthreads();

        u32 a[4][4], b[4][2];
#pragma unroll
        for (int mf = 0; mf < 4; mf++)
            ldsm_x4(a[mf], aaddr[mf] + buf * ABUF);
#pragma unroll
        for (int g = 0; g < 2; g++) {
            u32 t[4];
            ldsm_x4_t(t, baddr[g] + buf * BBUF);
            b[2*g][0] = t[0]; b[2*g][1] = t[1];
            b[2*g+1][0] = t[2]; b[2*g+1][1] = t[3];
        }
#pragma unroll
        for (int mf = 0; mf < 4; mf++)
#pragma unroll
            for (int nf = 0; nf < 4; nf++)
                mmaf16(acc[mf][nf], a[mf], b[nf]);
        __syncthreads();
        load_stage(buf, k0 + 32);
    }

    const int er = lane >> 2, ec = (lane & 3) * 2;
    float* Cz = (MODE == 0) ? C + (size_t)blockIdx.z * ZSZ : C;
#pragma unroll
    for (int mf = 0; mf < 4; mf++)
#pragma unroll
        for (int nf = 0; nf < 4; nf++) {
            int r = row0 + wm * 64 + mf * 16 + er;
            int c = col0 + wn * 32 + nf * 8 + ec;
            if (MODE == 0) {
                float* p0 = &Cz[(size_t)r * 256 + c];
                float* p1 = &Cz[(size_t)(r + 8) * 256 + c];
                p0[0] = acc[mf][nf][0]; p0[1] = acc[mf][nf][1];
                p1[0] = acc[mf][nf][2]; p1[1] = acc[mf][nf][3];
            } else {
                float bv0 = bias[c], bv1 = bias[c + 1];
#pragma unroll
                for (int half = 0; half < 2; half++) {
                    int rr = r + half * 8;
                    float v0 = acc[mf][nf][half * 2]     + bv0;
                    float v1 = acc[mf][nf][half * 2 + 1] + bv1;
                    v0 = v0 > 0.f ? v0 : NEG_SLOPE * v0;
                    v1 = v1 > 0.f ? v1 : NEG_SLOPE * v1;
                    size_t p;
                    if (MODE == 1) {
                        p = (size_t)rr * 256 + c;
                    } else {
                        int b = rr / MACH, m = rr - b * MACH;
                        p = (size_t)b * KP0 + (size_t)m * (HID + FEA) + c;
                    }
                    *(__half2*)&o[p] = __floats2half2_rn(v0, v1);
                }
            }
        }
}

// ---------------- split-K reduce + bias + leaky + fp16 store -----------------
template<int S>
__global__ void k_epi(const float* __restrict__ zp, const float* __restrict__ bias,
                      __half* __restrict__ z) {
    size_t i = (size_t)blockIdx.x * 256 + threadIdx.x;
    float v = bias[i & (HID - 1)];
#pragma unroll
    for (int s = 0; s < S; s++) v += zp[s * ZSZ + i];
    v = v > 0.f ? v : NEG_SLOPE * v;
    z[i] = __float2half(v);
}

// ---------------- final: reduce + bias + leaky + head GEMV -------------------
__global__ __launch_bounds__(256)
void k_epihead(const float* __restrict__ zp, const float* __restrict__ bias,
               const float* __restrict__ Wo, const float* __restrict__ bo,
               float* __restrict__ out) {
    __shared__ float zrow[HID];
    int b = blockIdx.x, t = threadIdx.x;
    size_t i = (size_t)b * HID + t;
    float v = bias[t];
#pragma unroll
    for (int s = 0; s < 4; s++) v += zp[s * ZSZ + i];
    v = v > 0.f ? v : NEG_SLOPE * v;
    zrow[t] = v;
    __syncthreads();
    if (t < 128) {
        int j = t >> 5, lane = t & 31;
        float a = 0.f;
#pragma unroll
        for (int q = 0; q < 8; q++) {
            int k = lane + q * 32;
            a = fmaf(zrow[k], Wo[k * 4 + j], a);
        }
#pragma unroll
        for (int o = 16; o > 0; o >>= 1)
            a += __shfl_down_sync(0xffffffffu, a, o);
        if (lane == 0) out[(size_t)b * 4 + j] = a + bo[j];
    }
}

// ---------------- x -> flat (fp16) + tail padding ----------------------------
#define NNFEA ((long long)NN * FEA)
__global__ void k_xpad(const float* __restrict__ x, __half* __restrict__ f) {
    long long idx = (long long)blockIdx.x * 256 + threadIdx.x;
    if (idx < NNFEA) {
        int i = (int)(idx / FEA);
        int j = (int)(idx - (long long)i * FEA);
        int b = i / MACH, m = i - b * MACH;
        f[(size_t)b * KP0 + (size_t)m * (HID + FEA) + HID + j] = __float2half(x[idx]);
    } else {
        long long q = idx - NNFEA;
        int b = (int)(q >> 3), j = (int)(q & 7);
        f[(size_t)b * KP0 + MLP_IN + j] = __float2half(0.f);
    }
}

// ---------------- launcher ---------------------------------------------------
extern "C" void kernel_launch(void* const* d_in, const int* in_sizes, int n_in,
                              void* d_out, int out_size) {
    const float* x   = (const float*)d_in[0];
    const void*  ei  = d_in[1];
    const float* ew  = (const float*)d_in[2];
    const float* W1  = (const float*)d_in[3];
    const float* b1  = (const float*)d_in[4];
    const float* W2  = (const float*)d_in[5];
    const float* b2  = (const float*)d_in[6];
    const float* Wf0 = (const float*)d_in[7];
    const float* bf0 = (const float*)d_in[8];
    const float* Wf1 = (const float*)d_in[9];
    const float* bf1 = (const float*)d_in[10];
    const float* Wf2 = (const float*)d_in[11];
    const float* bf2 = (const float*)d_in[12];
    const float* Wo  = (const float*)d_in[13];
    const float* bo  = (const float*)d_in[14];
    float* out = (float*)d_out;

    float* gf = nullptr; int* gcnt = nullptr; int2* gsw = nullptr; __half* gh = nullptr;
    cudaGetSymbolAddress((void**)&gf, g_f);
    cudaGetSymbolAddress((void**)&gcnt, g_cnt);
    cudaGetSymbolAddress((void**)&gsw, g_srcw);
    cudaGetSymbolAddress((void**)&gh, g_h);

    float* dinv = gf + OFF_DINV;
    float* zp   = gf + OFF_ZP;

    __half *xp = gh + OFF_XP, *xq = gh + OFF_XQ;
    __half *h  = gh + OFF_H,  *a  = gh + OFF_A;
    __half *f  = gh + OFF_F;
    __half *w1 = gh + OFF_W1, *w2 = gh + OFF_W2;
    __half *f0 = gh + OFF_F0, *f1 = gh + OFF_F1, *f2 = gh + OFF_F2;
    __half *z  = gh + OFF_Z;

    const int NB_E = (EE + 255) / 256;

    // slot 4 (profiled) = k_degfill, to verify int2-packed scatter
    k_init<<<(int)(XSZ / 256), 256>>>(ei, x, gcnt, xp);                // 1
    k_cvt_all<<<CVT_ROWS, 256>>>(W1, W2, Wf0, Wf1, Wf2, gh);           // 2
    k_xpad<<<(int)((NNFEA + BATCH * 8) / 256), 256>>>(x, f);           // 3
    k_degfill<<<NB_E, 256>>>(ei, ew, gcnt, gsw);                       // 4 <- profiled
    k_dinv<<<NN / 8, 256>>>(gsw, gcnt, dinv);                          // 5

    // conv1
    k_gather_x<<<NN / 32, 256>>>((const uint4*)xp, dinv, gcnt, gsw, (uint4*)xq);
    bmma<1><<<dim3(2, NN / 128, 1), 256>>>(xq, w1, nullptr, b1, h, KP1, KP1);

    // conv2
    k_gather_h<<<NN / 8, 256>>>((const uint4*)h, dinv, gcnt, gsw, (uint4*)a);
    bmma<2><<<dim3(2, NN / 128, 1), 256>>>(a, w2, nullptr, b2, f, HID, HID);

    // MLP0: split-K=8
    bmma<0><<<dim3(2, BATCH / 128, 8), 256>>>(f, f0, zp, nullptr, nullptr, KP0, 880);
    k_epi<8><<<(int)(ZSZ / 256), 256>>>(zp, bf0, z);

    // MLP1: split-K=4
    bmma<0><<<dim3(2, BATCH / 128, 4), 256>>>(z, f1, zp, nullptr, nullptr, HID, 64);
    k_epi<4><<<(int)(ZSZ / 256), 256>>>(zp, bf1, z);

    // MLP2: split-K=4 -> fused reduce + head
    bmma<0><<<dim3(2, BATCH / 128, 4), 256>>>(z, f2, zp, nullptr, nullptr, HID, 64);
    k_epihead<<<BATCH, 256>>>(zp, bf2, Wo, bo, out);
}